// round 2
// baseline (speedup 1.0000x reference)
#include <cuda_runtime.h>
#include <math.h>

#define N0 20000
#define N1 20000
#define N2 10000
#define NA 600000
#define NE 400000
#define HD 128
#define RR 13
#define LL 2
#define SL (20000 * 128)  // per-relation slab stride (floats) for xl/xr

// ---------------- scratch (static device globals; no allocation) ----------------
__device__ float g_x0[N0 * HD];
__device__ float g_x1[N1 * HD];
__device__ float g_x2[N2 * HD];
__device__ float g_a0[N0 * HD];
__device__ float g_a1[N1 * HD];
__device__ float g_a2[N2 * HD];
__device__ float g_xl[RR * SL];
__device__ float g_xr[RR * SL];
__device__ float g_e[RR * NE];
__device__ unsigned g_m[RR * N0];
__device__ float g_den[RR * N0];
__device__ float g_cnt[N0];
__device__ float g_cbias[3 * HD];

__constant__ int c_RD[RR] = {2, 2, 1, 1, 1, 1, 1, 0, 0, 0, 0, 0, 2};

// ---------------- helpers ----------------
__device__ __forceinline__ unsigned fkey(float f) {
    unsigned u = __float_as_uint(f);
    return (u & 0x80000000u) ? ~u : (u | 0x80000000u);
}
__device__ __forceinline__ float funkey(unsigned u) {
    return (u & 0x80000000u) ? __uint_as_float(u & 0x7FFFFFFFu)
                             : __uint_as_float(~u);
}
__device__ __forceinline__ float wsum(float v) {
#pragma unroll
    for (int o = 16; o; o >>= 1) v += __shfl_xor_sync(0xffffffffu, v, o);
    return v;
}
__device__ __forceinline__ void red4(float* p, float4 v) {
    asm volatile("red.global.add.v4.f32 [%0], {%1,%2,%3,%4};" ::"l"(p),
                 "f"(v.x), "f"(v.y), "f"(v.z), "f"(v.w)
                 : "memory");
}

// ---------------- generic zero ----------------
__global__ void zero_f_kernel(float* p, int n) {
    int i = blockIdx.x * blockDim.x + threadIdx.x;
    int st = gridDim.x * blockDim.x;
    for (; i < n; i += st) p[i] = 0.f;
}
__global__ void zero_md_kernel(unsigned* m, float* den, int n) {
    int i = blockIdx.x * blockDim.x + threadIdx.x;
    if (i < n) { m[i] = 0u; den[i] = 0.f; }
}

// ---------------- SGEMM (atom encoder, scatter epilogue) ----------------
template <int BM, bool SCATTER>
__global__ __launch_bounds__(256, 2) void gemm128_kernel(
    const float* __restrict__ A, const float* __restrict__ B,
    const float* __restrict__ bias, float* __restrict__ C,
    const int* __restrict__ sidx, int M) {
    constexpr int TM = BM / 16;
    constexpr int RB = BM / 64;
    __shared__ float sB[16 * 128];
    __shared__ float sA[16][BM + 4];

    int tid = threadIdx.x;
    int tx = tid & 15, ty = tid >> 4;
    int rowBase = blockIdx.x * BM;

    float acc[TM][8];
#pragma unroll
    for (int i = 0; i < TM; ++i)
#pragma unroll
        for (int j = 0; j < 8; ++j) acc[i][j] = 0.f;

    int lrow = tid >> 2;
    int lk4 = (tid & 3) << 2;

    for (int kc = 0; kc < 128; kc += 16) {
        *(float4*)&sB[tid * 4] = *(const float4*)&B[kc * 128 + tid * 4];
        *(float4*)&sB[1024 + tid * 4] =
            *(const float4*)&B[kc * 128 + 1024 + tid * 4];
#pragma unroll
        for (int p = 0; p < RB; ++p) {
            int row = p * 64 + lrow;
            float4 v = make_float4(0.f, 0.f, 0.f, 0.f);
            if (rowBase + row < M)
                v = *(const float4*)&A[(size_t)(rowBase + row) * 128 + kc + lk4];
            sA[lk4 + 0][row] = v.x;
            sA[lk4 + 1][row] = v.y;
            sA[lk4 + 2][row] = v.z;
            sA[lk4 + 3][row] = v.w;
        }
        __syncthreads();
#pragma unroll
        for (int kk = 0; kk < 16; ++kk) {
            float af[TM], bf[8];
#pragma unroll
            for (int p = 0; p < RB; ++p)
                *(float4*)&af[p * 4] = *(const float4*)&sA[kk][p * 64 + ty * 4];
            *(float4*)&bf[0] = *(const float4*)&sB[kk * 128 + tx * 4];
            *(float4*)&bf[4] = *(const float4*)&sB[kk * 128 + 64 + tx * 4];
#pragma unroll
            for (int i = 0; i < TM; ++i)
#pragma unroll
                for (int j = 0; j < 8; ++j) acc[i][j] += af[i] * bf[j];
        }
        __syncthreads();
    }

    float4 b0 = make_float4(0.f, 0.f, 0.f, 0.f), b1 = b0;
    if (!SCATTER) {
        b0 = *(const float4*)&bias[tx * 4];
        b1 = *(const float4*)&bias[64 + tx * 4];
    }
#pragma unroll
    for (int p = 0; p < RB; ++p)
#pragma unroll
        for (int i = 0; i < 4; ++i) {
            int r = rowBase + p * 64 + ty * 4 + i;
            if (r >= M) continue;
            int ii = p * 4 + i;
            if (SCATTER) {
                int di = sidx[r];
                float* o = C + (size_t)di * 128;
                red4(o + tx * 4,
                     make_float4(acc[ii][0], acc[ii][1], acc[ii][2], acc[ii][3]));
                red4(o + 64 + tx * 4,
                     make_float4(acc[ii][4], acc[ii][5], acc[ii][6], acc[ii][7]));
            } else {
                float4 o0 = make_float4(acc[ii][0] + b0.x, acc[ii][1] + b0.y,
                                        acc[ii][2] + b0.z, acc[ii][3] + b0.w);
                float4 o1 = make_float4(acc[ii][4] + b1.x, acc[ii][5] + b1.y,
                                        acc[ii][6] + b1.z, acc[ii][7] + b1.w);
                *(float4*)&C[(size_t)r * 128 + tx * 4] = o0;
                *(float4*)&C[(size_t)r * 128 + 64 + tx * 4] = o1;
            }
        }
}

// ---------------- batched relation GEMM: one launch for 13 relations ----------
struct GemmBatch {
    const float* A[RR];
    int M[RR];
};

__global__ __launch_bounds__(256, 2) void gemm_batch_kernel(
    GemmBatch gb, const float* __restrict__ Wbase,
    const float* __restrict__ biasBase, float* __restrict__ outBase) {
    constexpr int BM = 64;
    int z = blockIdx.y;
    int M = gb.M[z];
    int rowBase = blockIdx.x * BM;
    if (rowBase >= M) return;
    const float* A = gb.A[z];
    const float* B = Wbase + (size_t)z * HD * HD;
    const float* bias = biasBase + (size_t)z * HD;
    float* C = outBase + (size_t)z * SL;

    __shared__ float sB[16 * 128];
    __shared__ float sA[16][BM + 4];

    int tid = threadIdx.x;
    int tx = tid & 15, ty = tid >> 4;

    float acc[4][8];
#pragma unroll
    for (int i = 0; i < 4; ++i)
#pragma unroll
        for (int j = 0; j < 8; ++j) acc[i][j] = 0.f;

    int lrow = tid >> 2;
    int lk4 = (tid & 3) << 2;

    for (int kc = 0; kc < 128; kc += 16) {
        *(float4*)&sB[tid * 4] = *(const float4*)&B[kc * 128 + tid * 4];
        *(float4*)&sB[1024 + tid * 4] =
            *(const float4*)&B[kc * 128 + 1024 + tid * 4];
        {
            int row = lrow;
            float4 v = make_float4(0.f, 0.f, 0.f, 0.f);
            if (rowBase + row < M)
                v = *(const float4*)&A[(size_t)(rowBase + row) * 128 + kc + lk4];
            sA[lk4 + 0][row] = v.x;
            sA[lk4 + 1][row] = v.y;
            sA[lk4 + 2][row] = v.z;
            sA[lk4 + 3][row] = v.w;
        }
        __syncthreads();
#pragma unroll
        for (int kk = 0; kk < 16; ++kk) {
            float af[4], bf[8];
            *(float4*)&af[0] = *(const float4*)&sA[kk][ty * 4];
            *(float4*)&bf[0] = *(const float4*)&sB[kk * 128 + tx * 4];
            *(float4*)&bf[4] = *(const float4*)&sB[kk * 128 + 64 + tx * 4];
#pragma unroll
            for (int i = 0; i < 4; ++i)
#pragma unroll
                for (int j = 0; j < 8; ++j) acc[i][j] += af[i] * bf[j];
        }
        __syncthreads();
    }

    float4 b0 = *(const float4*)&bias[tx * 4];
    float4 b1 = *(const float4*)&bias[64 + tx * 4];
#pragma unroll
    for (int i = 0; i < 4; ++i) {
        int r = rowBase + ty * 4 + i;
        if (r >= M) continue;
        float4 o0 = make_float4(acc[i][0] + b0.x, acc[i][1] + b0.y,
                                acc[i][2] + b0.z, acc[i][3] + b0.w);
        float4 o1 = make_float4(acc[i][4] + b1.x, acc[i][5] + b1.y,
                                acc[i][6] + b1.z, acc[i][7] + b1.w);
        *(float4*)&C[(size_t)r * 128 + tx * 4] = o0;
        *(float4*)&C[(size_t)r * 128 + 64 + tx * 4] = o1;
    }
}

// ---------------- atom -> chemical count ----------------
__global__ void count_kernel(const int* __restrict__ hd, float* __restrict__ cnt,
                             int n) {
    int i = blockIdx.x * blockDim.x + threadIdx.x;
    if (i < n) atomicAdd(&cnt[hd[i]], 1.f);
}

__global__ void combine_kernel(const float* __restrict__ sum,
                               const float* __restrict__ cnt,
                               const float* __restrict__ xc,
                               float* __restrict__ out, int n) {
    int i = blockIdx.x * blockDim.x + threadIdx.x;
    if (i < n) out[i] = sum[i] / fmaxf(cnt[i >> 7], 1.f) + xc[i];
}

// ---------------- batched edge kernels: blockIdx.y = relation ----------------
__global__ void edge_logits_b(const int* __restrict__ eir,
                              const float* __restrict__ xl_all,
                              const float* __restrict__ xr_all,
                              const float* __restrict__ att_l,
                              float* __restrict__ e_all,
                              unsigned* __restrict__ m_all) {
    int r = blockIdx.y;
    int w = (blockIdx.x * blockDim.x + threadIdx.x) >> 5;
    int lane = threadIdx.x & 31;
    if (w >= NE) return;
    const int* src = eir + (size_t)r * 2 * NE;
    const int* dst = src + NE;
    const float* xl = xl_all + (size_t)r * SL;
    const float* xr = xr_all + (size_t)r * SL;
    int s = src[w], d = dst[w];
    float4 l4 = *(const float4*)&xl[(size_t)s * 128 + lane * 4];
    float4 r4 = *(const float4*)&xr[(size_t)d * 128 + lane * 4];
    float4 av = *(const float4*)&att_l[r * HD + lane * 4];
    float x0 = l4.x + r4.x; x0 = x0 > 0.f ? x0 : 0.2f * x0;
    float x1 = l4.y + r4.y; x1 = x1 > 0.f ? x1 : 0.2f * x1;
    float x2 = l4.z + r4.z; x2 = x2 > 0.f ? x2 : 0.2f * x2;
    float x3 = l4.w + r4.w; x3 = x3 > 0.f ? x3 : 0.2f * x3;
    float p = x0 * av.x + x1 * av.y + x2 * av.z + x3 * av.w;
    p = wsum(p);
    if (lane == 0) {
        e_all[(size_t)r * NE + w] = p;
        atomicMax(&m_all[r * N0 + d], fkey(p));
    }
}

__global__ void edge_denom_b(float* __restrict__ e_all,
                             const int* __restrict__ eir,
                             const unsigned* __restrict__ m_all,
                             float* __restrict__ den_all) {
    int r = blockIdx.y;
    int i = blockIdx.x * blockDim.x + threadIdx.x;
    if (i >= NE) return;
    int d = eir[(size_t)r * 2 * NE + NE + i];
    size_t ei = (size_t)r * NE + i;
    float ex = expf(e_all[ei] - funkey(m_all[r * N0 + d]));
    e_all[ei] = ex;
    atomicAdd(&den_all[r * N0 + d], ex);
}

struct AggPtrs {
    float* p[RR];
};

__global__ void edge_scatter_b(const float* __restrict__ e_all,
                               const float* __restrict__ xl_all,
                               const int* __restrict__ eir,
                               const float* __restrict__ den_all, AggPtrs ap) {
    int r = blockIdx.y;
    int w = (blockIdx.x * blockDim.x + threadIdx.x) >> 5;
    int lane = threadIdx.x & 31;
    if (w >= NE) return;
    const int* src = eir + (size_t)r * 2 * NE;
    const int* dst = src + NE;
    int s = src[w], d = dst[w];
    float alpha = e_all[(size_t)r * NE + w] / fmaxf(den_all[r * N0 + d], 1e-16f);
    const float* xl = xl_all + (size_t)r * SL;
    float4 v = *(const float4*)&xl[(size_t)s * 128 + lane * 4];
    float* o = ap.p[r] + (size_t)d * 128 + lane * 4;
    red4(o, make_float4(alpha * v.x, alpha * v.y, alpha * v.z, alpha * v.w));
}

// combined GATv2 output bias per dst type (sum of cb over relations hitting t)
__global__ void cbias_kernel(const float* __restrict__ cb_l,
                             float* __restrict__ out3) {
    int c = threadIdx.x;
    float s[3] = {0.f, 0.f, 0.f};
#pragma unroll
    for (int r = 0; r < RR; ++r) s[c_RD[r]] += cb_l[r * HD + c];
    out3[c] = s[0];
    out3[HD + c] = s[1];
    out3[2 * HD + c] = s[2];
}

// ---------------- layernorm + relu (warp per row), with folded cb bias -------
__global__ void ln_relu_kernel(const float* __restrict__ in,
                               const float* __restrict__ cbias,
                               const float* __restrict__ g,
                               const float* __restrict__ b,
                               float* __restrict__ out, int N) {
    int row = (blockIdx.x * blockDim.x + threadIdx.x) >> 5;
    int lane = threadIdx.x & 31;
    if (row >= N) return;
    float4 v = *(const float4*)&in[(size_t)row * 128 + lane * 4];
    float4 cv = *(const float4*)&cbias[lane * 4];
    v.x += cv.x; v.y += cv.y; v.z += cv.z; v.w += cv.w;
    float s = v.x + v.y + v.z + v.w;
    s = wsum(s);
    float mu = s * (1.f / 128.f);
    float d0 = v.x - mu, d1 = v.y - mu, d2 = v.z - mu, d3 = v.w - mu;
    float ss = d0 * d0 + d1 * d1 + d2 * d2 + d3 * d3;
    ss = wsum(ss);
    float inv = rsqrtf(ss * (1.f / 128.f) + 1e-5f);
    float4 gv = *(const float4*)&g[lane * 4];
    float4 bv = *(const float4*)&b[lane * 4];
    float4 o;
    o.x = fmaxf(d0 * inv * gv.x + bv.x, 0.f);
    o.y = fmaxf(d1 * inv * gv.y + bv.y, 0.f);
    o.z = fmaxf(d2 * inv * gv.z + bv.z, 0.f);
    o.w = fmaxf(d3 * inv * gv.w + bv.w, 0.f);
    *(float4*)&out[(size_t)row * 128 + lane * 4] = o;
}

// ---------------- prediction head ----------------
__global__ void pred_kernel(const float* __restrict__ x,
                            const float* __restrict__ Wp,
                            const float* __restrict__ bp,
                            float* __restrict__ out, int N) {
    int row = (blockIdx.x * blockDim.x + threadIdx.x) >> 5;
    int lane = threadIdx.x & 31;
    if (row >= N) return;
    float4 xv = *(const float4*)&x[(size_t)row * 128 + lane * 4];
    float4 w01 = *(const float4*)&Wp[lane * 8];
    float4 w23 = *(const float4*)&Wp[lane * 8 + 4];
    float a0 = xv.x * w01.x + xv.y * w01.z + xv.z * w23.x + xv.w * w23.z;
    float a1 = xv.x * w01.y + xv.y * w01.w + xv.z * w23.y + xv.w * w23.w;
    a0 = wsum(a0);
    a1 = wsum(a1);
    if (lane == 0) {
        out[row * 2 + 0] = a0 + bp[0];
        out[row * 2 + 1] = a1 + bp[1];
    }
}

// ---------------- host orchestration ----------------
extern "C" void kernel_launch(void* const* d_in, const int* in_sizes, int n_in,
                              void* d_out, int out_size) {
    const float* x_atom = (const float*)d_in[0];
    const float* x_chem = (const float*)d_in[1];
    const float* x_gene = (const float*)d_in[2];
    const float* x_assay = (const float*)d_in[3];
    const float* W_mol = (const float*)d_in[4];
    const float* Wl = (const float*)d_in[5];
    const float* Wr = (const float*)d_in[6];
    const float* bl = (const float*)d_in[7];
    const float* br = (const float*)d_in[8];
    const float* att = (const float*)d_in[9];
    const float* cb = (const float*)d_in[10];
    const float* lng = (const float*)d_in[11];
    const float* lnb = (const float*)d_in[12];
    const float* Wp = (const float*)d_in[13];
    const float* bp = (const float*)d_in[14];
    const int* hyper = (const int*)d_in[15];
    const int* eir = (const int*)d_in[16];
    float* out = (float*)d_out;
    (void)in_sizes; (void)n_in; (void)out_size;

    float *px0, *px1, *px2, *pa0, *pa1, *pa2, *pxl, *pxr, *pe, *pden, *pcnt,
        *pcb;
    unsigned* pm;
    cudaGetSymbolAddress((void**)&px0, g_x0);
    cudaGetSymbolAddress((void**)&px1, g_x1);
    cudaGetSymbolAddress((void**)&px2, g_x2);
    cudaGetSymbolAddress((void**)&pa0, g_a0);
    cudaGetSymbolAddress((void**)&pa1, g_a1);
    cudaGetSymbolAddress((void**)&pa2, g_a2);
    cudaGetSymbolAddress((void**)&pxl, g_xl);
    cudaGetSymbolAddress((void**)&pxr, g_xr);
    cudaGetSymbolAddress((void**)&pe, g_e);
    cudaGetSymbolAddress((void**)&pm, g_m);
    cudaGetSymbolAddress((void**)&pden, g_den);
    cudaGetSymbolAddress((void**)&pcnt, g_cnt);
    cudaGetSymbolAddress((void**)&pcb, g_cbias);

    const int T = 256;
    const int ZB = 1024;

    static const int RS[RR] = {0, 0, 0, 0, 0, 2, 1, 2, 2, 1, 1, 1, 1};
    static const int RD[RR] = {2, 2, 1, 1, 1, 1, 1, 0, 0, 0, 0, 0, 2};
    const int NT[3] = {N0, N1, N2};

    // ---- atom encoder + bottom-up mean aggregation into chemical ----
    zero_f_kernel<<<ZB, T>>>(pa0, N0 * HD);
    zero_f_kernel<<<(N0 + T - 1) / T, T>>>(pcnt, N0);
    count_kernel<<<(NA + T - 1) / T, T>>>(hyper, pcnt, NA);
    gemm128_kernel<128, true>
        <<<(NA + 127) / 128, T>>>(x_atom, W_mol, nullptr, pa0, hyper, NA);
    combine_kernel<<<(N0 * HD + T - 1) / T, T>>>(pa0, pcnt, x_chem, px0,
                                                 N0 * HD);

    const float* xsrc[3] = {px0, x_gene, x_assay};
    float* agg[3] = {pa0, pa1, pa2};
    float* xnew[3] = {px0, px1, px2};

    for (int l = 0; l < LL; ++l) {
        zero_f_kernel<<<ZB, T>>>(pa0, N0 * HD);
        zero_f_kernel<<<ZB, T>>>(pa1, N1 * HD);
        zero_f_kernel<<<ZB, T>>>(pa2, N2 * HD);
        zero_md_kernel<<<(RR * N0 + T - 1) / T, T>>>(pm, pden, RR * N0);

        GemmBatch gl, gr;
        AggPtrs ap;
        for (int r = 0; r < RR; ++r) {
            gl.A[r] = xsrc[RS[r]];
            gl.M[r] = NT[RS[r]];
            gr.A[r] = xsrc[RD[r]];
            gr.M[r] = NT[RD[r]];
            ap.p[r] = agg[RD[r]];
        }
        size_t lo = (size_t)l * RR;
        dim3 ggrid((N0 + 63) / 64, RR);
        gemm_batch_kernel<<<ggrid, T>>>(gl, Wl + lo * HD * HD, bl + lo * HD,
                                        pxl);
        gemm_batch_kernel<<<ggrid, T>>>(gr, Wr + lo * HD * HD, br + lo * HD,
                                        pxr);
        cbias_kernel<<<1, HD>>>(cb + lo * HD, pcb);

        dim3 egrid(NE / 8, RR);          // warp per edge, 8 warps/block
        dim3 dgrid((NE + T - 1) / T, RR);
        edge_logits_b<<<egrid, T>>>(eir, pxl, pxr, att + lo * HD, pe, pm);
        edge_denom_b<<<dgrid, T>>>(pe, eir, pm, pden);
        edge_scatter_b<<<egrid, T>>>(pe, pxl, eir, pden, ap);

        for (int t = 0; t < 3; ++t) {
            ln_relu_kernel<<<(NT[t] * 32 + T - 1) / T, T>>>(
                agg[t], pcb + t * HD, lng + (size_t)(l * 3 + t) * HD,
                lnb + (size_t)(l * 3 + t) * HD, xnew[t], NT[t]);
        }
        xsrc[0] = px0; xsrc[1] = px1; xsrc[2] = px2;
    }

    pred_kernel<<<(N0 * 32 + T - 1) / T, T>>>(px0, Wp, bp, out, N0);
}

// round 3
// speedup vs baseline: 1.6893x; 1.6893x over previous
#include <cuda_runtime.h>
#include <math.h>

#define N0 20000
#define N1 20000
#define N2 10000
#define NA 600000
#define NE 400000
#define HD 128
#define RR 13
#define LL 2

// ---------------- scratch (static device globals; no allocation) ---------------
__device__ float g_x0[N0 * HD];
__device__ float g_x1[N1 * HD];
__device__ float g_x2[N2 * HD];
__device__ float g_a0[N0 * HD];
__device__ float g_a1[N1 * HD];
__device__ float g_a2[N2 * HD];
__device__ float g_xl[N0 * HD];
__device__ float g_xr[N0 * HD];
__device__ float g_e[NE];
__device__ unsigned g_m[N0];
__device__ float g_den[N0];
__device__ float g_cnt[N0];
__device__ float g_cbias[3 * HD];

__constant__ int c_RD[RR] = {2, 2, 1, 1, 1, 1, 1, 0, 0, 0, 0, 0, 2};

// ---------------- helpers ----------------
__device__ __forceinline__ unsigned fkey(float f) {
    unsigned u = __float_as_uint(f);
    return (u & 0x80000000u) ? ~u : (u | 0x80000000u);
}
__device__ __forceinline__ float funkey(unsigned u) {
    return (u & 0x80000000u) ? __uint_as_float(u & 0x7FFFFFFFu)
                             : __uint_as_float(~u);
}
__device__ __forceinline__ float wsum(float v) {
#pragma unroll
    for (int o = 16; o; o >>= 1) v += __shfl_xor_sync(0xffffffffu, v, o);
    return v;
}
__device__ __forceinline__ void red4(float* p, float4 v) {
    asm volatile("red.global.add.v4.f32 [%0], {%1,%2,%3,%4};" ::"l"(p),
                 "f"(v.x), "f"(v.y), "f"(v.z), "f"(v.w)
                 : "memory");
}

// ---------------- generic zero ----------------
__global__ void zero_f_kernel(float* p, int n) {
    int i = blockIdx.x * blockDim.x + threadIdx.x;
    int st = gridDim.x * blockDim.x;
    for (; i < n; i += st) p[i] = 0.f;
}
__global__ void zero_md_kernel(unsigned* m, float* den, int n) {
    int i = blockIdx.x * blockDim.x + threadIdx.x;
    if (i < n) { m[i] = 0u; den[i] = 0.f; }
}

// ---------------- SGEMM: C[M,128] = A[M,128] @ B[128,128] (+bias | scatter) ---
template <int BM, bool SCATTER>
__global__ __launch_bounds__(256, 2) void gemm128_kernel(
    const float* __restrict__ A, const float* __restrict__ B,
    const float* __restrict__ bias, float* __restrict__ C,
    const int* __restrict__ sidx, int M) {
    constexpr int TM = BM / 16;
    constexpr int RB = BM / 64;
    __shared__ float sB[16 * 128];
    __shared__ float sA[16][BM + 4];

    int tid = threadIdx.x;
    int tx = tid & 15, ty = tid >> 4;
    int rowBase = blockIdx.x * BM;
    if (rowBase >= M) return;

    float acc[TM][8];
#pragma unroll
    for (int i = 0; i < TM; ++i)
#pragma unroll
        for (int j = 0; j < 8; ++j) acc[i][j] = 0.f;

    int lrow = tid >> 2;
    int lk4 = (tid & 3) << 2;

    for (int kc = 0; kc < 128; kc += 16) {
        *(float4*)&sB[tid * 4] = *(const float4*)&B[kc * 128 + tid * 4];
        *(float4*)&sB[1024 + tid * 4] =
            *(const float4*)&B[kc * 128 + 1024 + tid * 4];
#pragma unroll
        for (int p = 0; p < RB; ++p) {
            int row = p * 64 + lrow;
            float4 v = make_float4(0.f, 0.f, 0.f, 0.f);
            if (rowBase + row < M)
                v = *(const float4*)&A[(size_t)(rowBase + row) * 128 + kc + lk4];
            sA[lk4 + 0][row] = v.x;
            sA[lk4 + 1][row] = v.y;
            sA[lk4 + 2][row] = v.z;
            sA[lk4 + 3][row] = v.w;
        }
        __syncthreads();
#pragma unroll
        for (int kk = 0; kk < 16; ++kk) {
            float af[TM], bf[8];
#pragma unroll
            for (int p = 0; p < RB; ++p)
                *(float4*)&af[p * 4] = *(const float4*)&sA[kk][p * 64 + ty * 4];
            *(float4*)&bf[0] = *(const float4*)&sB[kk * 128 + tx * 4];
            *(float4*)&bf[4] = *(const float4*)&sB[kk * 128 + 64 + tx * 4];
#pragma unroll
            for (int i = 0; i < TM; ++i)
#pragma unroll
                for (int j = 0; j < 8; ++j) acc[i][j] += af[i] * bf[j];
        }
        __syncthreads();
    }

    float4 b0 = make_float4(0.f, 0.f, 0.f, 0.f), b1 = b0;
    if (!SCATTER) {
        b0 = *(const float4*)&bias[tx * 4];
        b1 = *(const float4*)&bias[64 + tx * 4];
    }
#pragma unroll
    for (int p = 0; p < RB; ++p)
#pragma unroll
        for (int i = 0; i < 4; ++i) {
            int r = rowBase + p * 64 + ty * 4 + i;
            if (r >= M) continue;
            int ii = p * 4 + i;
            if (SCATTER) {
                int di = sidx[r];
                float* o = C + (size_t)di * 128;
                red4(o + tx * 4,
                     make_float4(acc[ii][0], acc[ii][1], acc[ii][2], acc[ii][3]));
                red4(o + 64 + tx * 4,
                     make_float4(acc[ii][4], acc[ii][5], acc[ii][6], acc[ii][7]));
            } else {
                float4 o0 = make_float4(acc[ii][0] + b0.x, acc[ii][1] + b0.y,
                                        acc[ii][2] + b0.z, acc[ii][3] + b0.w);
                float4 o1 = make_float4(acc[ii][4] + b1.x, acc[ii][5] + b1.y,
                                        acc[ii][6] + b1.z, acc[ii][7] + b1.w);
                *(float4*)&C[(size_t)r * 128 + tx * 4] = o0;
                *(float4*)&C[(size_t)r * 128 + 64 + tx * 4] = o1;
            }
        }
}

// ---------------- atom -> chemical count ----------------
__global__ void count_kernel(const int* __restrict__ hd, float* __restrict__ cnt,
                             int n) {
    int i = blockIdx.x * blockDim.x + threadIdx.x;
    if (i < n) atomicAdd(&cnt[hd[i]], 1.f);
}

__global__ void combine_kernel(const float* __restrict__ sum,
                               const float* __restrict__ cnt,
                               const float* __restrict__ xc,
                               float* __restrict__ out, int n) {
    int i = blockIdx.x * blockDim.x + threadIdx.x;
    if (i < n) out[i] = sum[i] / fmaxf(cnt[i >> 7], 1.f) + xc[i];
}

// ---------------- edge kernels (one warp per edge, per-relation launch) ------
__global__ void edge_logits_kernel(const float* __restrict__ xl,
                                   const float* __restrict__ xr,
                                   const int* __restrict__ src,
                                   const int* __restrict__ dst,
                                   const float* __restrict__ a,
                                   float* __restrict__ e,
                                   unsigned* __restrict__ mkey, int E) {
    int w = (blockIdx.x * blockDim.x + threadIdx.x) >> 5;
    int lane = threadIdx.x & 31;
    if (w >= E) return;
    int s = src[w], d = dst[w];
    float4 l4 = *(const float4*)&xl[(size_t)s * 128 + lane * 4];
    float4 r4 = *(const float4*)&xr[(size_t)d * 128 + lane * 4];
    float4 av = *(const float4*)&a[lane * 4];
    float x0 = l4.x + r4.x; x0 = x0 > 0.f ? x0 : 0.2f * x0;
    float x1 = l4.y + r4.y; x1 = x1 > 0.f ? x1 : 0.2f * x1;
    float x2 = l4.z + r4.z; x2 = x2 > 0.f ? x2 : 0.2f * x2;
    float x3 = l4.w + r4.w; x3 = x3 > 0.f ? x3 : 0.2f * x3;
    float p = x0 * av.x + x1 * av.y + x2 * av.z + x3 * av.w;
    p = wsum(p);
    if (lane == 0) {
        e[w] = p;
        atomicMax(&mkey[d], fkey(p));
    }
}

__global__ void edge_denom_kernel(float* __restrict__ e,
                                  const int* __restrict__ dst,
                                  const unsigned* __restrict__ mkey,
                                  float* __restrict__ den, int E) {
    int i = blockIdx.x * blockDim.x + threadIdx.x;
    if (i >= E) return;
    int d = dst[i];
    float ex = expf(e[i] - funkey(mkey[d]));
    e[i] = ex;
    atomicAdd(&den[d], ex);
}

__global__ void edge_scatter_kernel(const float* __restrict__ ex,
                                    const float* __restrict__ xl,
                                    const int* __restrict__ src,
                                    const int* __restrict__ dst,
                                    const float* __restrict__ den,
                                    float* __restrict__ agg, int E) {
    int w = (blockIdx.x * blockDim.x + threadIdx.x) >> 5;
    int lane = threadIdx.x & 31;
    if (w >= E) return;
    int s = src[w], d = dst[w];
    float alpha = ex[w] / fmaxf(den[d], 1e-16f);
    float4 v = *(const float4*)&xl[(size_t)s * 128 + lane * 4];
    float* o = agg + (size_t)d * 128 + lane * 4;
    red4(o, make_float4(alpha * v.x, alpha * v.y, alpha * v.z, alpha * v.w));
}

// combined GATv2 output bias per dst type (sum of cb over relations hitting t)
__global__ void cbias_kernel(const float* __restrict__ cb_l,
                             float* __restrict__ out3) {
    int c = threadIdx.x;
    float s[3] = {0.f, 0.f, 0.f};
#pragma unroll
    for (int r = 0; r < RR; ++r) s[c_RD[r]] += cb_l[r * HD + c];
    out3[c] = s[0];
    out3[HD + c] = s[1];
    out3[2 * HD + c] = s[2];
}

// ---------------- layernorm + relu (warp per row), with folded cb bias -------
__global__ void ln_relu_kernel(const float* __restrict__ in,
                               const float* __restrict__ cbias,
                               const float* __restrict__ g,
                               const float* __restrict__ b,
                               float* __restrict__ out, int N) {
    int row = (blockIdx.x * blockDim.x + threadIdx.x) >> 5;
    int lane = threadIdx.x & 31;
    if (row >= N) return;
    float4 v = *(const float4*)&in[(size_t)row * 128 + lane * 4];
    float4 cv = *(const float4*)&cbias[lane * 4];
    v.x += cv.x; v.y += cv.y; v.z += cv.z; v.w += cv.w;
    float s = v.x + v.y + v.z + v.w;
    s = wsum(s);
    float mu = s * (1.f / 128.f);
    float d0 = v.x - mu, d1 = v.y - mu, d2 = v.z - mu, d3 = v.w - mu;
    float ss = d0 * d0 + d1 * d1 + d2 * d2 + d3 * d3;
    ss = wsum(ss);
    float inv = rsqrtf(ss * (1.f / 128.f) + 1e-5f);
    float4 gv = *(const float4*)&g[lane * 4];
    float4 bv = *(const float4*)&b[lane * 4];
    float4 o;
    o.x = fmaxf(d0 * inv * gv.x + bv.x, 0.f);
    o.y = fmaxf(d1 * inv * gv.y + bv.y, 0.f);
    o.z = fmaxf(d2 * inv * gv.z + bv.z, 0.f);
    o.w = fmaxf(d3 * inv * gv.w + bv.w, 0.f);
    *(float4*)&out[(size_t)row * 128 + lane * 4] = o;
}

// ---------------- prediction head ----------------
__global__ void pred_kernel(const float* __restrict__ x,
                            const float* __restrict__ Wp,
                            const float* __restrict__ bp,
                            float* __restrict__ out, int N) {
    int row = (blockIdx.x * blockDim.x + threadIdx.x) >> 5;
    int lane = threadIdx.x & 31;
    if (row >= N) return;
    float4 xv = *(const float4*)&x[(size_t)row * 128 + lane * 4];
    float4 w01 = *(const float4*)&Wp[lane * 8];
    float4 w23 = *(const float4*)&Wp[lane * 8 + 4];
    float a0 = xv.x * w01.x + xv.y * w01.z + xv.z * w23.x + xv.w * w23.z;
    float a1 = xv.x * w01.y + xv.y * w01.w + xv.z * w23.y + xv.w * w23.w;
    a0 = wsum(a0);
    a1 = wsum(a1);
    if (lane == 0) {
        out[row * 2 + 0] = a0 + bp[0];
        out[row * 2 + 1] = a1 + bp[1];
    }
}

// ---------------- host orchestration ----------------
extern "C" void kernel_launch(void* const* d_in, const int* in_sizes, int n_in,
                              void* d_out, int out_size) {
    const float* x_atom = (const float*)d_in[0];
    const float* x_chem = (const float*)d_in[1];
    const float* x_gene = (const float*)d_in[2];
    const float* x_assay = (const float*)d_in[3];
    const float* W_mol = (const float*)d_in[4];
    const float* Wl = (const float*)d_in[5];
    const float* Wr = (const float*)d_in[6];
    const float* bl = (const float*)d_in[7];
    const float* br = (const float*)d_in[8];
    const float* att = (const float*)d_in[9];
    const float* cb = (const float*)d_in[10];
    const float* lng = (const float*)d_in[11];
    const float* lnb = (const float*)d_in[12];
    const float* Wp = (const float*)d_in[13];
    const float* bp = (const float*)d_in[14];
    const int* hyper = (const int*)d_in[15];
    const int* eir = (const int*)d_in[16];
    float* out = (float*)d_out;
    (void)in_sizes; (void)n_in; (void)out_size;

    float *px0, *px1, *px2, *pa0, *pa1, *pa2, *pxl, *pxr, *pe, *pden, *pcnt,
        *pcb;
    unsigned* pm;
    cudaGetSymbolAddress((void**)&px0, g_x0);
    cudaGetSymbolAddress((void**)&px1, g_x1);
    cudaGetSymbolAddress((void**)&px2, g_x2);
    cudaGetSymbolAddress((void**)&pa0, g_a0);
    cudaGetSymbolAddress((void**)&pa1, g_a1);
    cudaGetSymbolAddress((void**)&pa2, g_a2);
    cudaGetSymbolAddress((void**)&pxl, g_xl);
    cudaGetSymbolAddress((void**)&pxr, g_xr);
    cudaGetSymbolAddress((void**)&pe, g_e);
    cudaGetSymbolAddress((void**)&pm, g_m);
    cudaGetSymbolAddress((void**)&pden, g_den);
    cudaGetSymbolAddress((void**)&pcnt, g_cnt);
    cudaGetSymbolAddress((void**)&pcb, g_cbias);

    const int T = 256;
    const int ZB = 1024;

    static const int RS[RR] = {0, 0, 0, 0, 0, 2, 1, 2, 2, 1, 1, 1, 1};
    static const int RD[RR] = {2, 2, 1, 1, 1, 1, 1, 0, 0, 0, 0, 0, 2};
    const int NT[3] = {N0, N1, N2};

    // ---- atom encoder + bottom-up mean aggregation into chemical ----
    zero_f_kernel<<<ZB, T>>>(pa0, N0 * HD);
    zero_f_kernel<<<(N0 + T - 1) / T, T>>>(pcnt, N0);
    count_kernel<<<(NA + T - 1) / T, T>>>(hyper, pcnt, NA);
    gemm128_kernel<128, true>
        <<<(NA + 127) / 128, T>>>(x_atom, W_mol, nullptr, pa0, hyper, NA);
    combine_kernel<<<(N0 * HD + T - 1) / T, T>>>(pa0, pcnt, x_chem, px0,
                                                 N0 * HD);

    const float* xsrc[3] = {px0, x_gene, x_assay};
    float* agg[3] = {pa0, pa1, pa2};
    float* xnew[3] = {px0, px1, px2};

    for (int l = 0; l < LL; ++l) {
        zero_f_kernel<<<ZB, T>>>(pa0, N0 * HD);
        zero_f_kernel<<<ZB, T>>>(pa1, N1 * HD);
        zero_f_kernel<<<ZB, T>>>(pa2, N2 * HD);
        size_t lo = (size_t)l * RR;
        cbias_kernel<<<1, HD>>>(cb + lo * HD, pcb);

        for (int r = 0; r < RR; ++r) {
            int s = RS[r], d = RD[r];
            int Ns = NT[s], Nd = NT[d];
            size_t wo = lo + r;
            gemm128_kernel<64, false><<<(Ns + 63) / 64, T>>>(
                xsrc[s], Wl + wo * HD * HD, bl + wo * HD, pxl, nullptr, Ns);
            gemm128_kernel<64, false><<<(Nd + 63) / 64, T>>>(
                xsrc[d], Wr + wo * HD * HD, br + wo * HD, pxr, nullptr, Nd);
            zero_md_kernel<<<(Nd + T - 1) / T, T>>>(pm, pden, Nd);
            const int* srcp = eir + (size_t)r * 2 * NE;
            const int* dstp = srcp + NE;
            edge_logits_kernel<<<(NE + 7) / 8, T>>>(pxl, pxr, srcp, dstp,
                                                    att + wo * HD, pe, pm, NE);
            edge_denom_kernel<<<(NE + T - 1) / T, T>>>(pe, dstp, pm, pden, NE);
            edge_scatter_kernel<<<(NE + 7) / 8, T>>>(pe, pxl, srcp, dstp, pden,
                                                     agg[d], NE);
        }
        for (int t = 0; t < 3; ++t) {
            ln_relu_kernel<<<(NT[t] * 32 + T - 1) / T, T>>>(
                agg[t], pcb + t * HD, lng + (size_t)(l * 3 + t) * HD,
                lnb + (size_t)(l * 3 + t) * HD, xnew[t], NT[t]);
        }
        xsrc[0] = px0; xsrc[1] = px1; xsrc[2] = px2;
    }

    pred_kernel<<<(N0 * 32 + T - 1) / T, T>>>(px0, Wp, bp, out, N0);
}

// round 4
// speedup vs baseline: 2.2492x; 1.3314x over previous
#include <cuda_runtime.h>
#include <math.h>

#define N0 20000
#define N1 20000
#define N2 10000
#define NA 600000
#define NE 400000
#define HD 128
#define RR 13
#define LL 2

// ---------------- scratch (static device globals; no allocation) ---------------
__device__ float g_x0[N0 * HD];
__device__ float g_x1[N1 * HD];
__device__ float g_x2[N2 * HD];
__device__ float g_a0[N0 * HD];
__device__ float g_a1[N1 * HD];
__device__ float g_a2[N2 * HD];
__device__ float g_xl[N0 * HD];
__device__ float g_xr[N0 * HD];
__device__ float g_t[N0 * HD];     // per-relation unnormalized aggregate
__device__ float g_den[N0];
__device__ float g_cnt[N0];
__device__ float g_cbias[3 * HD];

__constant__ int c_RD[RR] = {2, 2, 1, 1, 1, 1, 1, 0, 0, 0, 0, 0, 2};

// ---------------- helpers ----------------
__device__ __forceinline__ float wsum(float v) {
#pragma unroll
    for (int o = 16; o; o >>= 1) v += __shfl_xor_sync(0xffffffffu, v, o);
    return v;
}
__device__ __forceinline__ void red4(float* p, float4 v) {
    asm volatile("red.global.add.v4.f32 [%0], {%1,%2,%3,%4};" ::"l"(p),
                 "f"(v.x), "f"(v.y), "f"(v.z), "f"(v.w)
                 : "memory");
}

// ---------------- zero kernels ----------------
__global__ void zero_f_kernel(float* p, int n) {
    int i = blockIdx.x * blockDim.x + threadIdx.x;
    int st = gridDim.x * blockDim.x;
    for (; i < n; i += st) p[i] = 0.f;
}
// zero tmp (Nd*HD) and den (Nd) in one launch
__global__ void zero_td_kernel(float* tmp, float* den, int Nd) {
    int i = blockIdx.x * blockDim.x + threadIdx.x;
    int st = gridDim.x * blockDim.x;
    int n4 = Nd * (HD / 4);
    float4 z = make_float4(0.f, 0.f, 0.f, 0.f);
    for (int j = i; j < n4; j += st) ((float4*)tmp)[j] = z;
    for (int j = i; j < Nd; j += st) den[j] = 0.f;
}

// ---------------- SGEMM: C[M,128] = A[M,128] @ B[128,128] (+bias | scatter) ---
template <int BM, bool SCATTER>
__global__ __launch_bounds__(256, 2) void gemm128_kernel(
    const float* __restrict__ A, const float* __restrict__ B,
    const float* __restrict__ bias, float* __restrict__ C,
    const int* __restrict__ sidx, int M) {
    constexpr int TM = BM / 16;
    constexpr int RB = BM / 64;
    __shared__ float sB[16 * 128];
    __shared__ float sA[16][BM + 4];

    int tid = threadIdx.x;
    int tx = tid & 15, ty = tid >> 4;
    int rowBase = blockIdx.x * BM;
    if (rowBase >= M) return;

    float acc[TM][8];
#pragma unroll
    for (int i = 0; i < TM; ++i)
#pragma unroll
        for (int j = 0; j < 8; ++j) acc[i][j] = 0.f;

    int lrow = tid >> 2;
    int lk4 = (tid & 3) << 2;

    for (int kc = 0; kc < 128; kc += 16) {
        *(float4*)&sB[tid * 4] = *(const float4*)&B[kc * 128 + tid * 4];
        *(float4*)&sB[1024 + tid * 4] =
            *(const float4*)&B[kc * 128 + 1024 + tid * 4];
#pragma unroll
        for (int p = 0; p < RB; ++p) {
            int row = p * 64 + lrow;
            float4 v = make_float4(0.f, 0.f, 0.f, 0.f);
            if (rowBase + row < M)
                v = *(const float4*)&A[(size_t)(rowBase + row) * 128 + kc + lk4];
            sA[lk4 + 0][row] = v.x;
            sA[lk4 + 1][row] = v.y;
            sA[lk4 + 2][row] = v.z;
            sA[lk4 + 3][row] = v.w;
        }
        __syncthreads();
#pragma unroll
        for (int kk = 0; kk < 16; ++kk) {
            float af[TM], bf[8];
#pragma unroll
            for (int p = 0; p < RB; ++p)
                *(float4*)&af[p * 4] = *(const float4*)&sA[kk][p * 64 + ty * 4];
            *(float4*)&bf[0] = *(const float4*)&sB[kk * 128 + tx * 4];
            *(float4*)&bf[4] = *(const float4*)&sB[kk * 128 + 64 + tx * 4];
#pragma unroll
            for (int i = 0; i < TM; ++i)
#pragma unroll
                for (int j = 0; j < 8; ++j) acc[i][j] += af[i] * bf[j];
        }
        __syncthreads();
    }

    float4 b0 = make_float4(0.f, 0.f, 0.f, 0.f), b1 = b0;
    if (!SCATTER) {
        b0 = *(const float4*)&bias[tx * 4];
        b1 = *(const float4*)&bias[64 + tx * 4];
    }
#pragma unroll
    for (int p = 0; p < RB; ++p)
#pragma unroll
        for (int i = 0; i < 4; ++i) {
            int r = rowBase + p * 64 + ty * 4 + i;
            if (r >= M) continue;
            int ii = p * 4 + i;
            if (SCATTER) {
                int di = sidx[r];
                float* o = C + (size_t)di * 128;
                red4(o + tx * 4,
                     make_float4(acc[ii][0], acc[ii][1], acc[ii][2], acc[ii][3]));
                red4(o + 64 + tx * 4,
                     make_float4(acc[ii][4], acc[ii][5], acc[ii][6], acc[ii][7]));
            } else {
                float4 o0 = make_float4(acc[ii][0] + b0.x, acc[ii][1] + b0.y,
                                        acc[ii][2] + b0.z, acc[ii][3] + b0.w);
                float4 o1 = make_float4(acc[ii][4] + b1.x, acc[ii][5] + b1.y,
                                        acc[ii][6] + b1.z, acc[ii][7] + b1.w);
                *(float4*)&C[(size_t)r * 128 + tx * 4] = o0;
                *(float4*)&C[(size_t)r * 128 + 64 + tx * 4] = o1;
            }
        }
}

// ---------------- paired GEMM: grid.y=0 -> xl, grid.y=1 -> xr ----------------
struct Pair {
    const float* A[2];
    const float* W[2];
    const float* bias[2];
    float* C[2];
    int M[2];
};

__global__ __launch_bounds__(256, 2) void gemm_pair_kernel(Pair pr) {
    constexpr int BM = 64;
    int z = blockIdx.y;
    int M = pr.M[z];
    int rowBase = blockIdx.x * BM;
    if (rowBase >= M) return;
    const float* A = pr.A[z];
    const float* B = pr.W[z];
    const float* bias = pr.bias[z];
    float* C = pr.C[z];

    __shared__ float sB[16 * 128];
    __shared__ float sA[16][BM + 4];

    int tid = threadIdx.x;
    int tx = tid & 15, ty = tid >> 4;

    float acc[4][8];
#pragma unroll
    for (int i = 0; i < 4; ++i)
#pragma unroll
        for (int j = 0; j < 8; ++j) acc[i][j] = 0.f;

    int lrow = tid >> 2;
    int lk4 = (tid & 3) << 2;

    for (int kc = 0; kc < 128; kc += 16) {
        *(float4*)&sB[tid * 4] = *(const float4*)&B[kc * 128 + tid * 4];
        *(float4*)&sB[1024 + tid * 4] =
            *(const float4*)&B[kc * 128 + 1024 + tid * 4];
        {
            int row = lrow;
            float4 v = make_float4(0.f, 0.f, 0.f, 0.f);
            if (rowBase + row < M)
                v = *(const float4*)&A[(size_t)(rowBase + row) * 128 + kc + lk4];
            sA[lk4 + 0][row] = v.x;
            sA[lk4 + 1][row] = v.y;
            sA[lk4 + 2][row] = v.z;
            sA[lk4 + 3][row] = v.w;
        }
        __syncthreads();
#pragma unroll
        for (int kk = 0; kk < 16; ++kk) {
            float af[4], bf[8];
            *(float4*)&af[0] = *(const float4*)&sA[kk][ty * 4];
            *(float4*)&bf[0] = *(const float4*)&sB[kk * 128 + tx * 4];
            *(float4*)&bf[4] = *(const float4*)&sB[kk * 128 + 64 + tx * 4];
#pragma unroll
            for (int i = 0; i < 4; ++i)
#pragma unroll
                for (int j = 0; j < 8; ++j) acc[i][j] += af[i] * bf[j];
        }
        __syncthreads();
    }

    float4 b0 = *(const float4*)&bias[tx * 4];
    float4 b1 = *(const float4*)&bias[64 + tx * 4];
#pragma unroll
    for (int i = 0; i < 4; ++i) {
        int r = rowBase + ty * 4 + i;
        if (r >= M) continue;
        float4 o0 = make_float4(acc[i][0] + b0.x, acc[i][1] + b0.y,
                                acc[i][2] + b0.z, acc[i][3] + b0.w);
        float4 o1 = make_float4(acc[i][4] + b1.x, acc[i][5] + b1.y,
                                acc[i][6] + b1.z, acc[i][7] + b1.w);
        *(float4*)&C[(size_t)r * 128 + tx * 4] = o0;
        *(float4*)&C[(size_t)r * 128 + 64 + tx * 4] = o1;
    }
}

// ---------------- atom -> chemical count ----------------
__global__ void count_kernel(const int* __restrict__ hd, float* __restrict__ cnt,
                             int n) {
    int i = blockIdx.x * blockDim.x + threadIdx.x;
    if (i < n) atomicAdd(&cnt[hd[i]], 1.f);
}

__global__ void combine_kernel(const float* __restrict__ sum,
                               const float* __restrict__ cnt,
                               const float* __restrict__ xc,
                               float* __restrict__ out, int n) {
    int i = blockIdx.x * blockDim.x + threadIdx.x;
    if (i < n) out[i] = sum[i] / fmaxf(cnt[i >> 7], 1.f) + xc[i];
}

// ---------------- fused edge pass (one warp per edge) ------------------------
// Softmax shift-invariance: alpha = exp(e)/sum(exp(e)) (no max needed; |e|<~30).
// Computes e, ex=exp(e), scatters ex*xl[src] into tmp, accumulates ex into den.
__global__ void edge_fused_kernel(const float* __restrict__ xl,
                                  const float* __restrict__ xr,
                                  const int* __restrict__ src,
                                  const int* __restrict__ dst,
                                  const float* __restrict__ a,
                                  float* __restrict__ tmp,
                                  float* __restrict__ den, int E) {
    int w = (blockIdx.x * blockDim.x + threadIdx.x) >> 5;
    int lane = threadIdx.x & 31;
    if (w >= E) return;
    int s = src[w], d = dst[w];
    float4 l4 = *(const float4*)&xl[(size_t)s * 128 + lane * 4];
    float4 r4 = *(const float4*)&xr[(size_t)d * 128 + lane * 4];
    float4 av = *(const float4*)&a[lane * 4];
    float x0 = l4.x + r4.x; x0 = x0 > 0.f ? x0 : 0.2f * x0;
    float x1 = l4.y + r4.y; x1 = x1 > 0.f ? x1 : 0.2f * x1;
    float x2 = l4.z + r4.z; x2 = x2 > 0.f ? x2 : 0.2f * x2;
    float x3 = l4.w + r4.w; x3 = x3 > 0.f ? x3 : 0.2f * x3;
    float p = x0 * av.x + x1 * av.y + x2 * av.z + x3 * av.w;
    p = wsum(p);
    float ex = expf(p);
    float* o = tmp + (size_t)d * 128 + lane * 4;
    red4(o, make_float4(ex * l4.x, ex * l4.y, ex * l4.z, ex * l4.w));
    if (lane == 0) atomicAdd(&den[d], ex);
}

// agg[d] += tmp[d] / max(den[d], 1e-16)
__global__ void norm_acc_kernel(const float* __restrict__ tmp,
                                const float* __restrict__ den,
                                float* __restrict__ agg, int Nd) {
    int i = blockIdx.x * blockDim.x + threadIdx.x;  // float4 index
    if (i >= Nd * (HD / 4)) return;
    float inv = 1.f / fmaxf(den[i >> 5], 1e-16f);
    float4 t = ((const float4*)tmp)[i];
    float4 g = ((float4*)agg)[i];
    g.x += t.x * inv; g.y += t.y * inv; g.z += t.z * inv; g.w += t.w * inv;
    ((float4*)agg)[i] = g;
}

// combined GATv2 output bias per dst type
__global__ void cbias_kernel(const float* __restrict__ cb_l,
                             float* __restrict__ out3) {
    int c = threadIdx.x;
    float s[3] = {0.f, 0.f, 0.f};
#pragma unroll
    for (int r = 0; r < RR; ++r) s[c_RD[r]] += cb_l[r * HD + c];
    out3[c] = s[0];
    out3[HD + c] = s[1];
    out3[2 * HD + c] = s[2];
}

// ---------------- layernorm + relu (warp per row), with folded cb bias -------
__global__ void ln_relu_kernel(const float* __restrict__ in,
                               const float* __restrict__ cbias,
                               const float* __restrict__ g,
                               const float* __restrict__ b,
                               float* __restrict__ out, int N) {
    int row = (blockIdx.x * blockDim.x + threadIdx.x) >> 5;
    int lane = threadIdx.x & 31;
    if (row >= N) return;
    float4 v = *(const float4*)&in[(size_t)row * 128 + lane * 4];
    float4 cv = *(const float4*)&cbias[lane * 4];
    v.x += cv.x; v.y += cv.y; v.z += cv.z; v.w += cv.w;
    float s = v.x + v.y + v.z + v.w;
    s = wsum(s);
    float mu = s * (1.f / 128.f);
    float d0 = v.x - mu, d1 = v.y - mu, d2 = v.z - mu, d3 = v.w - mu;
    float ss = d0 * d0 + d1 * d1 + d2 * d2 + d3 * d3;
    ss = wsum(ss);
    float inv = rsqrtf(ss * (1.f / 128.f) + 1e-5f);
    float4 gv = *(const float4*)&g[lane * 4];
    float4 bv = *(const float4*)&b[lane * 4];
    float4 o;
    o.x = fmaxf(d0 * inv * gv.x + bv.x, 0.f);
    o.y = fmaxf(d1 * inv * gv.y + bv.y, 0.f);
    o.z = fmaxf(d2 * inv * gv.z + bv.z, 0.f);
    o.w = fmaxf(d3 * inv * gv.w + bv.w, 0.f);
    *(float4*)&out[(size_t)row * 128 + lane * 4] = o;
}

// ---------------- prediction head ----------------
__global__ void pred_kernel(const float* __restrict__ x,
                            const float* __restrict__ Wp,
                            const float* __restrict__ bp,
                            float* __restrict__ out, int N) {
    int row = (blockIdx.x * blockDim.x + threadIdx.x) >> 5;
    int lane = threadIdx.x & 31;
    if (row >= N) return;
    float4 xv = *(const float4*)&x[(size_t)row * 128 + lane * 4];
    float4 w01 = *(const float4*)&Wp[lane * 8];
    float4 w23 = *(const float4*)&Wp[lane * 8 + 4];
    float a0 = xv.x * w01.x + xv.y * w01.z + xv.z * w23.x + xv.w * w23.z;
    float a1 = xv.x * w01.y + xv.y * w01.w + xv.z * w23.y + xv.w * w23.w;
    a0 = wsum(a0);
    a1 = wsum(a1);
    if (lane == 0) {
        out[row * 2 + 0] = a0 + bp[0];
        out[row * 2 + 1] = a1 + bp[1];
    }
}

// ---------------- host orchestration ----------------
extern "C" void kernel_launch(void* const* d_in, const int* in_sizes, int n_in,
                              void* d_out, int out_size) {
    const float* x_atom = (const float*)d_in[0];
    const float* x_chem = (const float*)d_in[1];
    const float* x_gene = (const float*)d_in[2];
    const float* x_assay = (const float*)d_in[3];
    const float* W_mol = (const float*)d_in[4];
    const float* Wl = (const float*)d_in[5];
    const float* Wr = (const float*)d_in[6];
    const float* bl = (const float*)d_in[7];
    const float* br = (const float*)d_in[8];
    const float* att = (const float*)d_in[9];
    const float* cb = (const float*)d_in[10];
    const float* lng = (const float*)d_in[11];
    const float* lnb = (const float*)d_in[12];
    const float* Wp = (const float*)d_in[13];
    const float* bp = (const float*)d_in[14];
    const int* hyper = (const int*)d_in[15];
    const int* eir = (const int*)d_in[16];
    float* out = (float*)d_out;
    (void)in_sizes; (void)n_in; (void)out_size;

    float *px0, *px1, *px2, *pa0, *pa1, *pa2, *pxl, *pxr, *pt, *pden, *pcnt,
        *pcb;
    cudaGetSymbolAddress((void**)&px0, g_x0);
    cudaGetSymbolAddress((void**)&px1, g_x1);
    cudaGetSymbolAddress((void**)&px2, g_x2);
    cudaGetSymbolAddress((void**)&pa0, g_a0);
    cudaGetSymbolAddress((void**)&pa1, g_a1);
    cudaGetSymbolAddress((void**)&pa2, g_a2);
    cudaGetSymbolAddress((void**)&pxl, g_xl);
    cudaGetSymbolAddress((void**)&pxr, g_xr);
    cudaGetSymbolAddress((void**)&pt, g_t);
    cudaGetSymbolAddress((void**)&pden, g_den);
    cudaGetSymbolAddress((void**)&pcnt, g_cnt);
    cudaGetSymbolAddress((void**)&pcb, g_cbias);

    const int T = 256;
    const int ZB = 1024;

    static const int RS[RR] = {0, 0, 0, 0, 0, 2, 1, 2, 2, 1, 1, 1, 1};
    static const int RD[RR] = {2, 2, 1, 1, 1, 1, 1, 0, 0, 0, 0, 0, 2};
    const int NT[3] = {N0, N1, N2};

    // ---- atom encoder + bottom-up mean aggregation into chemical ----
    zero_f_kernel<<<ZB, T>>>(pa0, N0 * HD);
    zero_f_kernel<<<(N0 + T - 1) / T, T>>>(pcnt, N0);
    count_kernel<<<(NA + T - 1) / T, T>>>(hyper, pcnt, NA);
    gemm128_kernel<128, true>
        <<<(NA + 127) / 128, T>>>(x_atom, W_mol, nullptr, pa0, hyper, NA);
    combine_kernel<<<(N0 * HD + T - 1) / T, T>>>(pa0, pcnt, x_chem, px0,
                                                 N0 * HD);

    const float* xsrc[3] = {px0, x_gene, x_assay};
    float* agg[3] = {pa0, pa1, pa2};
    float* xnew[3] = {px0, px1, px2};

    for (int l = 0; l < LL; ++l) {
        zero_f_kernel<<<ZB, T>>>(pa0, N0 * HD);
        zero_f_kernel<<<ZB, T>>>(pa1, N1 * HD);
        zero_f_kernel<<<ZB, T>>>(pa2, N2 * HD);
        size_t lo = (size_t)l * RR;
        cbias_kernel<<<1, HD>>>(cb + lo * HD, pcb);

        for (int r = 0; r < RR; ++r) {
            int s = RS[r], d = RD[r];
            int Ns = NT[s], Nd = NT[d];
            size_t wo = lo + r;

            Pair pr;
            pr.A[0] = xsrc[s];  pr.M[0] = Ns;
            pr.A[1] = xsrc[d];  pr.M[1] = Nd;
            pr.W[0] = Wl + wo * HD * HD;
            pr.W[1] = Wr + wo * HD * HD;
            pr.bias[0] = bl + wo * HD;
            pr.bias[1] = br + wo * HD;
            pr.C[0] = pxl;
            pr.C[1] = pxr;
            int mx = Ns > Nd ? Ns : Nd;
            dim3 ggrid((mx + 63) / 64, 2);
            gemm_pair_kernel<<<ggrid, T>>>(pr);

            zero_td_kernel<<<ZB, T>>>(pt, pden, Nd);

            const int* srcp = eir + (size_t)r * 2 * NE;
            const int* dstp = srcp + NE;
            edge_fused_kernel<<<(NE + 7) / 8, T>>>(pxl, pxr, srcp, dstp,
                                                   att + wo * HD, pt, pden, NE);
            norm_acc_kernel<<<(Nd * (HD / 4) + T - 1) / T, T>>>(pt, pden,
                                                                agg[d], Nd);
        }
        for (int t = 0; t < 3; ++t) {
            ln_relu_kernel<<<(NT[t] * 32 + T - 1) / T, T>>>(
                agg[t], pcb + t * HD, lng + (size_t)(l * 3 + t) * HD,
                lnb + (size_t)(l * 3 + t) * HD, xnew[t], NT[t]);
        }
        xsrc[0] = px0; xsrc[1] = px1; xsrc[2] = px2;
    }

    pred_kernel<<<(N0 * 32 + T - 1) / T, T>>>(px0, Wp, bp, out, N0);
}

// round 5
// speedup vs baseline: 2.5381x; 1.1285x over previous
#include <cuda_runtime.h>
#include <cuda_bf16.h>
#include <math.h>
#include <stdint.h>

#define N0 20000
#define N1 20000
#define N2 10000
#define NA 600000
#define NE 400000
#define HD 128
#define RR 13
#define LL 2

// ---------------- scratch (static device globals; no allocation) ---------------
__device__ float g_x0[N0 * HD];
__device__ float g_x1[N1 * HD];
__device__ float g_x2[N2 * HD];
__device__ float g_a0[N0 * HD];
__device__ float g_a1[N1 * HD];
__device__ float g_a2[N2 * HD];
__device__ float g_xl[N0 * HD];
__device__ float g_xr[N0 * HD];
__device__ float g_t[N0 * HD];  // per-relation unnormalized aggregate
__device__ float g_den[N0];
__device__ float g_cnt[N0];
__device__ float g_cbias[3 * HD];

__constant__ int c_RD[RR] = {2, 2, 1, 1, 1, 1, 1, 0, 0, 0, 0, 0, 2};

// ---------------- helpers ----------------
__device__ __forceinline__ float wsum(float v) {
#pragma unroll
    for (int o = 16; o; o >>= 1) v += __shfl_xor_sync(0xffffffffu, v, o);
    return v;
}
__device__ __forceinline__ void red4(float* p, float4 v) {
    asm volatile("red.global.add.v4.f32 [%0], {%1,%2,%3,%4};" ::"l"(p),
                 "f"(v.x), "f"(v.y), "f"(v.z), "f"(v.w)
                 : "memory");
}
__device__ __forceinline__ void red2(float* p, float a, float b) {
    asm volatile("red.global.add.v2.f32 [%0], {%1,%2};" ::"l"(p), "f"(a),
                 "f"(b)
                 : "memory");
}
__device__ __forceinline__ void ldsm4(uint32_t* r, uint32_t addr) {
    asm volatile(
        "ldmatrix.sync.aligned.m8n8.x4.shared.b16 {%0,%1,%2,%3}, [%4];"
        : "=r"(r[0]), "=r"(r[1]), "=r"(r[2]), "=r"(r[3])
        : "r"(addr));
}
__device__ __forceinline__ void ldsm4t(uint32_t* r, uint32_t addr) {
    asm volatile(
        "ldmatrix.sync.aligned.m8n8.x4.trans.shared.b16 {%0,%1,%2,%3}, [%4];"
        : "=r"(r[0]), "=r"(r[1]), "=r"(r[2]), "=r"(r[3])
        : "r"(addr));
}
__device__ __forceinline__ void mma16816(float* d, const uint32_t* a,
                                         const uint32_t* b) {
    asm volatile(
        "mma.sync.aligned.m16n8k16.row.col.f32.bf16.bf16.f32 "
        "{%0,%1,%2,%3}, {%4,%5,%6,%7}, {%8,%9}, {%0,%1,%2,%3};"
        : "+f"(d[0]), "+f"(d[1]), "+f"(d[2]), "+f"(d[3])
        : "r"(a[0]), "r"(a[1]), "r"(a[2]), "r"(a[3]), "r"(b[0]), "r"(b[1]));
}
// fp32x4 -> bf16 hi + bf16 lo (exact residual split)
__device__ __forceinline__ void split4(float4 v, uint2& hi, uint2& lo) {
    __nv_bfloat162 h0 = __floats2bfloat162_rn(v.x, v.y);
    __nv_bfloat162 h1 = __floats2bfloat162_rn(v.z, v.w);
    float2 f0 = __bfloat1622float2(h0);
    float2 f1 = __bfloat1622float2(h1);
    __nv_bfloat162 l0 = __floats2bfloat162_rn(v.x - f0.x, v.y - f0.y);
    __nv_bfloat162 l1 = __floats2bfloat162_rn(v.z - f1.x, v.w - f1.y);
    hi = make_uint2(*(uint32_t*)&h0, *(uint32_t*)&h1);
    lo = make_uint2(*(uint32_t*)&l0, *(uint32_t*)&l1);
}

// ---------------- zero kernels ----------------
__global__ void zero_f_kernel(float* p, int n) {
    int i = blockIdx.x * blockDim.x + threadIdx.x;
    int st = gridDim.x * blockDim.x;
    for (; i < n; i += st) p[i] = 0.f;
}
__global__ void zero_td_kernel(float* tmp, float* den, int Nd) {
    int i = blockIdx.x * blockDim.x + threadIdx.x;
    int st = gridDim.x * blockDim.x;
    int n4 = Nd * (HD / 4);
    float4 z = make_float4(0.f, 0.f, 0.f, 0.f);
    for (int j = i; j < n4; j += st) ((float4*)tmp)[j] = z;
    for (int j = i; j < Nd; j += st) den[j] = 0.f;
}

// ---------------- tensor-core bf16x3 GEMM core ------------------------------
// C[M,128] = A[M,128] (fp32) @ B[128,128] (fp32), fp32 accum via 3 bf16 terms.
// Block: 128 rows, 256 threads = 8 warps (4x2), warp tile 32x64.
// smem (dynamic 64KB): Ah[128x64] Al[128x64] Bh[64x128] Bl[64x128] bf16,
// XOR-(row&7) 16B-chunk swizzle -> conflict-free ldmatrix phases.
template <bool SCATTER>
__device__ __forceinline__ void tc_gemm_core(const float* __restrict__ A,
                                             const float* __restrict__ B,
                                             const float* __restrict__ bias,
                                             float* __restrict__ C,
                                             const int* __restrict__ sidx,
                                             int M) {
    extern __shared__ __nv_bfloat16 sm[];
    __nv_bfloat16* sAh = sm;
    __nv_bfloat16* sAl = sm + 8192;
    __nv_bfloat16* sBh = sm + 16384;
    __nv_bfloat16* sBl = sm + 24576;
    const int tid = threadIdx.x;
    const int lane = tid & 31, warp = tid >> 5;
    const int wm = warp & 3, wn = warp >> 2;
    const int rowBase = blockIdx.x * 128;
    if (rowBase >= M) return;

    float acc[2][8][4];
#pragma unroll
    for (int a = 0; a < 2; ++a)
#pragma unroll
        for (int b = 0; b < 8; ++b)
#pragma unroll
            for (int c = 0; c < 4; ++c) acc[a][b][c] = 0.f;

    uint32_t sAh_b = (uint32_t)__cvta_generic_to_shared(sAh);
    uint32_t sAl_b = (uint32_t)__cvta_generic_to_shared(sAl);
    uint32_t sBh_b = (uint32_t)__cvta_generic_to_shared(sBh);
    uint32_t sBl_b = (uint32_t)__cvta_generic_to_shared(sBl);

    for (int kc = 0; kc < 128; kc += 64) {
        __syncthreads();
        // A chunk: 128 rows x 64 cols fp32 -> split into sAh/sAl
#pragma unroll
        for (int i = 0; i < 8; ++i) {
            int j = tid + 256 * i;
            int row = j >> 4, c4 = j & 15;
            float4 v = make_float4(0.f, 0.f, 0.f, 0.f);
            if (rowBase + row < M)
                v = *(const float4*)&A[(size_t)(rowBase + row) * 128 + kc +
                                       c4 * 4];
            uint2 h, l;
            split4(v, h, l);
            int off = row * 64 + (((c4 >> 1) ^ (row & 7)) << 3) + (c4 & 1) * 4;
            *(uint2*)&sAh[off] = h;
            *(uint2*)&sAl[off] = l;
        }
        // B chunk: 64 rows (k) x 128 cols fp32 -> split into sBh/sBl
#pragma unroll
        for (int i = 0; i < 8; ++i) {
            int j = tid + 256 * i;
            int row = j >> 5, c4 = j & 31;
            float4 v = *(const float4*)&B[(size_t)(kc + row) * 128 + c4 * 4];
            uint2 h, l;
            split4(v, h, l);
            int off = row * 128 + (((c4 >> 1) ^ (row & 7)) << 3) + (c4 & 1) * 4;
            *(uint2*)&sBh[off] = h;
            *(uint2*)&sBl[off] = l;
        }
        __syncthreads();
#pragma unroll
        for (int s = 0; s < 4; ++s) {
            uint32_t ah[2][4], al[2][4];
#pragma unroll
            for (int mf = 0; mf < 2; ++mf) {
                int mr = wm * 32 + mf * 16 + (lane & 15);
                int ck = 2 * s + (lane >> 4);
                uint32_t off = (uint32_t)(mr * 64 + ((ck ^ (mr & 7)) << 3)) * 2;
                ldsm4(ah[mf], sAh_b + off);
                ldsm4(al[mf], sAl_b + off);
            }
#pragma unroll
            for (int nf2 = 0; nf2 < 4; ++nf2) {
                int kr = s * 16 + (lane & 7) + ((lane >> 3) & 1) * 8;
                int cn = wn * 8 + nf2 * 2 + (lane >> 4);
                uint32_t off =
                    (uint32_t)(kr * 128 + ((cn ^ (kr & 7)) << 3)) * 2;
                uint32_t bh[4], bl[4];
                ldsm4t(bh, sBh_b + off);
                ldsm4t(bl, sBl_b + off);
#pragma unroll
                for (int mf = 0; mf < 2; ++mf) {
                    mma16816(acc[mf][nf2 * 2], ah[mf], bh);
                    mma16816(acc[mf][nf2 * 2], ah[mf], bl);
                    mma16816(acc[mf][nf2 * 2], al[mf], bh);
                    mma16816(acc[mf][nf2 * 2 + 1], ah[mf], bh + 2);
                    mma16816(acc[mf][nf2 * 2 + 1], ah[mf], bl + 2);
                    mma16816(acc[mf][nf2 * 2 + 1], al[mf], bh + 2);
                }
            }
        }
    }
    // epilogue: c-frag thread mapping (row = t/4 (+8), cols 2*(t%4)+{0,1})
    int c0 = wn * 64 + (lane & 3) * 2;
#pragma unroll
    for (int mf = 0; mf < 2; ++mf) {
        int r0 = rowBase + wm * 32 + mf * 16 + (lane >> 2);
#pragma unroll
        for (int nf = 0; nf < 8; ++nf) {
            int col = c0 + nf * 8;
            if (SCATTER) {
                if (r0 < M)
                    red2(&C[(size_t)sidx[r0] * 128 + col], acc[mf][nf][0],
                         acc[mf][nf][1]);
                if (r0 + 8 < M)
                    red2(&C[(size_t)sidx[r0 + 8] * 128 + col], acc[mf][nf][2],
                         acc[mf][nf][3]);
            } else {
                float2 bv = *(const float2*)&bias[col];
                if (r0 < M) {
                    C[(size_t)r0 * 128 + col] = acc[mf][nf][0] + bv.x;
                    C[(size_t)r0 * 128 + col + 1] = acc[mf][nf][1] + bv.y;
                }
                if (r0 + 8 < M) {
                    C[(size_t)(r0 + 8) * 128 + col] = acc[mf][nf][2] + bv.x;
                    C[(size_t)(r0 + 8) * 128 + col + 1] = acc[mf][nf][3] + bv.y;
                }
            }
        }
    }
}

struct Pair {
    const float* A[2];
    const float* W[2];
    const float* bias[2];
    float* C[2];
    int M[2];
};

__global__ __launch_bounds__(256, 2) void tc_gemm_scatter_kernel(
    const float* __restrict__ A, const float* __restrict__ B,
    float* __restrict__ C, const int* __restrict__ sidx, int M) {
    tc_gemm_core<true>(A, B, nullptr, C, sidx, M);
}
__global__ __launch_bounds__(256, 2) void tc_gemm_pair_kernel(Pair pr) {
    int z = blockIdx.y;
    tc_gemm_core<false>(pr.A[z], pr.W[z], pr.bias[z], pr.C[z], nullptr,
                        pr.M[z]);
}

// ---------------- atom -> chemical count ----------------
__global__ void count_kernel(const int* __restrict__ hd, float* __restrict__ cnt,
                             int n) {
    int i = blockIdx.x * blockDim.x + threadIdx.x;
    if (i < n) atomicAdd(&cnt[hd[i]], 1.f);
}
__global__ void combine_kernel(const float* __restrict__ sum,
                               const float* __restrict__ cnt,
                               const float* __restrict__ xc,
                               float* __restrict__ out, int n) {
    int i = blockIdx.x * blockDim.x + threadIdx.x;
    if (i < n) out[i] = sum[i] / fmaxf(cnt[i >> 7], 1.f) + xc[i];
}

// ---------------- fused edge pass (one warp per edge) ------------------------
__global__ void edge_fused_kernel(const float* __restrict__ xl,
                                  const float* __restrict__ xr,
                                  const int* __restrict__ src,
                                  const int* __restrict__ dst,
                                  const float* __restrict__ a,
                                  float* __restrict__ tmp,
                                  float* __restrict__ den, int E) {
    int w = (blockIdx.x * blockDim.x + threadIdx.x) >> 5;
    int lane = threadIdx.x & 31;
    if (w >= E) return;
    int s = src[w], d = dst[w];
    float4 l4 = *(const float4*)&xl[(size_t)s * 128 + lane * 4];
    float4 r4 = *(const float4*)&xr[(size_t)d * 128 + lane * 4];
    float4 av = *(const float4*)&a[lane * 4];
    float x0 = l4.x + r4.x; x0 = x0 > 0.f ? x0 : 0.2f * x0;
    float x1 = l4.y + r4.y; x1 = x1 > 0.f ? x1 : 0.2f * x1;
    float x2 = l4.z + r4.z; x2 = x2 > 0.f ? x2 : 0.2f * x2;
    float x3 = l4.w + r4.w; x3 = x3 > 0.f ? x3 : 0.2f * x3;
    float p = x0 * av.x + x1 * av.y + x2 * av.z + x3 * av.w;
    p = wsum(p);
    float ex = expf(p);
    float* o = tmp + (size_t)d * 128 + lane * 4;
    red4(o, make_float4(ex * l4.x, ex * l4.y, ex * l4.z, ex * l4.w));
    if (lane == 0) atomicAdd(&den[d], ex);
}

// agg[d] += tmp[d]/max(den[d],eps); re-zeroes tmp and den for next relation
__global__ void norm_acc_kernel(float* __restrict__ tmp,
                                float* __restrict__ den,
                                float* __restrict__ agg, int Nd) {
    int i = blockIdx.x * blockDim.x + threadIdx.x;  // float4 index
    if (i >= Nd * (HD / 4)) return;
    int d = i >> 5;
    float inv = 1.f / fmaxf(den[d], 1e-16f);
    float4 t = ((const float4*)tmp)[i];
    ((float4*)tmp)[i] = make_float4(0.f, 0.f, 0.f, 0.f);
    float4 g = ((float4*)agg)[i];
    g.x += t.x * inv; g.y += t.y * inv; g.z += t.z * inv; g.w += t.w * inv;
    ((float4*)agg)[i] = g;
    if ((i & 31) == 0) den[d] = 0.f;
}

// combined GATv2 output bias per dst type
__global__ void cbias_kernel(const float* __restrict__ cb_l,
                             float* __restrict__ out3) {
    int c = threadIdx.x;
    float s[3] = {0.f, 0.f, 0.f};
#pragma unroll
    for (int r = 0; r < RR; ++r) s[c_RD[r]] += cb_l[r * HD + c];
    out3[c] = s[0];
    out3[HD + c] = s[1];
    out3[2 * HD + c] = s[2];
}

// ---------------- layernorm + relu (warp per row), with folded cb bias -------
__global__ void ln_relu_kernel(const float* __restrict__ in,
                               const float* __restrict__ cbias,
                               const float* __restrict__ g,
                               const float* __restrict__ b,
                               float* __restrict__ out, int N) {
    int row = (blockIdx.x * blockDim.x + threadIdx.x) >> 5;
    int lane = threadIdx.x & 31;
    if (row >= N) return;
    float4 v = *(const float4*)&in[(size_t)row * 128 + lane * 4];
    float4 cv = *(const float4*)&cbias[lane * 4];
    v.x += cv.x; v.y += cv.y; v.z += cv.z; v.w += cv.w;
    float s = v.x + v.y + v.z + v.w;
    s = wsum(s);
    float mu = s * (1.f / 128.f);
    float d0 = v.x - mu, d1 = v.y - mu, d2 = v.z - mu, d3 = v.w - mu;
    float ss = d0 * d0 + d1 * d1 + d2 * d2 + d3 * d3;
    ss = wsum(ss);
    float inv = rsqrtf(ss * (1.f / 128.f) + 1e-5f);
    float4 gv = *(const float4*)&g[lane * 4];
    float4 bv = *(const float4*)&b[lane * 4];
    float4 o;
    o.x = fmaxf(d0 * inv * gv.x + bv.x, 0.f);
    o.y = fmaxf(d1 * inv * gv.y + bv.y, 0.f);
    o.z = fmaxf(d2 * inv * gv.z + bv.z, 0.f);
    o.w = fmaxf(d3 * inv * gv.w + bv.w, 0.f);
    *(float4*)&out[(size_t)row * 128 + lane * 4] = o;
}

// ---------------- prediction head ----------------
__global__ void pred_kernel(const float* __restrict__ x,
                            const float* __restrict__ Wp,
                            const float* __restrict__ bp,
                            float* __restrict__ out, int N) {
    int row = (blockIdx.x * blockDim.x + threadIdx.x) >> 5;
    int lane = threadIdx.x & 31;
    if (row >= N) return;
    float4 xv = *(const float4*)&x[(size_t)row * 128 + lane * 4];
    float4 w01 = *(const float4*)&Wp[lane * 8];
    float4 w23 = *(const float4*)&Wp[lane * 8 + 4];
    float a0 = xv.x * w01.x + xv.y * w01.z + xv.z * w23.x + xv.w * w23.z;
    float a1 = xv.x * w01.y + xv.y * w01.w + xv.z * w23.y + xv.w * w23.w;
    a0 = wsum(a0);
    a1 = wsum(a1);
    if (lane == 0) {
        out[row * 2 + 0] = a0 + bp[0];
        out[row * 2 + 1] = a1 + bp[1];
    }
}

// ---------------- host orchestration ----------------
extern "C" void kernel_launch(void* const* d_in, const int* in_sizes, int n_in,
                              void* d_out, int out_size) {
    const float* x_atom = (const float*)d_in[0];
    const float* x_chem = (const float*)d_in[1];
    const float* x_gene = (const float*)d_in[2];
    const float* x_assay = (const float*)d_in[3];
    const float* W_mol = (const float*)d_in[4];
    const float* Wl = (const float*)d_in[5];
    const float* Wr = (const float*)d_in[6];
    const float* bl = (const float*)d_in[7];
    const float* br = (const float*)d_in[8];
    const float* att = (const float*)d_in[9];
    const float* cb = (const float*)d_in[10];
    const float* lng = (const float*)d_in[11];
    const float* lnb = (const float*)d_in[12];
    const float* Wp = (const float*)d_in[13];
    const float* bp = (const float*)d_in[14];
    const int* hyper = (const int*)d_in[15];
    const int* eir = (const int*)d_in[16];
    float* out = (float*)d_out;
    (void)in_sizes; (void)n_in; (void)out_size;

    float *px0, *px1, *px2, *pa0, *pa1, *pa2, *pxl, *pxr, *pt, *pden, *pcnt,
        *pcb;
    cudaGetSymbolAddress((void**)&px0, g_x0);
    cudaGetSymbolAddress((void**)&px1, g_x1);
    cudaGetSymbolAddress((void**)&px2, g_x2);
    cudaGetSymbolAddress((void**)&pa0, g_a0);
    cudaGetSymbolAddress((void**)&pa1, g_a1);
    cudaGetSymbolAddress((void**)&pa2, g_a2);
    cudaGetSymbolAddress((void**)&pxl, g_xl);
    cudaGetSymbolAddress((void**)&pxr, g_xr);
    cudaGetSymbolAddress((void**)&pt, g_t);
    cudaGetSymbolAddress((void**)&pden, g_den);
    cudaGetSymbolAddress((void**)&pcnt, g_cnt);
    cudaGetSymbolAddress((void**)&pcb, g_cbias);

    const int T = 256;
    const int ZB = 1024;
    const int SMEMB = 65536;

    cudaFuncSetAttribute(tc_gemm_scatter_kernel,
                         cudaFuncAttributeMaxDynamicSharedMemorySize, SMEMB);
    cudaFuncSetAttribute(tc_gemm_pair_kernel,
                         cudaFuncAttributeMaxDynamicSharedMemorySize, SMEMB);

    static const int RS[RR] = {0, 0, 0, 0, 0, 2, 1, 2, 2, 1, 1, 1, 1};
    static const int RD[RR] = {2, 2, 1, 1, 1, 1, 1, 0, 0, 0, 0, 0, 2};
    const int NT[3] = {N0, N1, N2};

    // ---- atom encoder + bottom-up mean aggregation into chemical ----
    zero_f_kernel<<<ZB, T>>>(pa0, N0 * HD);
    zero_f_kernel<<<(N0 + T - 1) / T, T>>>(pcnt, N0);
    zero_td_kernel<<<ZB, T>>>(pt, pden, N0);  // once; norm_acc keeps it zeroed
    count_kernel<<<(NA + T - 1) / T, T>>>(hyper, pcnt, NA);
    tc_gemm_scatter_kernel<<<(NA + 127) / 128, T, SMEMB>>>(x_atom, W_mol, pa0,
                                                           hyper, NA);
    combine_kernel<<<(N0 * HD + T - 1) / T, T>>>(pa0, pcnt, x_chem, px0,
                                                 N0 * HD);

    const float* xsrc[3] = {px0, x_gene, x_assay};
    float* agg[3] = {pa0, pa1, pa2};
    float* xnew[3] = {px0, px1, px2};

    for (int l = 0; l < LL; ++l) {
        zero_f_kernel<<<ZB, T>>>(pa0, N0 * HD);
        zero_f_kernel<<<ZB, T>>>(pa1, N1 * HD);
        zero_f_kernel<<<ZB, T>>>(pa2, N2 * HD);
        size_t lo = (size_t)l * RR;
        cbias_kernel<<<1, HD>>>(cb + lo * HD, pcb);

        for (int r = 0; r < RR; ++r) {
            int s = RS[r], d = RD[r];
            int Ns = NT[s], Nd = NT[d];
            size_t wo = lo + r;

            Pair pr;
            pr.A[0] = xsrc[s];  pr.M[0] = Ns;
            pr.A[1] = xsrc[d];  pr.M[1] = Nd;
            pr.W[0] = Wl + wo * HD * HD;
            pr.W[1] = Wr + wo * HD * HD;
            pr.bias[0] = bl + wo * HD;
            pr.bias[1] = br + wo * HD;
            pr.C[0] = pxl;
            pr.C[1] = pxr;
            int mx = Ns > Nd ? Ns : Nd;
            dim3 ggrid((mx + 127) / 128, 2);
            tc_gemm_pair_kernel<<<ggrid, T, SMEMB>>>(pr);

            const int* srcp = eir + (size_t)r * 2 * NE;
            const int* dstp = srcp + NE;
            edge_fused_kernel<<<(NE + 7) / 8, T>>>(pxl, pxr, srcp, dstp,
                                                   att + wo * HD, pt, pden, NE);
            norm_acc_kernel<<<(Nd * (HD / 4) + T - 1) / T, T>>>(pt, pden,
                                                                agg[d], Nd);
        }
        for (int t = 0; t < 3; ++t) {
            ln_relu_kernel<<<(NT[t] * 32 + T - 1) / T, T>>>(
                agg[t], pcb + t * HD, lng + (size_t)(l * 3 + t) * HD,
                lnb + (size_t)(l * 3 + t) * HD, xnew[t], NT[t]);
        }
        xsrc[0] = px0; xsrc[1] = px1; xsrc[2] = px2;
    }

    pred_kernel<<<(N0 * 32 + T - 1) / T, T>>>(px0, Wp, bp, out, N0);
}

// round 6
// speedup vs baseline: 2.5704x; 1.0127x over previous
#include <cuda_runtime.h>
#include <cuda_bf16.h>
#include <math.h>
#include <stdint.h>

#define N0 20000
#define N1 20000
#define N2 10000
#define NA 600000
#define NE 400000
#define HD 128
#define RR 13
#define LL 2
#define SLAB (N0 * HD)

// ---------------- scratch (static device globals; no allocation) ---------------
__device__ float g_x0[N0 * HD];
__device__ float g_x1[N1 * HD];
__device__ float g_x2[N2 * HD];
__device__ float g_a0[N0 * HD];
__device__ float g_a1[N1 * HD];
__device__ float g_a2[N2 * HD];
__device__ float g_xl[2 * SLAB];  // double-buffered
__device__ float g_xr[2 * SLAB];
__device__ float g_t[N0 * HD];  // per-relation unnormalized aggregate
__device__ float g_den[N0];
__device__ float g_cnt[N0];
__device__ float g_cbias[3 * HD];

__constant__ int c_RD[RR] = {2, 2, 1, 1, 1, 1, 1, 0, 0, 0, 0, 0, 2};

// ---------------- helpers ----------------
__device__ __forceinline__ float wsum(float v) {
#pragma unroll
    for (int o = 16; o; o >>= 1) v += __shfl_xor_sync(0xffffffffu, v, o);
    return v;
}
__device__ __forceinline__ void red4(float* p, float4 v) {
    asm volatile("red.global.add.v4.f32 [%0], {%1,%2,%3,%4};" ::"l"(p),
                 "f"(v.x), "f"(v.y), "f"(v.z), "f"(v.w)
                 : "memory");
}
__device__ __forceinline__ void red2(float* p, float a, float b) {
    asm volatile("red.global.add.v2.f32 [%0], {%1,%2};" ::"l"(p), "f"(a),
                 "f"(b)
                 : "memory");
}
__device__ __forceinline__ void ldsm4(uint32_t* r, uint32_t addr) {
    asm volatile(
        "ldmatrix.sync.aligned.m8n8.x4.shared.b16 {%0,%1,%2,%3}, [%4];"
        : "=r"(r[0]), "=r"(r[1]), "=r"(r[2]), "=r"(r[3])
        : "r"(addr));
}
__device__ __forceinline__ void ldsm4t(uint32_t* r, uint32_t addr) {
    asm volatile(
        "ldmatrix.sync.aligned.m8n8.x4.trans.shared.b16 {%0,%1,%2,%3}, [%4];"
        : "=r"(r[0]), "=r"(r[1]), "=r"(r[2]), "=r"(r[3])
        : "r"(addr));
}
__device__ __forceinline__ void mma16816(float* d, const uint32_t* a,
                                         const uint32_t* b) {
    asm volatile(
        "mma.sync.aligned.m16n8k16.row.col.f32.bf16.bf16.f32 "
        "{%0,%1,%2,%3}, {%4,%5,%6,%7}, {%8,%9}, {%0,%1,%2,%3};"
        : "+f"(d[0]), "+f"(d[1]), "+f"(d[2]), "+f"(d[3])
        : "r"(a[0]), "r"(a[1]), "r"(a[2]), "r"(a[3]), "r"(b[0]), "r"(b[1]));
}
__device__ __forceinline__ void split4(float4 v, uint2& hi, uint2& lo) {
    __nv_bfloat162 h0 = __floats2bfloat162_rn(v.x, v.y);
    __nv_bfloat162 h1 = __floats2bfloat162_rn(v.z, v.w);
    float2 f0 = __bfloat1622float2(h0);
    float2 f1 = __bfloat1622float2(h1);
    __nv_bfloat162 l0 = __floats2bfloat162_rn(v.x - f0.x, v.y - f0.y);
    __nv_bfloat162 l1 = __floats2bfloat162_rn(v.z - f1.x, v.w - f1.y);
    hi = make_uint2(*(uint32_t*)&h0, *(uint32_t*)&h1);
    lo = make_uint2(*(uint32_t*)&l0, *(uint32_t*)&l1);
}

// ---------------- zero kernels ----------------
__global__ void zero_f_kernel(float* p, int n) {
    int i = blockIdx.x * blockDim.x + threadIdx.x;
    int st = gridDim.x * blockDim.x;
    for (; i < n; i += st) p[i] = 0.f;
}
__global__ void zero_td_kernel(float* tmp, float* den, int Nd) {
    int i = blockIdx.x * blockDim.x + threadIdx.x;
    int st = gridDim.x * blockDim.x;
    int n4 = Nd * (HD / 4);
    float4 z = make_float4(0.f, 0.f, 0.f, 0.f);
    for (int j = i; j < n4; j += st) ((float4*)tmp)[j] = z;
    for (int j = i; j < Nd; j += st) den[j] = 0.f;
}

// ---------------- tensor-core bf16x3 GEMM core ------------------------------
template <bool SCATTER>
__device__ __forceinline__ void tc_gemm_core(const float* __restrict__ A,
                                             const float* __restrict__ B,
                                             const float* __restrict__ bias,
                                             float* __restrict__ C,
                                             const int* __restrict__ sidx,
                                             int M) {
    extern __shared__ __nv_bfloat16 sm[];
    __nv_bfloat16* sAh = sm;
    __nv_bfloat16* sAl = sm + 8192;
    __nv_bfloat16* sBh = sm + 16384;
    __nv_bfloat16* sBl = sm + 24576;
    const int tid = threadIdx.x;
    const int lane = tid & 31, warp = tid >> 5;
    const int wm = warp & 3, wn = warp >> 2;
    const int rowBase = blockIdx.x * 128;
    if (rowBase >= M) return;

    float acc[2][8][4];
#pragma unroll
    for (int a = 0; a < 2; ++a)
#pragma unroll
        for (int b = 0; b < 8; ++b)
#pragma unroll
            for (int c = 0; c < 4; ++c) acc[a][b][c] = 0.f;

    uint32_t sAh_b = (uint32_t)__cvta_generic_to_shared(sAh);
    uint32_t sAl_b = (uint32_t)__cvta_generic_to_shared(sAl);
    uint32_t sBh_b = (uint32_t)__cvta_generic_to_shared(sBh);
    uint32_t sBl_b = (uint32_t)__cvta_generic_to_shared(sBl);

    for (int kc = 0; kc < 128; kc += 64) {
        __syncthreads();
#pragma unroll
        for (int i = 0; i < 8; ++i) {
            int j = tid + 256 * i;
            int row = j >> 4, c4 = j & 15;
            float4 v = make_float4(0.f, 0.f, 0.f, 0.f);
            if (rowBase + row < M)
                v = *(const float4*)&A[(size_t)(rowBase + row) * 128 + kc +
                                       c4 * 4];
            uint2 h, l;
            split4(v, h, l);
            int off = row * 64 + (((c4 >> 1) ^ (row & 7)) << 3) + (c4 & 1) * 4;
            *(uint2*)&sAh[off] = h;
            *(uint2*)&sAl[off] = l;
        }
#pragma unroll
        for (int i = 0; i < 8; ++i) {
            int j = tid + 256 * i;
            int row = j >> 5, c4 = j & 31;
            float4 v = *(const float4*)&B[(size_t)(kc + row) * 128 + c4 * 4];
            uint2 h, l;
            split4(v, h, l);
            int off = row * 128 + (((c4 >> 1) ^ (row & 7)) << 3) + (c4 & 1) * 4;
            *(uint2*)&sBh[off] = h;
            *(uint2*)&sBl[off] = l;
        }
        __syncthreads();
#pragma unroll
        for (int s = 0; s < 4; ++s) {
            uint32_t ah[2][4], al[2][4];
#pragma unroll
            for (int mf = 0; mf < 2; ++mf) {
                int mr = wm * 32 + mf * 16 + (lane & 15);
                int ck = 2 * s + (lane >> 4);
                uint32_t off = (uint32_t)(mr * 64 + ((ck ^ (mr & 7)) << 3)) * 2;
                ldsm4(ah[mf], sAh_b + off);
                ldsm4(al[mf], sAl_b + off);
            }
#pragma unroll
            for (int nf2 = 0; nf2 < 4; ++nf2) {
                int kr = s * 16 + (lane & 7) + ((lane >> 3) & 1) * 8;
                int cn = wn * 8 + nf2 * 2 + (lane >> 4);
                uint32_t off =
                    (uint32_t)(kr * 128 + ((cn ^ (kr & 7)) << 3)) * 2;
                uint32_t bh[4], bl[4];
                ldsm4t(bh, sBh_b + off);
                ldsm4t(bl, sBl_b + off);
#pragma unroll
                for (int mf = 0; mf < 2; ++mf) {
                    mma16816(acc[mf][nf2 * 2], ah[mf], bh);
                    mma16816(acc[mf][nf2 * 2], ah[mf], bl);
                    mma16816(acc[mf][nf2 * 2], al[mf], bh);
                    mma16816(acc[mf][nf2 * 2 + 1], ah[mf], bh + 2);
                    mma16816(acc[mf][nf2 * 2 + 1], ah[mf], bl + 2);
                    mma16816(acc[mf][nf2 * 2 + 1], al[mf], bh + 2);
                }
            }
        }
    }
    int c0 = wn * 64 + (lane & 3) * 2;
#pragma unroll
    for (int mf = 0; mf < 2; ++mf) {
        int r0 = rowBase + wm * 32 + mf * 16 + (lane >> 2);
#pragma unroll
        for (int nf = 0; nf < 8; ++nf) {
            int col = c0 + nf * 8;
            if (SCATTER) {
                if (r0 < M)
                    red2(&C[(size_t)sidx[r0] * 128 + col], acc[mf][nf][0],
                         acc[mf][nf][1]);
                if (r0 + 8 < M)
                    red2(&C[(size_t)sidx[r0 + 8] * 128 + col], acc[mf][nf][2],
                         acc[mf][nf][3]);
            } else {
                float2 bv = *(const float2*)&bias[col];
                if (r0 < M) {
                    C[(size_t)r0 * 128 + col] = acc[mf][nf][0] + bv.x;
                    C[(size_t)r0 * 128 + col + 1] = acc[mf][nf][1] + bv.y;
                }
                if (r0 + 8 < M) {
                    C[(size_t)(r0 + 8) * 128 + col] = acc[mf][nf][2] + bv.x;
                    C[(size_t)(r0 + 8) * 128 + col + 1] = acc[mf][nf][3] + bv.y;
                }
            }
        }
    }
}

struct Pair {
    const float* A[2];
    const float* W[2];
    const float* bias[2];
    float* C[2];
    int M[2];
};

__global__ __launch_bounds__(256, 2) void tc_gemm_scatter_kernel(
    const float* __restrict__ A, const float* __restrict__ B,
    float* __restrict__ C, const int* __restrict__ sidx, int M) {
    tc_gemm_core<true>(A, B, nullptr, C, sidx, M);
}
__global__ __launch_bounds__(256, 2) void tc_gemm_pair_kernel(Pair pr) {
    int z = blockIdx.y;
    tc_gemm_core<false>(pr.A[z], pr.W[z], pr.bias[z], pr.C[z], nullptr,
                        pr.M[z]);
}

// ---------------- atom -> chemical count ----------------
__global__ void count_kernel(const int* __restrict__ hd, float* __restrict__ cnt,
                             int n) {
    int i = blockIdx.x * blockDim.x + threadIdx.x;
    if (i < n) atomicAdd(&cnt[hd[i]], 1.f);
}
__global__ void combine_kernel(const float* __restrict__ sum,
                               const float* __restrict__ cnt,
                               const float* __restrict__ xc,
                               float* __restrict__ out, int n) {
    int i = blockIdx.x * blockDim.x + threadIdx.x;
    if (i < n) out[i] = sum[i] / fmaxf(cnt[i >> 7], 1.f) + xc[i];
}

// ---------------- fused edge pass (one warp per edge) ------------------------
__global__ void edge_fused_kernel(const float* __restrict__ xl,
                                  const float* __restrict__ xr,
                                  const int* __restrict__ src,
                                  const int* __restrict__ dst,
                                  const float* __restrict__ a,
                                  float* __restrict__ tmp,
                                  float* __restrict__ den, int E) {
    int w = (blockIdx.x * blockDim.x + threadIdx.x) >> 5;
    int lane = threadIdx.x & 31;
    if (w >= E) return;
    int s = src[w], d = dst[w];
    float4 l4 = *(const float4*)&xl[(size_t)s * 128 + lane * 4];
    float4 r4 = *(const float4*)&xr[(size_t)d * 128 + lane * 4];
    float4 av = *(const float4*)&a[lane * 4];
    float x0 = l4.x + r4.x; x0 = x0 > 0.f ? x0 : 0.2f * x0;
    float x1 = l4.y + r4.y; x1 = x1 > 0.f ? x1 : 0.2f * x1;
    float x2 = l4.z + r4.z; x2 = x2 > 0.f ? x2 : 0.2f * x2;
    float x3 = l4.w + r4.w; x3 = x3 > 0.f ? x3 : 0.2f * x3;
    float p = x0 * av.x + x1 * av.y + x2 * av.z + x3 * av.w;
    p = wsum(p);
    float ex = expf(p);
    float* o = tmp + (size_t)d * 128 + lane * 4;
    red4(o, make_float4(ex * l4.x, ex * l4.y, ex * l4.z, ex * l4.w));
    if (lane == 0) atomicAdd(&den[d], ex);
}

// agg[d] += tmp[d]/max(den[d],eps); re-zeroes tmp and den for next relation
__global__ void norm_acc_kernel(float* __restrict__ tmp,
                                float* __restrict__ den,
                                float* __restrict__ agg, int Nd) {
    int i = blockIdx.x * blockDim.x + threadIdx.x;
    if (i >= Nd * (HD / 4)) return;
    int d = i >> 5;
    float inv = 1.f / fmaxf(den[d], 1e-16f);
    float4 t = ((const float4*)tmp)[i];
    ((float4*)tmp)[i] = make_float4(0.f, 0.f, 0.f, 0.f);
    float4 g = ((float4*)agg)[i];
    g.x += t.x * inv; g.y += t.y * inv; g.z += t.z * inv; g.w += t.w * inv;
    ((float4*)agg)[i] = g;
    if ((i & 31) == 0) den[d] = 0.f;
}

// combined GATv2 output bias per dst type
__global__ void cbias_kernel(const float* __restrict__ cb_l,
                             float* __restrict__ out3) {
    int c = threadIdx.x;
    float s[3] = {0.f, 0.f, 0.f};
#pragma unroll
    for (int r = 0; r < RR; ++r) s[c_RD[r]] += cb_l[r * HD + c];
    out3[c] = s[0];
    out3[HD + c] = s[1];
    out3[2 * HD + c] = s[2];
}

// ---------------- layernorm + relu (warp per row), with folded cb bias -------
__global__ void ln_relu_kernel(const float* __restrict__ in,
                               const float* __restrict__ cbias,
                               const float* __restrict__ g,
                               const float* __restrict__ b,
                               float* __restrict__ out, int N) {
    int row = (blockIdx.x * blockDim.x + threadIdx.x) >> 5;
    int lane = threadIdx.x & 31;
    if (row >= N) return;
    float4 v = *(const float4*)&in[(size_t)row * 128 + lane * 4];
    float4 cv = *(const float4*)&cbias[lane * 4];
    v.x += cv.x; v.y += cv.y; v.z += cv.z; v.w += cv.w;
    float s = v.x + v.y + v.z + v.w;
    s = wsum(s);
    float mu = s * (1.f / 128.f);
    float d0 = v.x - mu, d1 = v.y - mu, d2 = v.z - mu, d3 = v.w - mu;
    float ss = d0 * d0 + d1 * d1 + d2 * d2 + d3 * d3;
    ss = wsum(ss);
    float inv = rsqrtf(ss * (1.f / 128.f) + 1e-5f);
    float4 gv = *(const float4*)&g[lane * 4];
    float4 bv = *(const float4*)&b[lane * 4];
    float4 o;
    o.x = fmaxf(d0 * inv * gv.x + bv.x, 0.f);
    o.y = fmaxf(d1 * inv * gv.y + bv.y, 0.f);
    o.z = fmaxf(d2 * inv * gv.z + bv.z, 0.f);
    o.w = fmaxf(d3 * inv * gv.w + bv.w, 0.f);
    *(float4*)&out[(size_t)row * 128 + lane * 4] = o;
}

// ---------------- prediction head ----------------
__global__ void pred_kernel(const float* __restrict__ x,
                            const float* __restrict__ Wp,
                            const float* __restrict__ bp,
                            float* __restrict__ out, int N) {
    int row = (blockIdx.x * blockDim.x + threadIdx.x) >> 5;
    int lane = threadIdx.x & 31;
    if (row >= N) return;
    float4 xv = *(const float4*)&x[(size_t)row * 128 + lane * 4];
    float4 w01 = *(const float4*)&Wp[lane * 8];
    float4 w23 = *(const float4*)&Wp[lane * 8 + 4];
    float a0 = xv.x * w01.x + xv.y * w01.z + xv.z * w23.x + xv.w * w23.z;
    float a1 = xv.x * w01.y + xv.y * w01.w + xv.z * w23.y + xv.w * w23.w;
    a0 = wsum(a0);
    a1 = wsum(a1);
    if (lane == 0) {
        out[row * 2 + 0] = a0 + bp[0];
        out[row * 2 + 1] = a1 + bp[1];
    }
}

// ---------------- host orchestration ----------------
extern "C" void kernel_launch(void* const* d_in, const int* in_sizes, int n_in,
                              void* d_out, int out_size) {
    const float* x_atom = (const float*)d_in[0];
    const float* x_chem = (const float*)d_in[1];
    const float* x_gene = (const float*)d_in[2];
    const float* x_assay = (const float*)d_in[3];
    const float* W_mol = (const float*)d_in[4];
    const float* Wl = (const float*)d_in[5];
    const float* Wr = (const float*)d_in[6];
    const float* bl = (const float*)d_in[7];
    const float* br = (const float*)d_in[8];
    const float* att = (const float*)d_in[9];
    const float* cb = (const float*)d_in[10];
    const float* lng = (const float*)d_in[11];
    const float* lnb = (const float*)d_in[12];
    const float* Wp = (const float*)d_in[13];
    const float* bp = (const float*)d_in[14];
    const int* hyper = (const int*)d_in[15];
    const int* eir = (const int*)d_in[16];
    float* out = (float*)d_out;
    (void)in_sizes; (void)n_in; (void)out_size;

    float *px0, *px1, *px2, *pa0, *pa1, *pa2, *pxl, *pxr, *pt, *pden, *pcnt,
        *pcb;
    cudaGetSymbolAddress((void**)&px0, g_x0);
    cudaGetSymbolAddress((void**)&px1, g_x1);
    cudaGetSymbolAddress((void**)&px2, g_x2);
    cudaGetSymbolAddress((void**)&pa0, g_a0);
    cudaGetSymbolAddress((void**)&pa1, g_a1);
    cudaGetSymbolAddress((void**)&pa2, g_a2);
    cudaGetSymbolAddress((void**)&pxl, g_xl);
    cudaGetSymbolAddress((void**)&pxr, g_xr);
    cudaGetSymbolAddress((void**)&pt, g_t);
    cudaGetSymbolAddress((void**)&pden, g_den);
    cudaGetSymbolAddress((void**)&pcnt, g_cnt);
    cudaGetSymbolAddress((void**)&pcb, g_cbias);

    // one-time stream/event creation (first call is the uncaptured
    // correctness run; capture replays see only the recorded dependencies)
    static cudaStream_t s1 = nullptr;
    static cudaEvent_t evFork, evG[LL * RR], evE[LL * RR], evL[LL];
    if (!s1) {
        cudaStreamCreateWithFlags(&s1, cudaStreamNonBlocking);
        cudaEventCreateWithFlags(&evFork, cudaEventDisableTiming);
        for (int i = 0; i < LL * RR; ++i) {
            cudaEventCreateWithFlags(&evG[i], cudaEventDisableTiming);
            cudaEventCreateWithFlags(&evE[i], cudaEventDisableTiming);
        }
        for (int i = 0; i < LL; ++i)
            cudaEventCreateWithFlags(&evL[i], cudaEventDisableTiming);
    }

    const int T = 256;
    const int ZB = 1024;
    const int SMEMB = 65536;

    cudaFuncSetAttribute(tc_gemm_scatter_kernel,
                         cudaFuncAttributeMaxDynamicSharedMemorySize, SMEMB);
    cudaFuncSetAttribute(tc_gemm_pair_kernel,
                         cudaFuncAttributeMaxDynamicSharedMemorySize, SMEMB);

    static const int RS[RR] = {0, 0, 0, 0, 0, 2, 1, 2, 2, 1, 1, 1, 1};
    static const int RD[RR] = {2, 2, 1, 1, 1, 1, 1, 0, 0, 0, 0, 0, 2};
    const int NT[3] = {N0, N1, N2};

    // ---- atom encoder + bottom-up mean aggregation into chemical (stream 0) --
    zero_f_kernel<<<ZB, T>>>(pa0, N0 * HD);
    zero_f_kernel<<<(N0 + T - 1) / T, T>>>(pcnt, N0);
    zero_td_kernel<<<ZB, T>>>(pt, pden, N0);  // norm_acc keeps these zeroed
    count_kernel<<<(NA + T - 1) / T, T>>>(hyper, pcnt, NA);
    tc_gemm_scatter_kernel<<<(NA + 127) / 128, T, SMEMB>>>(x_atom, W_mol, pa0,
                                                           hyper, NA);
    combine_kernel<<<(N0 * HD + T - 1) / T, T>>>(pa0, pcnt, x_chem, px0,
                                                 N0 * HD);

    // fork: s1 joins the dependency graph after the prelude
    cudaEventRecord(evFork, 0);
    cudaStreamWaitEvent(s1, evFork, 0);

    const float* xsrc[3] = {px0, x_gene, x_assay};
    float* agg[3] = {pa0, pa1, pa2};
    float* xnew[3] = {px0, px1, px2};

    for (int l = 0; l < LL; ++l) {
        zero_f_kernel<<<ZB, T>>>(pa0, N0 * HD);
        zero_f_kernel<<<ZB, T>>>(pa1, N1 * HD);
        zero_f_kernel<<<ZB, T>>>(pa2, N2 * HD);
        size_t lo = (size_t)l * RR;
        cbias_kernel<<<1, HD>>>(cb + lo * HD, pcb);

        for (int r = 0; r < RR; ++r) {
            int s = RS[r], d = RD[r];
            int Ns = NT[s], Nd = NT[d];
            size_t wo = lo + r;
            int idx = l * RR + r;
            int buf = idx & 1;
            float* bxl = pxl + (size_t)buf * SLAB;
            float* bxr = pxr + (size_t)buf * SLAB;

            // producer (s1): GEMM pair into buffer `buf`
            if (idx >= 2) cudaStreamWaitEvent(s1, evE[idx - 2], 0);  // WAR
            Pair pr;
            pr.A[0] = xsrc[s];  pr.M[0] = Ns;
            pr.A[1] = xsrc[d];  pr.M[1] = Nd;
            pr.W[0] = Wl + wo * HD * HD;
            pr.W[1] = Wr + wo * HD * HD;
            pr.bias[0] = bl + wo * HD;
            pr.bias[1] = br + wo * HD;
            pr.C[0] = bxl;
            pr.C[1] = bxr;
            int mx = Ns > Nd ? Ns : Nd;
            dim3 ggrid((mx + 127) / 128, 2);
            tc_gemm_pair_kernel<<<ggrid, T, SMEMB, s1>>>(pr);
            cudaEventRecord(evG[idx], s1);

            // consumer (stream 0): edge pass + normalize
            cudaStreamWaitEvent(0, evG[idx], 0);
            const int* srcp = eir + (size_t)r * 2 * NE;
            const int* dstp = srcp + NE;
            edge_fused_kernel<<<(NE + 7) / 8, T>>>(bxl, bxr, srcp, dstp,
                                                   att + wo * HD, pt, pden, NE);
            norm_acc_kernel<<<(Nd * (HD / 4) + T - 1) / T, T>>>(pt, pden,
                                                                agg[d], Nd);
            cudaEventRecord(evE[idx], 0);
        }
        for (int t = 0; t < 3; ++t) {
            ln_relu_kernel<<<(NT[t] * 32 + T - 1) / T, T>>>(
                agg[t], pcb + t * HD, lng + (size_t)(l * 3 + t) * HD,
                lnb + (size_t)(l * 3 + t) * HD, xnew[t], NT[t]);
        }
        xsrc[0] = px0; xsrc[1] = px1; xsrc[2] = px2;
        // next layer's GEMMs (on s1) read xnew -> wait for ln_relu
        cudaEventRecord(evL[l], 0);
        cudaStreamWaitEvent(s1, evL[l], 0);
    }

    pred_kernel<<<(N0 * 32 + T - 1) / T, T>>>(px0, Wp, bp, out, N0);
}

// round 7
// speedup vs baseline: 3.6792x; 1.4314x over previous
#include <cuda_runtime.h>
#include <cuda_bf16.h>
#include <math.h>
#include <stdint.h>

#define N0 20000
#define N1 20000
#define N2 10000
#define NA 600000
#define NE 400000
#define HD 128
#define RR 13
#define LL 2
#define SLAB (N0 * HD)
#define CBASE 20000           // per-relation counter stride
#define NCNT 260096           // 1016 * 256 (flat counter array, zero-padded)
#define NBLK 1016

// ---------------- scratch (static device globals; no allocation) ---------------
__device__ float g_x0[N0 * HD];
__device__ float g_x1[N1 * HD];
__device__ float g_x2[N2 * HD];
__device__ float g_a0[N0 * HD];
__device__ float g_a1[N1 * HD];
__device__ float g_a2[N2 * HD];
__device__ float g_xl[2 * SLAB];  // double-buffered GEMM outputs
__device__ float g_xr[2 * SLAB];
__device__ float g_cnt[N0];
__device__ float g_cbias[3 * HD];
// CSR scratch
__device__ int g_counts[NCNT];
__device__ int g_offs[NCNT];
__device__ int g_fill[NCNT];
__device__ int g_sums[NBLK];
__device__ int g_ssorted[RR * NE];  // 20.8 MB: src ids grouped by dst

__constant__ int c_RD[RR] = {2, 2, 1, 1, 1, 1, 1, 0, 0, 0, 0, 0, 2};

// ---------------- helpers ----------------
__device__ __forceinline__ float wsum(float v) {
#pragma unroll
    for (int o = 16; o; o >>= 1) v += __shfl_xor_sync(0xffffffffu, v, o);
    return v;
}
__device__ __forceinline__ void red2(float* p, float a, float b) {
    asm volatile("red.global.add.v2.f32 [%0], {%1,%2};" ::"l"(p), "f"(a),
                 "f"(b)
                 : "memory");
}
__device__ __forceinline__ void ldsm4(uint32_t* r, uint32_t addr) {
    asm volatile(
        "ldmatrix.sync.aligned.m8n8.x4.shared.b16 {%0,%1,%2,%3}, [%4];"
        : "=r"(r[0]), "=r"(r[1]), "=r"(r[2]), "=r"(r[3])
        : "r"(addr));
}
__device__ __forceinline__ void ldsm4t(uint32_t* r, uint32_t addr) {
    asm volatile(
        "ldmatrix.sync.aligned.m8n8.x4.trans.shared.b16 {%0,%1,%2,%3}, [%4];"
        : "=r"(r[0]), "=r"(r[1]), "=r"(r[2]), "=r"(r[3])
        : "r"(addr));
}
__device__ __forceinline__ void mma16816(float* d, const uint32_t* a,
                                         const uint32_t* b) {
    asm volatile(
        "mma.sync.aligned.m16n8k16.row.col.f32.bf16.bf16.f32 "
        "{%0,%1,%2,%3}, {%4,%5,%6,%7}, {%8,%9}, {%0,%1,%2,%3};"
        : "+f"(d[0]), "+f"(d[1]), "+f"(d[2]), "+f"(d[3])
        : "r"(a[0]), "r"(a[1]), "r"(a[2]), "r"(a[3]), "r"(b[0]), "r"(b[1]));
}
__device__ __forceinline__ void split4(float4 v, uint2& hi, uint2& lo) {
    __nv_bfloat162 h0 = __floats2bfloat162_rn(v.x, v.y);
    __nv_bfloat162 h1 = __floats2bfloat162_rn(v.z, v.w);
    float2 f0 = __bfloat1622float2(h0);
    float2 f1 = __bfloat1622float2(h1);
    __nv_bfloat162 l0 = __floats2bfloat162_rn(v.x - f0.x, v.y - f0.y);
    __nv_bfloat162 l1 = __floats2bfloat162_rn(v.z - f1.x, v.w - f1.y);
    hi = make_uint2(*(uint32_t*)&h0, *(uint32_t*)&h1);
    lo = make_uint2(*(uint32_t*)&l0, *(uint32_t*)&l1);
}

// ---------------- zero kernels ----------------
__global__ void zero_f_kernel(float* p, int n) {
    int i = blockIdx.x * blockDim.x + threadIdx.x;
    int st = gridDim.x * blockDim.x;
    for (; i < n; i += st) p[i] = 0.f;
}
__global__ void zero_i_kernel(int* p, int n) {
    int i = blockIdx.x * blockDim.x + threadIdx.x;
    int st = gridDim.x * blockDim.x;
    for (; i < n; i += st) p[i] = 0;
}

// ---------------- CSR build ----------------
__global__ void hist_kernel(const int* __restrict__ eir,
                            int* __restrict__ cnt) {
    int r = blockIdx.y;
    int i = blockIdx.x * blockDim.x + threadIdx.x;
    if (i < NE) atomicAdd(&cnt[r * CBASE + eir[(size_t)r * 2 * NE + NE + i]], 1);
}
__global__ void scanA_kernel(const int* __restrict__ cnt, int* __restrict__ out,
                             int* __restrict__ sums) {
    __shared__ int sh[256];
    int i = blockIdx.x * 256 + threadIdx.x;
    int v = cnt[i];
    sh[threadIdx.x] = v;
    __syncthreads();
    for (int o = 1; o < 256; o <<= 1) {
        int t = (threadIdx.x >= o) ? sh[threadIdx.x - o] : 0;
        __syncthreads();
        sh[threadIdx.x] += t;
        __syncthreads();
    }
    out[i] = sh[threadIdx.x] - v;
    if (threadIdx.x == 255) sums[blockIdx.x] = sh[255];
}
__global__ void scanB_kernel(int* __restrict__ sums) {
    __shared__ int sh[1024];
    int v = (threadIdx.x < NBLK) ? sums[threadIdx.x] : 0;
    sh[threadIdx.x] = v;
    __syncthreads();
    for (int o = 1; o < 1024; o <<= 1) {
        int t = (threadIdx.x >= o) ? sh[threadIdx.x - o] : 0;
        __syncthreads();
        sh[threadIdx.x] += t;
        __syncthreads();
    }
    if (threadIdx.x < NBLK) sums[threadIdx.x] = sh[threadIdx.x] - v;
}
__global__ void scanC_kernel(int* __restrict__ out, const int* __restrict__ sums,
                             int* __restrict__ fill) {
    int i = blockIdx.x * 256 + threadIdx.x;
    int v = out[i] + sums[blockIdx.x];
    out[i] = v;
    fill[i] = v;
}
__global__ void csr_scatter_kernel(const int* __restrict__ eir,
                                   int* __restrict__ fill,
                                   int* __restrict__ ssorted) {
    int r = blockIdx.y;
    int i = blockIdx.x * blockDim.x + threadIdx.x;
    if (i >= NE) return;
    int d = eir[(size_t)r * 2 * NE + NE + i];
    int s = eir[(size_t)r * 2 * NE + i];
    int pos = atomicAdd(&fill[r * CBASE + d], 1);
    ssorted[pos] = s;
}

// ---------------- tensor-core bf16x3 GEMM core ------------------------------
template <bool SCATTER>
__device__ __forceinline__ void tc_gemm_core(const float* __restrict__ A,
                                             const float* __restrict__ B,
                                             const float* __restrict__ bias,
                                             float* __restrict__ C,
                                             const int* __restrict__ sidx,
                                             int M) {
    extern __shared__ __nv_bfloat16 sm[];
    __nv_bfloat16* sAh = sm;
    __nv_bfloat16* sAl = sm + 8192;
    __nv_bfloat16* sBh = sm + 16384;
    __nv_bfloat16* sBl = sm + 24576;
    const int tid = threadIdx.x;
    const int lane = tid & 31, warp = tid >> 5;
    const int wm = warp & 3, wn = warp >> 2;
    const int rowBase = blockIdx.x * 128;
    if (rowBase >= M) return;

    float acc[2][8][4];
#pragma unroll
    for (int a = 0; a < 2; ++a)
#pragma unroll
        for (int b = 0; b < 8; ++b)
#pragma unroll
            for (int c = 0; c < 4; ++c) acc[a][b][c] = 0.f;

    uint32_t sAh_b = (uint32_t)__cvta_generic_to_shared(sAh);
    uint32_t sAl_b = (uint32_t)__cvta_generic_to_shared(sAl);
    uint32_t sBh_b = (uint32_t)__cvta_generic_to_shared(sBh);
    uint32_t sBl_b = (uint32_t)__cvta_generic_to_shared(sBl);

    for (int kc = 0; kc < 128; kc += 64) {
        __syncthreads();
#pragma unroll
        for (int i = 0; i < 8; ++i) {
            int j = tid + 256 * i;
            int row = j >> 4, c4 = j & 15;
            float4 v = make_float4(0.f, 0.f, 0.f, 0.f);
            if (rowBase + row < M)
                v = *(const float4*)&A[(size_t)(rowBase + row) * 128 + kc +
                                       c4 * 4];
            uint2 h, l;
            split4(v, h, l);
            int off = row * 64 + (((c4 >> 1) ^ (row & 7)) << 3) + (c4 & 1) * 4;
            *(uint2*)&sAh[off] = h;
            *(uint2*)&sAl[off] = l;
        }
#pragma unroll
        for (int i = 0; i < 8; ++i) {
            int j = tid + 256 * i;
            int row = j >> 5, c4 = j & 31;
            float4 v = *(const float4*)&B[(size_t)(kc + row) * 128 + c4 * 4];
            uint2 h, l;
            split4(v, h, l);
            int off = row * 128 + (((c4 >> 1) ^ (row & 7)) << 3) + (c4 & 1) * 4;
            *(uint2*)&sBh[off] = h;
            *(uint2*)&sBl[off] = l;
        }
        __syncthreads();
#pragma unroll
        for (int s = 0; s < 4; ++s) {
            uint32_t ah[2][4], al[2][4];
#pragma unroll
            for (int mf = 0; mf < 2; ++mf) {
                int mr = wm * 32 + mf * 16 + (lane & 15);
                int ck = 2 * s + (lane >> 4);
                uint32_t off = (uint32_t)(mr * 64 + ((ck ^ (mr & 7)) << 3)) * 2;
                ldsm4(ah[mf], sAh_b + off);
                ldsm4(al[mf], sAl_b + off);
            }
#pragma unroll
            for (int nf2 = 0; nf2 < 4; ++nf2) {
                int kr = s * 16 + (lane & 7) + ((lane >> 3) & 1) * 8;
                int cn = wn * 8 + nf2 * 2 + (lane >> 4);
                uint32_t off =
                    (uint32_t)(kr * 128 + ((cn ^ (kr & 7)) << 3)) * 2;
                uint32_t bh[4], bl[4];
                ldsm4t(bh, sBh_b + off);
                ldsm4t(bl, sBl_b + off);
#pragma unroll
                for (int mf = 0; mf < 2; ++mf) {
                    mma16816(acc[mf][nf2 * 2], ah[mf], bh);
                    mma16816(acc[mf][nf2 * 2], ah[mf], bl);
                    mma16816(acc[mf][nf2 * 2], al[mf], bh);
                    mma16816(acc[mf][nf2 * 2 + 1], ah[mf], bh + 2);
                    mma16816(acc[mf][nf2 * 2 + 1], ah[mf], bl + 2);
                    mma16816(acc[mf][nf2 * 2 + 1], al[mf], bh + 2);
                }
            }
        }
    }
    int c0 = wn * 64 + (lane & 3) * 2;
#pragma unroll
    for (int mf = 0; mf < 2; ++mf) {
        int r0 = rowBase + wm * 32 + mf * 16 + (lane >> 2);
#pragma unroll
        for (int nf = 0; nf < 8; ++nf) {
            int col = c0 + nf * 8;
            if (SCATTER) {
                if (r0 < M)
                    red2(&C[(size_t)sidx[r0] * 128 + col], acc[mf][nf][0],
                         acc[mf][nf][1]);
                if (r0 + 8 < M)
                    red2(&C[(size_t)sidx[r0 + 8] * 128 + col], acc[mf][nf][2],
                         acc[mf][nf][3]);
            } else {
                float2 bv = *(const float2*)&bias[col];
                if (r0 < M) {
                    C[(size_t)r0 * 128 + col] = acc[mf][nf][0] + bv.x;
                    C[(size_t)r0 * 128 + col + 1] = acc[mf][nf][1] + bv.y;
                }
                if (r0 + 8 < M) {
                    C[(size_t)(r0 + 8) * 128 + col] = acc[mf][nf][2] + bv.x;
                    C[(size_t)(r0 + 8) * 128 + col + 1] = acc[mf][nf][3] + bv.y;
                }
            }
        }
    }
}

struct Pair {
    const float* A[2];
    const float* W[2];
    const float* bias[2];
    float* C[2];
    int M[2];
};

__global__ __launch_bounds__(256, 2) void tc_gemm_scatter_kernel(
    const float* __restrict__ A, const float* __restrict__ B,
    float* __restrict__ C, const int* __restrict__ sidx, int M) {
    tc_gemm_core<true>(A, B, nullptr, C, sidx, M);
}
__global__ __launch_bounds__(256, 2) void tc_gemm_pair_kernel(Pair pr) {
    int z = blockIdx.y;
    tc_gemm_core<false>(pr.A[z], pr.W[z], pr.bias[z], pr.C[z], nullptr,
                        pr.M[z]);
}

// ---------------- atom -> chemical count ----------------
__global__ void count_kernel(const int* __restrict__ hd, float* __restrict__ cnt,
                             int n) {
    int i = blockIdx.x * blockDim.x + threadIdx.x;
    if (i < n) atomicAdd(&cnt[hd[i]], 1.f);
}
__global__ void combine_kernel(const float* __restrict__ sum,
                               const float* __restrict__ cnt,
                               const float* __restrict__ xc,
                               float* __restrict__ out, int n) {
    int i = blockIdx.x * blockDim.x + threadIdx.x;
    if (i < n) out[i] = sum[i] / fmaxf(cnt[i >> 7], 1.f) + xc[i];
}

// ---------------- CSR edge aggregation (one warp per dst node) ---------------
// Full GATv2 relation pass in registers: logits, exp (shift-free), weighted
// accumulate, normalize, direct non-atomic agg update (one warp owns a dst).
__global__ __launch_bounds__(256) void edge_csr_kernel(
    const int* __restrict__ ssorted, const int* __restrict__ offs,
    const float* __restrict__ xl, const float* __restrict__ xr,
    const float* __restrict__ a, float* __restrict__ agg, int Nd, int robase) {
    int d = (blockIdx.x * blockDim.x + threadIdx.x) >> 5;
    int lane = threadIdx.x & 31;
    if (d >= Nd) return;
    int beg = offs[robase + d], end = offs[robase + d + 1];
    if (beg == end) return;
    float4 r4 = *(const float4*)&xr[(size_t)d * 128 + lane * 4];
    float4 av = *(const float4*)&a[lane * 4];
    float4 acc = make_float4(0.f, 0.f, 0.f, 0.f);
    float sden = 0.f;
    int s = ssorted[beg];
    for (int j = beg; j < end; ++j) {
        float4 l4 = *(const float4*)&xl[(size_t)s * 128 + lane * 4];
        if (j + 1 < end) s = ssorted[j + 1];  // prefetch next src id
        float x0 = l4.x + r4.x; x0 = x0 > 0.f ? x0 : 0.2f * x0;
        float x1 = l4.y + r4.y; x1 = x1 > 0.f ? x1 : 0.2f * x1;
        float x2 = l4.z + r4.z; x2 = x2 > 0.f ? x2 : 0.2f * x2;
        float x3 = l4.w + r4.w; x3 = x3 > 0.f ? x3 : 0.2f * x3;
        float p = x0 * av.x + x1 * av.y + x2 * av.z + x3 * av.w;
        p = wsum(p);
        float ex = expf(p);
        acc.x += ex * l4.x; acc.y += ex * l4.y;
        acc.z += ex * l4.z; acc.w += ex * l4.w;
        sden += ex;
    }
    float inv = 1.f / fmaxf(sden, 1e-16f);
    float* o = &agg[(size_t)d * 128 + lane * 4];
    float4 g = *(float4*)o;
    g.x += acc.x * inv; g.y += acc.y * inv;
    g.z += acc.z * inv; g.w += acc.w * inv;
    *(float4*)o = g;
}

// combined GATv2 output bias per dst type
__global__ void cbias_kernel(const float* __restrict__ cb_l,
                             float* __restrict__ out3) {
    int c = threadIdx.x;
    float s[3] = {0.f, 0.f, 0.f};
#pragma unroll
    for (int r = 0; r < RR; ++r) s[c_RD[r]] += cb_l[r * HD + c];
    out3[c] = s[0];
    out3[HD + c] = s[1];
    out3[2 * HD + c] = s[2];
}

// ---------------- layernorm + relu (warp per row), with folded cb bias -------
__global__ void ln_relu_kernel(const float* __restrict__ in,
                               const float* __restrict__ cbias,
                               const float* __restrict__ g,
                               const float* __restrict__ b,
                               float* __restrict__ out, int N) {
    int row = (blockIdx.x * blockDim.x + threadIdx.x) >> 5;
    int lane = threadIdx.x & 31;
    if (row >= N) return;
    float4 v = *(const float4*)&in[(size_t)row * 128 + lane * 4];
    float4 cv = *(const float4*)&cbias[lane * 4];
    v.x += cv.x; v.y += cv.y; v.z += cv.z; v.w += cv.w;
    float s = v.x + v.y + v.z + v.w;
    s = wsum(s);
    float mu = s * (1.f / 128.f);
    float d0 = v.x - mu, d1 = v.y - mu, d2 = v.z - mu, d3 = v.w - mu;
    float ss = d0 * d0 + d1 * d1 + d2 * d2 + d3 * d3;
    ss = wsum(ss);
    float inv = rsqrtf(ss * (1.f / 128.f) + 1e-5f);
    float4 gv = *(const float4*)&g[lane * 4];
    float4 bv = *(const float4*)&b[lane * 4];
    float4 o;
    o.x = fmaxf(d0 * inv * gv.x + bv.x, 0.f);
    o.y = fmaxf(d1 * inv * gv.y + bv.y, 0.f);
    o.z = fmaxf(d2 * inv * gv.z + bv.z, 0.f);
    o.w = fmaxf(d3 * inv * gv.w + bv.w, 0.f);
    *(float4*)&out[(size_t)row * 128 + lane * 4] = o;
}

// ---------------- prediction head ----------------
__global__ void pred_kernel(const float* __restrict__ x,
                            const float* __restrict__ Wp,
                            const float* __restrict__ bp,
                            float* __restrict__ out, int N) {
    int row = (blockIdx.x * blockDim.x + threadIdx.x) >> 5;
    int lane = threadIdx.x & 31;
    if (row >= N) return;
    float4 xv = *(const float4*)&x[(size_t)row * 128 + lane * 4];
    float4 w01 = *(const float4*)&Wp[lane * 8];
    float4 w23 = *(const float4*)&Wp[lane * 8 + 4];
    float a0 = xv.x * w01.x + xv.y * w01.z + xv.z * w23.x + xv.w * w23.z;
    float a1 = xv.x * w01.y + xv.y * w01.w + xv.z * w23.y + xv.w * w23.w;
    a0 = wsum(a0);
    a1 = wsum(a1);
    if (lane == 0) {
        out[row * 2 + 0] = a0 + bp[0];
        out[row * 2 + 1] = a1 + bp[1];
    }
}

// ---------------- host orchestration ----------------
extern "C" void kernel_launch(void* const* d_in, const int* in_sizes, int n_in,
                              void* d_out, int out_size) {
    const float* x_atom = (const float*)d_in[0];
    const float* x_chem = (const float*)d_in[1];
    const float* x_gene = (const float*)d_in[2];
    const float* x_assay = (const float*)d_in[3];
    const float* W_mol = (const float*)d_in[4];
    const float* Wl = (const float*)d_in[5];
    const float* Wr = (const float*)d_in[6];
    const float* bl = (const float*)d_in[7];
    const float* br = (const float*)d_in[8];
    const float* att = (const float*)d_in[9];
    const float* cb = (const float*)d_in[10];
    const float* lng = (const float*)d_in[11];
    const float* lnb = (const float*)d_in[12];
    const float* Wp = (const float*)d_in[13];
    const float* bp = (const float*)d_in[14];
    const int* hyper = (const int*)d_in[15];
    const int* eir = (const int*)d_in[16];
    float* out = (float*)d_out;
    (void)in_sizes; (void)n_in; (void)out_size;

    float *px0, *px1, *px2, *pa0, *pa1, *pa2, *pxl, *pxr, *pcnt, *pcb;
    int *pcounts, *poffs, *pfill, *psums, *pss;
    cudaGetSymbolAddress((void**)&px0, g_x0);
    cudaGetSymbolAddress((void**)&px1, g_x1);
    cudaGetSymbolAddress((void**)&px2, g_x2);
    cudaGetSymbolAddress((void**)&pa0, g_a0);
    cudaGetSymbolAddress((void**)&pa1, g_a1);
    cudaGetSymbolAddress((void**)&pa2, g_a2);
    cudaGetSymbolAddress((void**)&pxl, g_xl);
    cudaGetSymbolAddress((void**)&pxr, g_xr);
    cudaGetSymbolAddress((void**)&pcnt, g_cnt);
    cudaGetSymbolAddress((void**)&pcb, g_cbias);
    cudaGetSymbolAddress((void**)&pcounts, g_counts);
    cudaGetSymbolAddress((void**)&poffs, g_offs);
    cudaGetSymbolAddress((void**)&pfill, g_fill);
    cudaGetSymbolAddress((void**)&psums, g_sums);
    cudaGetSymbolAddress((void**)&pss, g_ssorted);

    static cudaStream_t s1 = nullptr;
    static cudaEvent_t evStart, evFork, evCSR, evG[LL * RR], evE[LL * RR],
        evL[LL];
    if (!s1) {
        cudaStreamCreateWithFlags(&s1, cudaStreamNonBlocking);
        cudaEventCreateWithFlags(&evStart, cudaEventDisableTiming);
        cudaEventCreateWithFlags(&evFork, cudaEventDisableTiming);
        cudaEventCreateWithFlags(&evCSR, cudaEventDisableTiming);
        for (int i = 0; i < LL * RR; ++i) {
            cudaEventCreateWithFlags(&evG[i], cudaEventDisableTiming);
            cudaEventCreateWithFlags(&evE[i], cudaEventDisableTiming);
        }
        for (int i = 0; i < LL; ++i)
            cudaEventCreateWithFlags(&evL[i], cudaEventDisableTiming);
    }

    const int T = 256;
    const int ZB = 1024;
    const int SMEMB = 65536;

    cudaFuncSetAttribute(tc_gemm_scatter_kernel,
                         cudaFuncAttributeMaxDynamicSharedMemorySize, SMEMB);
    cudaFuncSetAttribute(tc_gemm_pair_kernel,
                         cudaFuncAttributeMaxDynamicSharedMemorySize, SMEMB);

    static const int RS[RR] = {0, 0, 0, 0, 0, 2, 1, 2, 2, 1, 1, 1, 1};
    static const int RD[RR] = {2, 2, 1, 1, 1, 1, 1, 0, 0, 0, 0, 0, 2};
    const int NT[3] = {N0, N1, N2};

    // fork s1 at the very start: it builds the CSR concurrently with the
    // atom-encoder prelude on stream 0.
    cudaEventRecord(evStart, 0);
    cudaStreamWaitEvent(s1, evStart, 0);
    zero_i_kernel<<<256, T, 0, s1>>>(pcounts, NCNT);
    {
        dim3 hg((NE + T - 1) / T, RR);
        hist_kernel<<<hg, T, 0, s1>>>(eir, pcounts);
        scanA_kernel<<<NBLK, 256, 0, s1>>>(pcounts, poffs, psums);
        scanB_kernel<<<1, 1024, 0, s1>>>(psums);
        scanC_kernel<<<NBLK, 256, 0, s1>>>(poffs, psums, pfill);
        csr_scatter_kernel<<<hg, T, 0, s1>>>(eir, pfill, pss);
    }
    cudaEventRecord(evCSR, s1);

    // ---- atom encoder + bottom-up mean aggregation into chemical (stream 0) --
    zero_f_kernel<<<ZB, T>>>(pa0, N0 * HD);
    zero_f_kernel<<<(N0 + T - 1) / T, T>>>(pcnt, N0);
    count_kernel<<<(NA + T - 1) / T, T>>>(hyper, pcnt, NA);
    tc_gemm_scatter_kernel<<<(NA + 127) / 128, T, SMEMB>>>(x_atom, W_mol, pa0,
                                                           hyper, NA);
    combine_kernel<<<(N0 * HD + T - 1) / T, T>>>(pa0, pcnt, x_chem, px0,
                                                 N0 * HD);
    cudaEventRecord(evFork, 0);
    cudaStreamWaitEvent(s1, evFork, 0);  // s1's GEMMs read px0
    cudaStreamWaitEvent(0, evCSR, 0);    // edge kernels need the CSR

    const float* xsrc[3] = {px0, x_gene, x_assay};
    float* agg[3] = {pa0, pa1, pa2};
    float* xnew[3] = {px0, px1, px2};

    for (int l = 0; l < LL; ++l) {
        zero_f_kernel<<<ZB, T>>>(pa0, N0 * HD);
        zero_f_kernel<<<ZB, T>>>(pa1, N1 * HD);
        zero_f_kernel<<<ZB, T>>>(pa2, N2 * HD);
        size_t lo = (size_t)l * RR;
        cbias_kernel<<<1, HD>>>(cb + lo * HD, pcb);

        for (int r = 0; r < RR; ++r) {
            int s = RS[r], d = RD[r];
            int Ns = NT[s], Nd = NT[d];
            size_t wo = lo + r;
            int idx = l * RR + r;
            int buf = idx & 1;
            float* bxl = pxl + (size_t)buf * SLAB;
            float* bxr = pxr + (size_t)buf * SLAB;

            if (idx >= 2) cudaStreamWaitEvent(s1, evE[idx - 2], 0);  // WAR
            Pair pr;
            pr.A[0] = xsrc[s];  pr.M[0] = Ns;
            pr.A[1] = xsrc[d];  pr.M[1] = Nd;
            pr.W[0] = Wl + wo * HD * HD;
            pr.W[1] = Wr + wo * HD * HD;
            pr.bias[0] = bl + wo * HD;
            pr.bias[1] = br + wo * HD;
            pr.C[0] = bxl;
            pr.C[1] = bxr;
            int mx = Ns > Nd ? Ns : Nd;
            dim3 ggrid((mx + 127) / 128, 2);
            tc_gemm_pair_kernel<<<ggrid, T, SMEMB, s1>>>(pr);
            cudaEventRecord(evG[idx], s1);

            cudaStreamWaitEvent(0, evG[idx], 0);
            edge_csr_kernel<<<(Nd * 32 + T - 1) / T, T>>>(
                pss, poffs, bxl, bxr, att + wo * HD, agg[d], Nd, r * CBASE);
            cudaEventRecord(evE[idx], 0);
        }
        for (int t = 0; t < 3; ++t) {
            ln_relu_kernel<<<(NT[t] * 32 + T - 1) / T, T>>>(
                agg[t], pcb + t * HD, lng + (size_t)(l * 3 + t) * HD,
                lnb + (size_t)(l * 3 + t) * HD, xnew[t], NT[t]);
        }
        xsrc[0] = px0; xsrc[1] = px1; xsrc[2] = px2;
        cudaEventRecord(evL[l], 0);
        cudaStreamWaitEvent(s1, evL[l], 0);
    }

    pred_kernel<<<(N0 * 32 + T - 1) / T, T>>>(px0, Wp, bp, out, N0);
}

// round 8
// speedup vs baseline: 4.0270x; 1.0945x over previous
#include <cuda_runtime.h>
#include <cuda_bf16.h>
#include <math.h>
#include <stdint.h>

#define N0 20000
#define N1 20000
#define N2 10000
#define NA 600000
#define NE 400000
#define HD 128
#define RR 13
#define LL 2
#define SLAB (N0 * HD)
#define CBASE 20000           // per-relation counter stride
#define NCNT 260096           // 1016 * 256 (flat counter array, zero-padded)
#define NBLK 1016
#define NROWS (N0 + N1 + N2)  // 50000

// ---------------- scratch (static device globals; no allocation) ---------------
__device__ float g_x0[N0 * HD];
__device__ float g_x1[N1 * HD];
__device__ float g_x2[N2 * HD];
__device__ float g_a0[N0 * HD];
__device__ float g_a1[N1 * HD];
__device__ float g_a2[N2 * HD];
__device__ float g_xl[2 * SLAB];  // double-buffered GEMM outputs
__device__ float g_xr[2 * SLAB];
__device__ float g_cnt[N0];
__device__ float g_cbias[LL * 3 * HD];
// CSR scratch
__device__ int g_counts[NCNT];
__device__ int g_offs[NCNT];
__device__ int g_fill[NCNT];
__device__ int g_sums[NBLK];
__device__ int g_ssorted[RR * NE];  // 20.8 MB: src ids grouped by dst

__constant__ int c_RD[RR] = {2, 2, 1, 1, 1, 1, 1, 0, 0, 0, 0, 0, 2};

// ---------------- helpers ----------------
__device__ __forceinline__ float wsum(float v) {
#pragma unroll
    for (int o = 16; o; o >>= 1) v += __shfl_xor_sync(0xffffffffu, v, o);
    return v;
}
__device__ __forceinline__ void red2(float* p, float a, float b) {
    asm volatile("red.global.add.v2.f32 [%0], {%1,%2};" ::"l"(p), "f"(a),
                 "f"(b)
                 : "memory");
}
__device__ __forceinline__ void ldsm4(uint32_t* r, uint32_t addr) {
    asm volatile(
        "ldmatrix.sync.aligned.m8n8.x4.shared.b16 {%0,%1,%2,%3}, [%4];"
        : "=r"(r[0]), "=r"(r[1]), "=r"(r[2]), "=r"(r[3])
        : "r"(addr));
}
__device__ __forceinline__ void ldsm4t(uint32_t* r, uint32_t addr) {
    asm volatile(
        "ldmatrix.sync.aligned.m8n8.x4.trans.shared.b16 {%0,%1,%2,%3}, [%4];"
        : "=r"(r[0]), "=r"(r[1]), "=r"(r[2]), "=r"(r[3])
        : "r"(addr));
}
__device__ __forceinline__ void mma16816(float* d, const uint32_t* a,
                                         const uint32_t* b) {
    asm volatile(
        "mma.sync.aligned.m16n8k16.row.col.f32.bf16.bf16.f32 "
        "{%0,%1,%2,%3}, {%4,%5,%6,%7}, {%8,%9}, {%0,%1,%2,%3};"
        : "+f"(d[0]), "+f"(d[1]), "+f"(d[2]), "+f"(d[3])
        : "r"(a[0]), "r"(a[1]), "r"(a[2]), "r"(a[3]), "r"(b[0]), "r"(b[1]));
}
__device__ __forceinline__ void split4(float4 v, uint2& hi, uint2& lo) {
    __nv_bfloat162 h0 = __floats2bfloat162_rn(v.x, v.y);
    __nv_bfloat162 h1 = __floats2bfloat162_rn(v.z, v.w);
    float2 f0 = __bfloat1622float2(h0);
    float2 f1 = __bfloat1622float2(h1);
    __nv_bfloat162 l0 = __floats2bfloat162_rn(v.x - f0.x, v.y - f0.y);
    __nv_bfloat162 l1 = __floats2bfloat162_rn(v.z - f1.x, v.w - f1.y);
    hi = make_uint2(*(uint32_t*)&h0, *(uint32_t*)&h1);
    lo = make_uint2(*(uint32_t*)&l0, *(uint32_t*)&l1);
}

// ---------------- zero kernels ----------------
__global__ void zero_f_kernel(float* p, int n) {
    int i = blockIdx.x * blockDim.x + threadIdx.x;
    int st = gridDim.x * blockDim.x;
    for (; i < n; i += st) p[i] = 0.f;
}
__global__ void zero_i_kernel(int* p, int n) {
    int i = blockIdx.x * blockDim.x + threadIdx.x;
    int st = gridDim.x * blockDim.x;
    for (; i < n; i += st) p[i] = 0;
}

// ---------------- CSR build ----------------
__global__ void hist_kernel(const int* __restrict__ eir,
                            int* __restrict__ cnt) {
    int r = blockIdx.y;
    int i = blockIdx.x * blockDim.x + threadIdx.x;
    if (i < NE) atomicAdd(&cnt[r * CBASE + eir[(size_t)r * 2 * NE + NE + i]], 1);
}
__global__ void scanA_kernel(const int* __restrict__ cnt, int* __restrict__ out,
                             int* __restrict__ sums) {
    __shared__ int sh[256];
    int i = blockIdx.x * 256 + threadIdx.x;
    int v = cnt[i];
    sh[threadIdx.x] = v;
    __syncthreads();
    for (int o = 1; o < 256; o <<= 1) {
        int t = (threadIdx.x >= o) ? sh[threadIdx.x - o] : 0;
        __syncthreads();
        sh[threadIdx.x] += t;
        __syncthreads();
    }
    out[i] = sh[threadIdx.x] - v;
    if (threadIdx.x == 255) sums[blockIdx.x] = sh[255];
}
__global__ void scanB_kernel(int* __restrict__ sums) {
    __shared__ int sh[1024];
    int v = (threadIdx.x < NBLK) ? sums[threadIdx.x] : 0;
    sh[threadIdx.x] = v;
    __syncthreads();
    for (int o = 1; o < 1024; o <<= 1) {
        int t = (threadIdx.x >= o) ? sh[threadIdx.x - o] : 0;
        __syncthreads();
        sh[threadIdx.x] += t;
        __syncthreads();
    }
    if (threadIdx.x < NBLK) sums[threadIdx.x] = sh[threadIdx.x] - v;
}
__global__ void scanC_kernel(int* __restrict__ out, const int* __restrict__ sums,
                             int* __restrict__ fill) {
    int i = blockIdx.x * 256 + threadIdx.x;
    int v = out[i] + sums[blockIdx.x];
    out[i] = v;
    fill[i] = v;
}
__global__ void csr_scatter_kernel(const int* __restrict__ eir,
                                   int* __restrict__ fill,
                                   int* __restrict__ ssorted) {
    int r = blockIdx.y;
    int i = blockIdx.x * blockDim.x + threadIdx.x;
    if (i >= NE) return;
    int d = eir[(size_t)r * 2 * NE + NE + i];
    int s = eir[(size_t)r * 2 * NE + i];
    int pos = atomicAdd(&fill[r * CBASE + d], 1);
    ssorted[pos] = s;
}

// ---------------- tensor-core bf16x3 GEMM core ------------------------------
template <bool SCATTER>
__device__ __forceinline__ void tc_gemm_core(const float* __restrict__ A,
                                             const float* __restrict__ B,
                                             const float* __restrict__ bias,
                                             float* __restrict__ C,
                                             const int* __restrict__ sidx,
                                             int M) {
    extern __shared__ __nv_bfloat16 sm[];
    __nv_bfloat16* sAh = sm;
    __nv_bfloat16* sAl = sm + 8192;
    __nv_bfloat16* sBh = sm + 16384;
    __nv_bfloat16* sBl = sm + 24576;
    const int tid = threadIdx.x;
    const int lane = tid & 31, warp = tid >> 5;
    const int wm = warp & 3, wn = warp >> 2;
    const int rowBase = blockIdx.x * 128;
    if (rowBase >= M) return;

    float acc[2][8][4];
#pragma unroll
    for (int a = 0; a < 2; ++a)
#pragma unroll
        for (int b = 0; b < 8; ++b)
#pragma unroll
            for (int c = 0; c < 4; ++c) acc[a][b][c] = 0.f;

    uint32_t sAh_b = (uint32_t)__cvta_generic_to_shared(sAh);
    uint32_t sAl_b = (uint32_t)__cvta_generic_to_shared(sAl);
    uint32_t sBh_b = (uint32_t)__cvta_generic_to_shared(sBh);
    uint32_t sBl_b = (uint32_t)__cvta_generic_to_shared(sBl);

    for (int kc = 0; kc < 128; kc += 64) {
        __syncthreads();
#pragma unroll
        for (int i = 0; i < 8; ++i) {
            int j = tid + 256 * i;
            int row = j >> 4, c4 = j & 15;
            float4 v = make_float4(0.f, 0.f, 0.f, 0.f);
            if (rowBase + row < M)
                v = *(const float4*)&A[(size_t)(rowBase + row) * 128 + kc +
                                       c4 * 4];
            uint2 h, l;
            split4(v, h, l);
            int off = row * 64 + (((c4 >> 1) ^ (row & 7)) << 3) + (c4 & 1) * 4;
            *(uint2*)&sAh[off] = h;
            *(uint2*)&sAl[off] = l;
        }
#pragma unroll
        for (int i = 0; i < 8; ++i) {
            int j = tid + 256 * i;
            int row = j >> 5, c4 = j & 31;
            float4 v = *(const float4*)&B[(size_t)(kc + row) * 128 + c4 * 4];
            uint2 h, l;
            split4(v, h, l);
            int off = row * 128 + (((c4 >> 1) ^ (row & 7)) << 3) + (c4 & 1) * 4;
            *(uint2*)&sBh[off] = h;
            *(uint2*)&sBl[off] = l;
        }
        __syncthreads();
#pragma unroll
        for (int s = 0; s < 4; ++s) {
            uint32_t ah[2][4], al[2][4];
#pragma unroll
            for (int mf = 0; mf < 2; ++mf) {
                int mr = wm * 32 + mf * 16 + (lane & 15);
                int ck = 2 * s + (lane >> 4);
                uint32_t off = (uint32_t)(mr * 64 + ((ck ^ (mr & 7)) << 3)) * 2;
                ldsm4(ah[mf], sAh_b + off);
                ldsm4(al[mf], sAl_b + off);
            }
#pragma unroll
            for (int nf2 = 0; nf2 < 4; ++nf2) {
                int kr = s * 16 + (lane & 7) + ((lane >> 3) & 1) * 8;
                int cn = wn * 8 + nf2 * 2 + (lane >> 4);
                uint32_t off =
                    (uint32_t)(kr * 128 + ((cn ^ (kr & 7)) << 3)) * 2;
                uint32_t bh[4], bl[4];
                ldsm4t(bh, sBh_b + off);
                ldsm4t(bl, sBl_b + off);
#pragma unroll
                for (int mf = 0; mf < 2; ++mf) {
                    mma16816(acc[mf][nf2 * 2], ah[mf], bh);
                    mma16816(acc[mf][nf2 * 2], ah[mf], bl);
                    mma16816(acc[mf][nf2 * 2], al[mf], bh);
                    mma16816(acc[mf][nf2 * 2 + 1], ah[mf], bh + 2);
                    mma16816(acc[mf][nf2 * 2 + 1], ah[mf], bl + 2);
                    mma16816(acc[mf][nf2 * 2 + 1], al[mf], bh + 2);
                }
            }
        }
    }
    int c0 = wn * 64 + (lane & 3) * 2;
#pragma unroll
    for (int mf = 0; mf < 2; ++mf) {
        int r0 = rowBase + wm * 32 + mf * 16 + (lane >> 2);
#pragma unroll
        for (int nf = 0; nf < 8; ++nf) {
            int col = c0 + nf * 8;
            if (SCATTER) {
                if (r0 < M)
                    red2(&C[(size_t)sidx[r0] * 128 + col], acc[mf][nf][0],
                         acc[mf][nf][1]);
                if (r0 + 8 < M)
                    red2(&C[(size_t)sidx[r0 + 8] * 128 + col], acc[mf][nf][2],
                         acc[mf][nf][3]);
            } else {
                float2 bv = *(const float2*)&bias[col];
                if (r0 < M) {
                    C[(size_t)r0 * 128 + col] = acc[mf][nf][0] + bv.x;
                    C[(size_t)r0 * 128 + col + 1] = acc[mf][nf][1] + bv.y;
                }
                if (r0 + 8 < M) {
                    C[(size_t)(r0 + 8) * 128 + col] = acc[mf][nf][2] + bv.x;
                    C[(size_t)(r0 + 8) * 128 + col + 1] = acc[mf][nf][3] + bv.y;
                }
            }
        }
    }
}

struct Pair {
    const float* A[2];
    const float* W[2];
    const float* bias[2];
    float* C[2];
    int M[2];
};

__global__ __launch_bounds__(256, 2) void tc_gemm_scatter_kernel(
    const float* __restrict__ A, const float* __restrict__ B,
    float* __restrict__ C, const int* __restrict__ sidx, int M) {
    tc_gemm_core<true>(A, B, nullptr, C, sidx, M);
}
__global__ __launch_bounds__(256, 2) void tc_gemm_pair_kernel(Pair pr) {
    int z = blockIdx.y;
    tc_gemm_core<false>(pr.A[z], pr.W[z], pr.bias[z], pr.C[z], nullptr,
                        pr.M[z]);
}

// ---------------- atom -> chemical count ----------------
__global__ void count_kernel(const int* __restrict__ hd, float* __restrict__ cnt,
                             int n) {
    int i = blockIdx.x * blockDim.x + threadIdx.x;
    if (i < n) atomicAdd(&cnt[hd[i]], 1.f);
}
__global__ void combine_kernel(const float* __restrict__ sum,
                               const float* __restrict__ cnt,
                               const float* __restrict__ xc,
                               float* __restrict__ out, int n) {
    int i = blockIdx.x * blockDim.x + threadIdx.x;
    if (i < n) out[i] = sum[i] / fmaxf(cnt[i >> 7], 1.f) + xc[i];
}

// ---------------- CSR edge aggregation (one warp per dst node) ---------------
// STORE: first relation for this dst type -> writes agg (incl. zeros).
// !STORE: accumulates into agg. Unroll-2 over edges for ILP; __expf.
template <bool STORE>
__global__ __launch_bounds__(256) void edge_csr_kernel(
    const int* __restrict__ ssorted, const int* __restrict__ offs,
    const float* __restrict__ xl, const float* __restrict__ xr,
    const float* __restrict__ a, float* __restrict__ agg, int Nd, int robase) {
    int d = (blockIdx.x * blockDim.x + threadIdx.x) >> 5;
    int lane = threadIdx.x & 31;
    if (d >= Nd) return;
    int beg = offs[robase + d], end = offs[robase + d + 1];
    float* o = &agg[(size_t)d * 128 + lane * 4];
    if (beg == end) {
        if (STORE) *(float4*)o = make_float4(0.f, 0.f, 0.f, 0.f);
        return;
    }
    float4 r4 = *(const float4*)&xr[(size_t)d * 128 + lane * 4];
    float4 av = *(const float4*)&a[lane * 4];
    float4 acc = make_float4(0.f, 0.f, 0.f, 0.f);
    float sden = 0.f;
    int j = beg;
    for (; j + 1 < end; j += 2) {
        int s0 = ssorted[j], s1 = ssorted[j + 1];
        float4 A = *(const float4*)&xl[(size_t)s0 * 128 + lane * 4];
        float4 B = *(const float4*)&xl[(size_t)s1 * 128 + lane * 4];
        float a0 = A.x + r4.x; a0 = a0 > 0.f ? a0 : 0.2f * a0;
        float a1 = A.y + r4.y; a1 = a1 > 0.f ? a1 : 0.2f * a1;
        float a2 = A.z + r4.z; a2 = a2 > 0.f ? a2 : 0.2f * a2;
        float a3 = A.w + r4.w; a3 = a3 > 0.f ? a3 : 0.2f * a3;
        float b0 = B.x + r4.x; b0 = b0 > 0.f ? b0 : 0.2f * b0;
        float b1 = B.y + r4.y; b1 = b1 > 0.f ? b1 : 0.2f * b1;
        float b2 = B.z + r4.z; b2 = b2 > 0.f ? b2 : 0.2f * b2;
        float b3 = B.w + r4.w; b3 = b3 > 0.f ? b3 : 0.2f * b3;
        float pA = a0 * av.x + a1 * av.y + a2 * av.z + a3 * av.w;
        float pB = b0 * av.x + b1 * av.y + b2 * av.z + b3 * av.w;
        pA = wsum(pA);
        pB = wsum(pB);
        float eA = __expf(pA), eB = __expf(pB);
        acc.x += eA * A.x + eB * B.x;
        acc.y += eA * A.y + eB * B.y;
        acc.z += eA * A.z + eB * B.z;
        acc.w += eA * A.w + eB * B.w;
        sden += eA + eB;
    }
    if (j < end) {
        int s0 = ssorted[j];
        float4 A = *(const float4*)&xl[(size_t)s0 * 128 + lane * 4];
        float a0 = A.x + r4.x; a0 = a0 > 0.f ? a0 : 0.2f * a0;
        float a1 = A.y + r4.y; a1 = a1 > 0.f ? a1 : 0.2f * a1;
        float a2 = A.z + r4.z; a2 = a2 > 0.f ? a2 : 0.2f * a2;
        float a3 = A.w + r4.w; a3 = a3 > 0.f ? a3 : 0.2f * a3;
        float pA = a0 * av.x + a1 * av.y + a2 * av.z + a3 * av.w;
        pA = wsum(pA);
        float eA = __expf(pA);
        acc.x += eA * A.x; acc.y += eA * A.y;
        acc.z += eA * A.z; acc.w += eA * A.w;
        sden += eA;
    }
    float inv = 1.f / fmaxf(sden, 1e-16f);
    if (STORE) {
        *(float4*)o = make_float4(acc.x * inv, acc.y * inv, acc.z * inv,
                                  acc.w * inv);
    } else {
        float4 g = *(float4*)o;
        g.x += acc.x * inv; g.y += acc.y * inv;
        g.z += acc.z * inv; g.w += acc.w * inv;
        *(float4*)o = g;
    }
}

// combined GATv2 output bias per (layer, dst type)
__global__ void cbias2_kernel(const float* __restrict__ cb,
                              float* __restrict__ out) {
    int l = blockIdx.x;
    int c = threadIdx.x;
    float s[3] = {0.f, 0.f, 0.f};
#pragma unroll
    for (int r = 0; r < RR; ++r) s[c_RD[r]] += cb[(l * RR + r) * HD + c];
    out[(l * 3 + 0) * HD + c] = s[0];
    out[(l * 3 + 1) * HD + c] = s[1];
    out[(l * 3 + 2) * HD + c] = s[2];
}

// ---------------- merged layernorm + relu over all 3 types -------------------
__global__ void ln_relu_all_kernel(const float* __restrict__ a0,
                                   const float* __restrict__ a1,
                                   const float* __restrict__ a2,
                                   float* __restrict__ x0,
                                   float* __restrict__ x1,
                                   float* __restrict__ x2,
                                   const float* __restrict__ cb3,
                                   const float* __restrict__ g3,
                                   const float* __restrict__ b3) {
    int row = (blockIdx.x * blockDim.x + threadIdx.x) >> 5;
    int lane = threadIdx.x & 31;
    if (row >= NROWS) return;
    int t, lr;
    const float* in;
    float* out;
    if (row < N0) { t = 0; lr = row; in = a0; out = x0; }
    else if (row < N0 + N1) { t = 1; lr = row - N0; in = a1; out = x1; }
    else { t = 2; lr = row - N0 - N1; in = a2; out = x2; }
    float4 v = *(const float4*)&in[(size_t)lr * 128 + lane * 4];
    float4 cv = *(const float4*)&cb3[t * HD + lane * 4];
    v.x += cv.x; v.y += cv.y; v.z += cv.z; v.w += cv.w;
    float s = v.x + v.y + v.z + v.w;
    s = wsum(s);
    float mu = s * (1.f / 128.f);
    float d0 = v.x - mu, d1 = v.y - mu, d2 = v.z - mu, d3 = v.w - mu;
    float ss = d0 * d0 + d1 * d1 + d2 * d2 + d3 * d3;
    ss = wsum(ss);
    float inv = rsqrtf(ss * (1.f / 128.f) + 1e-5f);
    float4 gv = *(const float4*)&g3[t * HD + lane * 4];
    float4 bv = *(const float4*)&b3[t * HD + lane * 4];
    float4 o;
    o.x = fmaxf(d0 * inv * gv.x + bv.x, 0.f);
    o.y = fmaxf(d1 * inv * gv.y + bv.y, 0.f);
    o.z = fmaxf(d2 * inv * gv.z + bv.z, 0.f);
    o.w = fmaxf(d3 * inv * gv.w + bv.w, 0.f);
    *(float4*)&out[(size_t)lr * 128 + lane * 4] = o;
}

// ---------------- prediction head ----------------
__global__ void pred_kernel(const float* __restrict__ x,
                            const float* __restrict__ Wp,
                            const float* __restrict__ bp,
                            float* __restrict__ out, int N) {
    int row = (blockIdx.x * blockDim.x + threadIdx.x) >> 5;
    int lane = threadIdx.x & 31;
    if (row >= N) return;
    float4 xv = *(const float4*)&x[(size_t)row * 128 + lane * 4];
    float4 w01 = *(const float4*)&Wp[lane * 8];
    float4 w23 = *(const float4*)&Wp[lane * 8 + 4];
    float a0 = xv.x * w01.x + xv.y * w01.z + xv.z * w23.x + xv.w * w23.z;
    float a1 = xv.x * w01.y + xv.y * w01.w + xv.z * w23.y + xv.w * w23.w;
    a0 = wsum(a0);
    a1 = wsum(a1);
    if (lane == 0) {
        out[row * 2 + 0] = a0 + bp[0];
        out[row * 2 + 1] = a1 + bp[1];
    }
}

// ---------------- host orchestration ----------------
extern "C" void kernel_launch(void* const* d_in, const int* in_sizes, int n_in,
                              void* d_out, int out_size) {
    const float* x_atom = (const float*)d_in[0];
    const float* x_chem = (const float*)d_in[1];
    const float* x_gene = (const float*)d_in[2];
    const float* x_assay = (const float*)d_in[3];
    const float* W_mol = (const float*)d_in[4];
    const float* Wl = (const float*)d_in[5];
    const float* Wr = (const float*)d_in[6];
    const float* bl = (const float*)d_in[7];
    const float* br = (const float*)d_in[8];
    const float* att = (const float*)d_in[9];
    const float* cb = (const float*)d_in[10];
    const float* lng = (const float*)d_in[11];
    const float* lnb = (const float*)d_in[12];
    const float* Wp = (const float*)d_in[13];
    const float* bp = (const float*)d_in[14];
    const int* hyper = (const int*)d_in[15];
    const int* eir = (const int*)d_in[16];
    float* out = (float*)d_out;
    (void)in_sizes; (void)n_in; (void)out_size;

    float *px0, *px1, *px2, *pa0, *pa1, *pa2, *pxl, *pxr, *pcnt, *pcb;
    int *pcounts, *poffs, *pfill, *psums, *pss;
    cudaGetSymbolAddress((void**)&px0, g_x0);
    cudaGetSymbolAddress((void**)&px1, g_x1);
    cudaGetSymbolAddress((void**)&px2, g_x2);
    cudaGetSymbolAddress((void**)&pa0, g_a0);
    cudaGetSymbolAddress((void**)&pa1, g_a1);
    cudaGetSymbolAddress((void**)&pa2, g_a2);
    cudaGetSymbolAddress((void**)&pxl, g_xl);
    cudaGetSymbolAddress((void**)&pxr, g_xr);
    cudaGetSymbolAddress((void**)&pcnt, g_cnt);
    cudaGetSymbolAddress((void**)&pcb, g_cbias);
    cudaGetSymbolAddress((void**)&pcounts, g_counts);
    cudaGetSymbolAddress((void**)&poffs, g_offs);
    cudaGetSymbolAddress((void**)&pfill, g_fill);
    cudaGetSymbolAddress((void**)&psums, g_sums);
    cudaGetSymbolAddress((void**)&pss, g_ssorted);

    static cudaStream_t s1 = nullptr;
    static cudaEvent_t evStart, evFork, evCSR, evG[LL * RR], evE[LL * RR],
        evL[LL];
    if (!s1) {
        cudaStreamCreateWithFlags(&s1, cudaStreamNonBlocking);
        cudaEventCreateWithFlags(&evStart, cudaEventDisableTiming);
        cudaEventCreateWithFlags(&evFork, cudaEventDisableTiming);
        cudaEventCreateWithFlags(&evCSR, cudaEventDisableTiming);
        for (int i = 0; i < LL * RR; ++i) {
            cudaEventCreateWithFlags(&evG[i], cudaEventDisableTiming);
            cudaEventCreateWithFlags(&evE[i], cudaEventDisableTiming);
        }
        for (int i = 0; i < LL; ++i)
            cudaEventCreateWithFlags(&evL[i], cudaEventDisableTiming);
    }

    const int T = 256;
    const int ZB = 1024;
    const int SMEMB = 65536;

    cudaFuncSetAttribute(tc_gemm_scatter_kernel,
                         cudaFuncAttributeMaxDynamicSharedMemorySize, SMEMB);
    cudaFuncSetAttribute(tc_gemm_pair_kernel,
                         cudaFuncAttributeMaxDynamicSharedMemorySize, SMEMB);

    static const int RS[RR] = {0, 0, 0, 0, 0, 2, 1, 2, 2, 1, 1, 1, 1};
    static const int RD[RR] = {2, 2, 1, 1, 1, 1, 1, 0, 0, 0, 0, 0, 2};
    // first relation per dst type (store mode): r0 -> t2, r2 -> t1, r7 -> t0
    static const bool FIRST[RR] = {true,  false, true,  false, false,
                                   false, false, true,  false, false,
                                   false, false, false};
    const int NT[3] = {N0, N1, N2};

    // fork s1 at the very start: CSR build + cbias precompute run concurrently
    // with the atom-encoder prelude on stream 0.
    cudaEventRecord(evStart, 0);
    cudaStreamWaitEvent(s1, evStart, 0);
    zero_i_kernel<<<256, T, 0, s1>>>(pcounts, NCNT);
    {
        dim3 hg((NE + T - 1) / T, RR);
        hist_kernel<<<hg, T, 0, s1>>>(eir, pcounts);
        scanA_kernel<<<NBLK, 256, 0, s1>>>(pcounts, poffs, psums);
        scanB_kernel<<<1, 1024, 0, s1>>>(psums);
        scanC_kernel<<<NBLK, 256, 0, s1>>>(poffs, psums, pfill);
        csr_scatter_kernel<<<hg, T, 0, s1>>>(eir, pfill, pss);
        cbias2_kernel<<<LL, HD, 0, s1>>>(cb, pcb);
    }
    cudaEventRecord(evCSR, s1);

    // ---- atom encoder + bottom-up mean aggregation into chemical (stream 0) --
    zero_f_kernel<<<ZB, T>>>(pa0, N0 * HD);
    zero_f_kernel<<<(N0 + T - 1) / T, T>>>(pcnt, N0);
    count_kernel<<<(NA + T - 1) / T, T>>>(hyper, pcnt, NA);
    tc_gemm_scatter_kernel<<<(NA + 127) / 128, T, SMEMB>>>(x_atom, W_mol, pa0,
                                                           hyper, NA);
    combine_kernel<<<(N0 * HD + T - 1) / T, T>>>(pa0, pcnt, x_chem, px0,
                                                 N0 * HD);
    cudaEventRecord(evFork, 0);
    cudaStreamWaitEvent(s1, evFork, 0);  // s1's GEMMs read px0
    cudaStreamWaitEvent(0, evCSR, 0);    // edge kernels need CSR + cbias

    const float* xsrc[3] = {px0, x_gene, x_assay};
    float* agg[3] = {pa0, pa1, pa2};

    for (int l = 0; l < LL; ++l) {
        size_t lo = (size_t)l * RR;

        for (int r = 0; r < RR; ++r) {
            int s = RS[r], d = RD[r];
            int Ns = NT[s], Nd = NT[d];
            size_t wo = lo + r;
            int idx = l * RR + r;
            int buf = idx & 1;
            float* bxl = pxl + (size_t)buf * SLAB;
            float* bxr = pxr + (size_t)buf * SLAB;

            if (idx >= 2) cudaStreamWaitEvent(s1, evE[idx - 2], 0);  // WAR
            Pair pr;
            pr.A[0] = xsrc[s];  pr.M[0] = Ns;
            pr.A[1] = xsrc[d];  pr.M[1] = Nd;
            pr.W[0] = Wl + wo * HD * HD;
            pr.W[1] = Wr + wo * HD * HD;
            pr.bias[0] = bl + wo * HD;
            pr.bias[1] = br + wo * HD;
            pr.C[0] = bxl;
            pr.C[1] = bxr;
            int mx = Ns > Nd ? Ns : Nd;
            dim3 ggrid((mx + 127) / 128, 2);
            tc_gemm_pair_kernel<<<ggrid, T, SMEMB, s1>>>(pr);
            cudaEventRecord(evG[idx], s1);

            cudaStreamWaitEvent(0, evG[idx], 0);
            int eg = (Nd * 32 + T - 1) / T;
            if (FIRST[r])
                edge_csr_kernel<true><<<eg, T>>>(pss, poffs, bxl, bxr,
                                                 att + wo * HD, agg[d], Nd,
                                                 r * CBASE);
            else
                edge_csr_kernel<false><<<eg, T>>>(pss, poffs, bxl, bxr,
                                                  att + wo * HD, agg[d], Nd,
                                                  r * CBASE);
            cudaEventRecord(evE[idx], 0);
        }
        ln_relu_all_kernel<<<(NROWS * 32 + T - 1) / T, T>>>(
            pa0, pa1, pa2, px0, px1, px2, pcb + l * 3 * HD,
            lng + (size_t)l * 3 * HD, lnb + (size_t)l * 3 * HD);
        xsrc[0] = px0; xsrc[1] = px1; xsrc[2] = px2;
        cudaEventRecord(evL[l], 0);
        cudaStreamWaitEvent(s1, evL[l], 0);
    }

    pred_kernel<<<(N0 * 32 + T - 1) / T, T>>>(px0, Wp, bp, out, N0);
}

// round 10
// speedup vs baseline: 4.8511x; 1.2047x over previous
#include <cuda_runtime.h>
#include <cuda_bf16.h>
#include <cuda_fp16.h>
#include <math.h>
#include <stdint.h>

#define N0 20000
#define N1 20000
#define N2 10000
#define NA 600000
#define NE 400000
#define HD 128
#define RR 13
#define LL 2
#define SLAB (N0 * HD)
#define CBASE 20000           // per-relation counter stride
#define NCNT 260096           // 1016 * 256 (flat counter array, zero-padded)
#define NBLK 1016
#define NROWS (N0 + N1 + N2)  // 50000
#define NBUF 4                // xl/xr pipeline depth

// ---------------- scratch (static device globals; no allocation) ---------------
__device__ float g_x0[N0 * HD];
__device__ float g_x1[N1 * HD];
__device__ float g_x2[N2 * HD];
__device__ float g_a0[N0 * HD];
__device__ float g_a1[N1 * HD];
__device__ float g_a2[N2 * HD];
__device__ __half g_xlh[NBUF * SLAB];  // fp16 Wl outputs (gathered randomly)
__device__ float g_xr[NBUF * SLAB];    // fp32 Wr outputs (read linearly)
__device__ float g_cnt[N0];
__device__ float g_cbias[LL * 3 * HD];
// CSR scratch
__device__ int g_counts[NCNT];
__device__ int g_offs[NCNT];
__device__ int g_fill[NCNT];
__device__ int g_sums[NBLK];
__device__ int g_ssorted[RR * NE];  // 20.8 MB: src ids grouped by dst

__constant__ int c_RD[RR] = {2, 2, 1, 1, 1, 1, 1, 0, 0, 0, 0, 0, 2};

// ---------------- helpers ----------------
__device__ __forceinline__ float wsum(float v) {
#pragma unroll
    for (int o = 16; o; o >>= 1) v += __shfl_xor_sync(0xffffffffu, v, o);
    return v;
}
__device__ __forceinline__ void red2(float* p, float a, float b) {
    asm volatile("red.global.add.v2.f32 [%0], {%1,%2};" ::"l"(p), "f"(a),
                 "f"(b)
                 : "memory");
}
__device__ __forceinline__ void ldsm4(uint32_t* r, uint32_t addr) {
    asm volatile(
        "ldmatrix.sync.aligned.m8n8.x4.shared.b16 {%0,%1,%2,%3}, [%4];"
        : "=r"(r[0]), "=r"(r[1]), "=r"(r[2]), "=r"(r[3])
        : "r"(addr));
}
__device__ __forceinline__ void ldsm4t(uint32_t* r, uint32_t addr) {
    asm volatile(
        "ldmatrix.sync.aligned.m8n8.x4.trans.shared.b16 {%0,%1,%2,%3}, [%4];"
        : "=r"(r[0]), "=r"(r[1]), "=r"(r[2]), "=r"(r[3])
        : "r"(addr));
}
__device__ __forceinline__ void mma16816(float* d, const uint32_t* a,
                                         const uint32_t* b) {
    asm volatile(
        "mma.sync.aligned.m16n8k16.row.col.f32.bf16.bf16.f32 "
        "{%0,%1,%2,%3}, {%4,%5,%6,%7}, {%8,%9}, {%0,%1,%2,%3};"
        : "+f"(d[0]), "+f"(d[1]), "+f"(d[2]), "+f"(d[3])
        : "r"(a[0]), "r"(a[1]), "r"(a[2]), "r"(a[3]), "r"(b[0]), "r"(b[1]));
}
__device__ __forceinline__ void split4(float4 v, uint2& hi, uint2& lo) {
    __nv_bfloat162 h0 = __floats2bfloat162_rn(v.x, v.y);
    __nv_bfloat162 h1 = __floats2bfloat162_rn(v.z, v.w);
    float2 f0 = __bfloat1622float2(h0);
    float2 f1 = __bfloat1622float2(h1);
    __nv_bfloat162 l0 = __floats2bfloat162_rn(v.x - f0.x, v.y - f0.y);
    __nv_bfloat162 l1 = __floats2bfloat162_rn(v.z - f1.x, v.w - f1.y);
    hi = make_uint2(*(uint32_t*)&h0, *(uint32_t*)&h1);
    lo = make_uint2(*(uint32_t*)&l0, *(uint32_t*)&l1);
}

// ---------------- zero kernels ----------------
__global__ void zero_f_kernel(float* p, int n) {
    int i = blockIdx.x * blockDim.x + threadIdx.x;
    int st = gridDim.x * blockDim.x;
    for (; i < n; i += st) p[i] = 0.f;
}
__global__ void zero_i_kernel(int* p, int n) {
    int i = blockIdx.x * blockDim.x + threadIdx.x;
    int st = gridDim.x * blockDim.x;
    for (; i < n; i += st) p[i] = 0;
}

// ---------------- CSR build ----------------
__global__ void hist_kernel(const int* __restrict__ eir,
                            int* __restrict__ cnt) {
    int r = blockIdx.y;
    int i = blockIdx.x * blockDim.x + threadIdx.x;
    if (i < NE) atomicAdd(&cnt[r * CBASE + eir[(size_t)r * 2 * NE + NE + i]], 1);
}
__global__ void scanA_kernel(const int* __restrict__ cnt, int* __restrict__ out,
                             int* __restrict__ sums) {
    __shared__ int sh[256];
    int i = blockIdx.x * 256 + threadIdx.x;
    int v = cnt[i];
    sh[threadIdx.x] = v;
    __syncthreads();
    for (int o = 1; o < 256; o <<= 1) {
        int t = (threadIdx.x >= o) ? sh[threadIdx.x - o] : 0;
        __syncthreads();
        sh[threadIdx.x] += t;
        __syncthreads();
    }
    out[i] = sh[threadIdx.x] - v;
    if (threadIdx.x == 255) sums[blockIdx.x] = sh[255];
}
__global__ void scanB_kernel(int* __restrict__ sums) {
    __shared__ int sh[1024];
    int v = (threadIdx.x < NBLK) ? sums[threadIdx.x] : 0;
    sh[threadIdx.x] = v;
    __syncthreads();
    for (int o = 1; o < 1024; o <<= 1) {
        int t = (threadIdx.x >= o) ? sh[threadIdx.x - o] : 0;
        __syncthreads();
        sh[threadIdx.x] += t;
        __syncthreads();
    }
    if (threadIdx.x < NBLK) sums[threadIdx.x] = sh[threadIdx.x] - v;
}
__global__ void scanC_kernel(int* __restrict__ out, const int* __restrict__ sums,
                             int* __restrict__ fill) {
    int i = blockIdx.x * 256 + threadIdx.x;
    int v = out[i] + sums[blockIdx.x];
    out[i] = v;
    fill[i] = v;
}
__global__ void csr_scatter_kernel(const int* __restrict__ eir,
                                   int* __restrict__ fill,
                                   int* __restrict__ ssorted) {
    int r = blockIdx.y;
    int i = blockIdx.x * blockDim.x + threadIdx.x;
    if (i >= NE) return;
    int d = eir[(size_t)r * 2 * NE + NE + i];
    int s = eir[(size_t)r * 2 * NE + i];
    int pos = atomicAdd(&fill[r * CBASE + d], 1);
    ssorted[pos] = s;
}

// ---------------- tensor-core bf16x3 GEMM core ------------------------------
// HALFOUT: write fp16 output (for the randomly gathered Wl results).
template <bool SCATTER, bool HALFOUT>
__device__ __forceinline__ void tc_gemm_core(const float* __restrict__ A,
                                             const float* __restrict__ B,
                                             const float* __restrict__ bias,
                                             void* __restrict__ Cv,
                                             const int* __restrict__ sidx,
                                             int M) {
    extern __shared__ __nv_bfloat16 sm[];
    __nv_bfloat16* sAh = sm;
    __nv_bfloat16* sAl = sm + 8192;
    __nv_bfloat16* sBh = sm + 16384;
    __nv_bfloat16* sBl = sm + 24576;
    const int tid = threadIdx.x;
    const int lane = tid & 31, warp = tid >> 5;
    const int wm = warp & 3, wn = warp >> 2;
    const int rowBase = blockIdx.x * 128;
    if (rowBase >= M) return;

    float acc[2][8][4];
#pragma unroll
    for (int a = 0; a < 2; ++a)
#pragma unroll
        for (int b = 0; b < 8; ++b)
#pragma unroll
            for (int c = 0; c < 4; ++c) acc[a][b][c] = 0.f;

    uint32_t sAh_b = (uint32_t)__cvta_generic_to_shared(sAh);
    uint32_t sAl_b = (uint32_t)__cvta_generic_to_shared(sAl);
    uint32_t sBh_b = (uint32_t)__cvta_generic_to_shared(sBh);
    uint32_t sBl_b = (uint32_t)__cvta_generic_to_shared(sBl);

    for (int kc = 0; kc < 128; kc += 64) {
        __syncthreads();
#pragma unroll
        for (int i = 0; i < 8; ++i) {
            int j = tid + 256 * i;
            int row = j >> 4, c4 = j & 15;
            float4 v = make_float4(0.f, 0.f, 0.f, 0.f);
            if (rowBase + row < M)
                v = *(const float4*)&A[(size_t)(rowBase + row) * 128 + kc +
                                       c4 * 4];
            uint2 h, l;
            split4(v, h, l);
            int off = row * 64 + (((c4 >> 1) ^ (row & 7)) << 3) + (c4 & 1) * 4;
            *(uint2*)&sAh[off] = h;
            *(uint2*)&sAl[off] = l;
        }
#pragma unroll
        for (int i = 0; i < 8; ++i) {
            int j = tid + 256 * i;
            int row = j >> 5, c4 = j & 31;
            float4 v = *(const float4*)&B[(size_t)(kc + row) * 128 + c4 * 4];
            uint2 h, l;
            split4(v, h, l);
            int off = row * 128 + (((c4 >> 1) ^ (row & 7)) << 3) + (c4 & 1) * 4;
            *(uint2*)&sBh[off] = h;
            *(uint2*)&sBl[off] = l;
        }
        __syncthreads();
#pragma unroll
        for (int s = 0; s < 4; ++s) {
            uint32_t ah[2][4], al[2][4];
#pragma unroll
            for (int mf = 0; mf < 2; ++mf) {
                int mr = wm * 32 + mf * 16 + (lane & 15);
                int ck = 2 * s + (lane >> 4);
                uint32_t off = (uint32_t)(mr * 64 + ((ck ^ (mr & 7)) << 3)) * 2;
                ldsm4(ah[mf], sAh_b + off);
                ldsm4(al[mf], sAl_b + off);
            }
#pragma unroll
            for (int nf2 = 0; nf2 < 4; ++nf2) {
                int kr = s * 16 + (lane & 7) + ((lane >> 3) & 1) * 8;
                int cn = wn * 8 + nf2 * 2 + (lane >> 4);
                uint32_t off =
                    (uint32_t)(kr * 128 + ((cn ^ (kr & 7)) << 3)) * 2;
                uint32_t bh[4], bl[4];
                ldsm4t(bh, sBh_b + off);
                ldsm4t(bl, sBl_b + off);
#pragma unroll
                for (int mf = 0; mf < 2; ++mf) {
                    mma16816(acc[mf][nf2 * 2], ah[mf], bh);
                    mma16816(acc[mf][nf2 * 2], ah[mf], bl);
                    mma16816(acc[mf][nf2 * 2], al[mf], bh);
                    mma16816(acc[mf][nf2 * 2 + 1], ah[mf], bh + 2);
                    mma16816(acc[mf][nf2 * 2 + 1], ah[mf], bl + 2);
                    mma16816(acc[mf][nf2 * 2 + 1], al[mf], bh + 2);
                }
            }
        }
    }
    int c0 = wn * 64 + (lane & 3) * 2;
#pragma unroll
    for (int mf = 0; mf < 2; ++mf) {
        int r0 = rowBase + wm * 32 + mf * 16 + (lane >> 2);
#pragma unroll
        for (int nf = 0; nf < 8; ++nf) {
            int col = c0 + nf * 8;
            if (SCATTER) {
                float* C = (float*)Cv;
                if (r0 < M)
                    red2(&C[(size_t)sidx[r0] * 128 + col], acc[mf][nf][0],
                         acc[mf][nf][1]);
                if (r0 + 8 < M)
                    red2(&C[(size_t)sidx[r0 + 8] * 128 + col], acc[mf][nf][2],
                         acc[mf][nf][3]);
            } else {
                float2 bv = *(const float2*)&bias[col];
                if (HALFOUT) {
                    __half* C = (__half*)Cv;
                    if (r0 < M)
                        *(__half2*)&C[(size_t)r0 * 128 + col] =
                            __floats2half2_rn(acc[mf][nf][0] + bv.x,
                                              acc[mf][nf][1] + bv.y);
                    if (r0 + 8 < M)
                        *(__half2*)&C[(size_t)(r0 + 8) * 128 + col] =
                            __floats2half2_rn(acc[mf][nf][2] + bv.x,
                                              acc[mf][nf][3] + bv.y);
                } else {
                    float* C = (float*)Cv;
                    if (r0 < M) {
                        C[(size_t)r0 * 128 + col] = acc[mf][nf][0] + bv.x;
                        C[(size_t)r0 * 128 + col + 1] = acc[mf][nf][1] + bv.y;
                    }
                    if (r0 + 8 < M) {
                        C[(size_t)(r0 + 8) * 128 + col] =
                            acc[mf][nf][2] + bv.x;
                        C[(size_t)(r0 + 8) * 128 + col + 1] =
                            acc[mf][nf][3] + bv.y;
                    }
                }
            }
        }
    }
}

struct Pair {
    const float* A[2];
    const float* W[2];
    const float* bias[2];
    void* C[2];
    int M[2];
};

__global__ __launch_bounds__(256, 2) void tc_gemm_scatter_kernel(
    const float* __restrict__ A, const float* __restrict__ B,
    float* __restrict__ C, const int* __restrict__ sidx, int M) {
    tc_gemm_core<true, false>(A, B, nullptr, C, sidx, M);
}
// z=0 -> Wl GEMM, fp16 output; z=1 -> Wr GEMM, fp32 output
__global__ __launch_bounds__(256, 2) void tc_gemm_pair_kernel(Pair pr) {
    int z = blockIdx.y;
    if (z == 0)
        tc_gemm_core<false, true>(pr.A[0], pr.W[0], pr.bias[0], pr.C[0],
                                  nullptr, pr.M[0]);
    else
        tc_gemm_core<false, false>(pr.A[1], pr.W[1], pr.bias[1], pr.C[1],
                                   nullptr, pr.M[1]);
}

// ---------------- atom -> chemical count ----------------
__global__ void count_kernel(const int* __restrict__ hd, float* __restrict__ cnt,
                             int n) {
    int i = blockIdx.x * blockDim.x + threadIdx.x;
    if (i < n) atomicAdd(&cnt[hd[i]], 1.f);
}
__global__ void combine_kernel(const float* __restrict__ sum,
                               const float* __restrict__ cnt,
                               const float* __restrict__ xc,
                               float* __restrict__ out, int n) {
    int i = blockIdx.x * blockDim.x + threadIdx.x;
    if (i < n) out[i] = sum[i] / fmaxf(cnt[i >> 7], 1.f) + xc[i];
}

// ---------------- CSR edge aggregation (one warp per dst node) ---------------
// xl in fp16 (halved random-gather traffic); xr/agg fp32. Unroll-2; __expf.
template <bool STORE>
__global__ __launch_bounds__(256) void edge_csr_kernel(
    const int* __restrict__ ssorted, const int* __restrict__ offs,
    const __half* __restrict__ xl, const float* __restrict__ xr,
    const float* __restrict__ a, float* __restrict__ agg, int Nd, int robase) {
    int d = (blockIdx.x * blockDim.x + threadIdx.x) >> 5;
    int lane = threadIdx.x & 31;
    if (d >= Nd) return;
    int beg = offs[robase + d], end = offs[robase + d + 1];
    float* o = &agg[(size_t)d * 128 + lane * 4];
    if (beg == end) {
        if (STORE) *(float4*)o = make_float4(0.f, 0.f, 0.f, 0.f);
        return;
    }
    float4 r4 = *(const float4*)&xr[(size_t)d * 128 + lane * 4];
    float4 av = *(const float4*)&a[lane * 4];
    float4 acc = make_float4(0.f, 0.f, 0.f, 0.f);
    float sden = 0.f;
    int j = beg;
    for (; j + 1 < end; j += 2) {
        int s0 = ssorted[j], s1 = ssorted[j + 1];
        uint2 uA = *(const uint2*)&xl[(size_t)s0 * 128 + lane * 4];
        uint2 uB = *(const uint2*)&xl[(size_t)s1 * 128 + lane * 4];
        float2 A01 = __half22float2(*(__half2*)&uA.x);
        float2 A23 = __half22float2(*(__half2*)&uA.y);
        float2 B01 = __half22float2(*(__half2*)&uB.x);
        float2 B23 = __half22float2(*(__half2*)&uB.y);
        float a0 = A01.x + r4.x; a0 = a0 > 0.f ? a0 : 0.2f * a0;
        float a1 = A01.y + r4.y; a1 = a1 > 0.f ? a1 : 0.2f * a1;
        float a2 = A23.x + r4.z; a2 = a2 > 0.f ? a2 : 0.2f * a2;
        float a3 = A23.y + r4.w; a3 = a3 > 0.f ? a3 : 0.2f * a3;
        float b0 = B01.x + r4.x; b0 = b0 > 0.f ? b0 : 0.2f * b0;
        float b1 = B01.y + r4.y; b1 = b1 > 0.f ? b1 : 0.2f * b1;
        float b2 = B23.x + r4.z; b2 = b2 > 0.f ? b2 : 0.2f * b2;
        float b3 = B23.y + r4.w; b3 = b3 > 0.f ? b3 : 0.2f * b3;
        float pA = a0 * av.x + a1 * av.y + a2 * av.z + a3 * av.w;
        float pB = b0 * av.x + b1 * av.y + b2 * av.z + b3 * av.w;
        pA = wsum(pA);
        pB = wsum(pB);
        float eA = __expf(pA), eB = __expf(pB);
        acc.x += eA * A01.x + eB * B01.x;
        acc.y += eA * A01.y + eB * B01.y;
        acc.z += eA * A23.x + eB * B23.x;
        acc.w += eA * A23.y + eB * B23.y;
        sden += eA + eB;
    }
    if (j < end) {
        int s0 = ssorted[j];
        uint2 uA = *(const uint2*)&xl[(size_t)s0 * 128 + lane * 4];
        float2 A01 = __half22float2(*(__half2*)&uA.x);
        float2 A23 = __half22float2(*(__half2*)&uA.y);
        float a0 = A01.x + r4.x; a0 = a0 > 0.f ? a0 : 0.2f * a0;
        float a1 = A01.y + r4.y; a1 = a1 > 0.f ? a1 : 0.2f * a1;
        float a2 = A23.x + r4.z; a2 = a2 > 0.f ? a2 : 0.2f * a2;
        float a3 = A23.y + r4.w; a3 = a3 > 0.f ? a3 : 0.2f * a3;
        float pA = a0 * av.x + a1 * av.y + a2 * av.z + a3 * av.w;
        pA = wsum(pA);
        float eA = __expf(pA);
        acc.x += eA * A01.x; acc.y += eA * A01.y;
        acc.z += eA * A23.x; acc.w += eA * A23.y;
        sden += eA;
    }
    float inv = 1.f / fmaxf(sden, 1e-16f);
    if (STORE) {
        *(float4*)o = make_float4(acc.x * inv, acc.y * inv, acc.z * inv,
                                  acc.w * inv);
    } else {
        float4 g = *(float4*)o;
        g.x += acc.x * inv; g.y += acc.y * inv;
        g.z += acc.z * inv; g.w += acc.w * inv;
        *(float4*)o = g;
    }
}

// combined GATv2 output bias per (layer, dst type)
__global__ void cbias2_kernel(const float* __restrict__ cb,
                              float* __restrict__ out) {
    int l = blockIdx.x;
    int c = threadIdx.x;
    float s[3] = {0.f, 0.f, 0.f};
#pragma unroll
    for (int r = 0; r < RR; ++r) s[c_RD[r]] += cb[(l * RR + r) * HD + c];
    out[(l * 3 + 0) * HD + c] = s[0];
    out[(l * 3 + 1) * HD + c] = s[1];
    out[(l * 3 + 2) * HD + c] = s[2];
}

// ---------------- merged layernorm + relu over all 3 types -------------------
__global__ void ln_relu_all_kernel(const float* __restrict__ a0,
                                   const float* __restrict__ a1,
                                   const float* __restrict__ a2,
                                   float* __restrict__ x0,
                                   float* __restrict__ x1,
                                   float* __restrict__ x2,
                                   const float* __restrict__ cb3,
                                   const float* __restrict__ g3,
                                   const float* __restrict__ b3) {
    int row = (blockIdx.x * blockDim.x + threadIdx.x) >> 5;
    int lane = threadIdx.x & 31;
    if (row >= NROWS) return;
    int t, lr;
    const float* in;
    float* out;
    if (row < N0) { t = 0; lr = row; in = a0; out = x0; }
    else if (row < N0 + N1) { t = 1; lr = row - N0; in = a1; out = x1; }
    else { t = 2; lr = row - N0 - N1; in = a2; out = x2; }
    float4 v = *(const float4*)&in[(size_t)lr * 128 + lane * 4];
    float4 cv = *(const float4*)&cb3[t * HD + lane * 4];
    v.x += cv.x; v.y += cv.y; v.z += cv.z; v.w += cv.w;
    float s = v.x + v.y + v.z + v.w;
    s = wsum(s);
    float mu = s * (1.f / 128.f);
    float d0 = v.x - mu, d1 = v.y - mu, d2 = v.z - mu, d3 = v.w - mu;
    float ss = d0 * d0 + d1 * d1 + d2 * d2 + d3 * d3;
    ss = wsum(ss);
    float inv = rsqrtf(ss * (1.f / 128.f) + 1e-5f);
    float4 gv = *(const float4*)&g3[t * HD + lane * 4];
    float4 bv = *(const float4*)&b3[t * HD + lane * 4];
    float4 o;
    o.x = fmaxf(d0 * inv * gv.x + bv.x, 0.f);
    o.y = fmaxf(d1 * inv * gv.y + bv.y, 0.f);
    o.z = fmaxf(d2 * inv * gv.z + bv.z, 0.f);
    o.w = fmaxf(d3 * inv * gv.w + bv.w, 0.f);
    *(float4*)&out[(size_t)lr * 128 + lane * 4] = o;
}

// ---------------- prediction head ----------------
__global__ void pred_kernel(const float* __restrict__ x,
                            const float* __restrict__ Wp,
                            const float* __restrict__ bp,
                            float* __restrict__ out, int N) {
    int row = (blockIdx.x * blockDim.x + threadIdx.x) >> 5;
    int lane = threadIdx.x & 31;
    if (row >= N) return;
    float4 xv = *(const float4*)&x[(size_t)row * 128 + lane * 4];
    float4 w01 = *(const float4*)&Wp[lane * 8];
    float4 w23 = *(const float4*)&Wp[lane * 8 + 4];
    float a0 = xv.x * w01.x + xv.y * w01.z + xv.z * w23.x + xv.w * w23.z;
    float a1 = xv.x * w01.y + xv.y * w01.w + xv.z * w23.y + xv.w * w23.w;
    a0 = wsum(a0);
    a1 = wsum(a1);
    if (lane == 0) {
        out[row * 2 + 0] = a0 + bp[0];
        out[row * 2 + 1] = a1 + bp[1];
    }
}

// ---------------- host orchestration ----------------
extern "C" void kernel_launch(void* const* d_in, const int* in_sizes, int n_in,
                              void* d_out, int out_size) {
    const float* x_atom = (const float*)d_in[0];
    const float* x_chem = (const float*)d_in[1];
    const float* x_gene = (const float*)d_in[2];
    const float* x_assay = (const float*)d_in[3];
    const float* W_mol = (const float*)d_in[4];
    const float* Wl = (const float*)d_in[5];
    const float* Wr = (const float*)d_in[6];
    const float* bl = (const float*)d_in[7];
    const float* br = (const float*)d_in[8];
    const float* att = (const float*)d_in[9];
    const float* cb = (const float*)d_in[10];
    const float* lng = (const float*)d_in[11];
    const float* lnb = (const float*)d_in[12];
    const float* Wp = (const float*)d_in[13];
    const float* bp = (const float*)d_in[14];
    const int* hyper = (const int*)d_in[15];
    const int* eir = (const int*)d_in[16];
    float* out = (float*)d_out;
    (void)in_sizes; (void)n_in; (void)out_size;

    float *px0, *px1, *px2, *pa0, *pa1, *pa2, *pxr, *pcnt, *pcb;
    __half* pxlh;
    int *pcounts, *poffs, *pfill, *psums, *pss;
    cudaGetSymbolAddress((void**)&px0, g_x0);
    cudaGetSymbolAddress((void**)&px1, g_x1);
    cudaGetSymbolAddress((void**)&px2, g_x2);
    cudaGetSymbolAddress((void**)&pa0, g_a0);
    cudaGetSymbolAddress((void**)&pa1, g_a1);
    cudaGetSymbolAddress((void**)&pa2, g_a2);
    cudaGetSymbolAddress((void**)&pxlh, g_xlh);
    cudaGetSymbolAddress((void**)&pxr, g_xr);
    cudaGetSymbolAddress((void**)&pcnt, g_cnt);
    cudaGetSymbolAddress((void**)&pcb, g_cbias);
    cudaGetSymbolAddress((void**)&pcounts, g_counts);
    cudaGetSymbolAddress((void**)&poffs, g_offs);
    cudaGetSymbolAddress((void**)&pfill, g_fill);
    cudaGetSymbolAddress((void**)&psums, g_sums);
    cudaGetSymbolAddress((void**)&pss, g_ssorted);

    // same 2-stream topology that passed teardown checks in rounds 6-8
    static cudaStream_t s1 = nullptr;
    static cudaEvent_t evStart, evFork, evCSR, evG[LL * RR], evE[LL * RR],
        evL[LL];
    if (!s1) {
        cudaStreamCreateWithFlags(&s1, cudaStreamNonBlocking);
        cudaEventCreateWithFlags(&evStart, cudaEventDisableTiming);
        cudaEventCreateWithFlags(&evFork, cudaEventDisableTiming);
        cudaEventCreateWithFlags(&evCSR, cudaEventDisableTiming);
        for (int i = 0; i < LL * RR; ++i) {
            cudaEventCreateWithFlags(&evG[i], cudaEventDisableTiming);
            cudaEventCreateWithFlags(&evE[i], cudaEventDisableTiming);
        }
        for (int i = 0; i < LL; ++i)
            cudaEventCreateWithFlags(&evL[i], cudaEventDisableTiming);
    }

    const int T = 256;
    const int ZB = 1024;
    const int SMEMB = 65536;

    cudaFuncSetAttribute(tc_gemm_scatter_kernel,
                         cudaFuncAttributeMaxDynamicSharedMemorySize, SMEMB);
    cudaFuncSetAttribute(tc_gemm_pair_kernel,
                         cudaFuncAttributeMaxDynamicSharedMemorySize, SMEMB);

    static const int RS[RR] = {0, 0, 0, 0, 0, 2, 1, 2, 2, 1, 1, 1, 1};
    static const int RD[RR] = {2, 2, 1, 1, 1, 1, 1, 0, 0, 0, 0, 0, 2};
    // round-robin over dst types (keeps agg streams well interleaved even on
    // one consumer stream; preserves STORE-before-accumulate per type)
    static const int ORD[RR] = {0, 2, 7, 1, 3, 8, 12, 4, 9, 5, 10, 6, 11};
    // first relation per dst type (store mode): r0 -> t2, r2 -> t1, r7 -> t0
    static const bool FIRST[RR] = {true,  false, true,  false, false,
                                   false, false, true,  false, false,
                                   false, false, false};
    const int NT[3] = {N0, N1, N2};

    // fork s1 at the very start: CSR build + cbias precompute run concurrently
    // with the atom-encoder prelude on stream 0.
    cudaEventRecord(evStart, 0);
    cudaStreamWaitEvent(s1, evStart, 0);
    zero_i_kernel<<<256, T, 0, s1>>>(pcounts, NCNT);
    {
        dim3 hg((NE + T - 1) / T, RR);
        hist_kernel<<<hg, T, 0, s1>>>(eir, pcounts);
        scanA_kernel<<<NBLK, 256, 0, s1>>>(pcounts, poffs, psums);
        scanB_kernel<<<1, 1024, 0, s1>>>(psums);
        scanC_kernel<<<NBLK, 256, 0, s1>>>(poffs, psums, pfill);
        csr_scatter_kernel<<<hg, T, 0, s1>>>(eir, pfill, pss);
        cbias2_kernel<<<LL, HD, 0, s1>>>(cb, pcb);
    }
    cudaEventRecord(evCSR, s1);

    // ---- atom encoder + bottom-up mean aggregation into chemical (stream 0) --
    zero_f_kernel<<<ZB, T>>>(pa0, N0 * HD);
    zero_f_kernel<<<(N0 + T - 1) / T, T>>>(pcnt, N0);
    count_kernel<<<(NA + T - 1) / T, T>>>(hyper, pcnt, NA);
    tc_gemm_scatter_kernel<<<(NA + 127) / 128, T, SMEMB>>>(x_atom, W_mol, pa0,
                                                           hyper, NA);
    combine_kernel<<<(N0 * HD + T - 1) / T, T>>>(pa0, pcnt, x_chem, px0,
                                                 N0 * HD);
    cudaEventRecord(evFork, 0);
    cudaStreamWaitEvent(s1, evFork, 0);  // s1's GEMMs read px0
    cudaStreamWaitEvent(0, evCSR, 0);    // edge kernels need CSR + cbias

    const float* xsrc[3] = {px0, x_gene, x_assay};
    float* agg[3] = {pa0, pa1, pa2};

    for (int l = 0; l < LL; ++l) {
        size_t lo = (size_t)l * RR;

        for (int q = 0; q < RR; ++q) {
            int r = ORD[q];
            int s = RS[r], d = RD[r];
            int Ns = NT[s], Nd = NT[d];
            size_t wo = lo + r;
            int k = l * RR + q;   // sequential pipeline index
            int buf = k & (NBUF - 1);
            __half* bxl = pxlh + (size_t)buf * SLAB;
            float* bxr = pxr + (size_t)buf * SLAB;

            if (k >= NBUF) cudaStreamWaitEvent(s1, evE[k - NBUF], 0);  // WAR
            Pair pr;
            pr.A[0] = xsrc[s];  pr.M[0] = Ns;
            pr.A[1] = xsrc[d];  pr.M[1] = Nd;
            pr.W[0] = Wl + wo * HD * HD;
            pr.W[1] = Wr + wo * HD * HD;
            pr.bias[0] = bl + wo * HD;
            pr.bias[1] = br + wo * HD;
            pr.C[0] = bxl;
            pr.C[1] = bxr;
            int mx = Ns > Nd ? Ns : Nd;
            dim3 ggrid((mx + 127) / 128, 2);
            tc_gemm_pair_kernel<<<ggrid, T, SMEMB, s1>>>(pr);
            cudaEventRecord(evG[k], s1);

            cudaStreamWaitEvent(0, evG[k], 0);
            int eg = (Nd * 32 + T - 1) / T;
            if (FIRST[r])
                edge_csr_kernel<true><<<eg, T>>>(pss, poffs, bxl, bxr,
                                                 att + wo * HD, agg[d], Nd,
                                                 r * CBASE);
            else
                edge_csr_kernel<false><<<eg, T>>>(pss, poffs, bxl, bxr,
                                                  att + wo * HD, agg[d], Nd,
                                                  r * CBASE);
            cudaEventRecord(evE[k], 0);
        }
        ln_relu_all_kernel<<<(NROWS * 32 + T - 1) / T, T>>>(
            pa0, pa1, pa2, px0, px1, px2, pcb + l * 3 * HD,
            lng + (size_t)l * 3 * HD, lnb + (size_t)l * 3 * HD);
        xsrc[0] = px0; xsrc[1] = px1; xsrc[2] = px2;
        cudaEventRecord(evL[l], 0);
        cudaStreamWaitEvent(s1, evL[l], 0);
    }

    pred_kernel<<<(N0 * 32 + T - 1) / T, T>>>(px0, Wp, bp, out, N0);
}

// round 11
// speedup vs baseline: 5.6775x; 1.1704x over previous
#include <cuda_runtime.h>
#include <cuda_bf16.h>
#include <cuda_fp16.h>
#include <math.h>
#include <stdint.h>

#define N0 20000
#define N1 20000
#define N2 10000
#define NA 600000
#define NE 400000
#define HD 128
#define RR 13
#define LL 2
#define SLAB (N0 * HD)
#define CBASE 20000           // per-relation counter stride (edge CSR)
#define NCNT 260096           // 1016 * 256 (edge counter array, zero-padded)
#define NBLK 1016
#define NCNT2 20224           // 79 * 256 (atom counter array, zero-padded)
#define NBLK2 79
#define NROWS (N0 + N1 + N2)  // 50000
#define NBUF 4                // xl/xr pipeline depth

// ---------------- scratch (static device globals; no allocation) ---------------
__device__ float g_x0[N0 * HD];
__device__ float g_x1[N1 * HD];
__device__ float g_x2[N2 * HD];
__device__ float g_a0[N0 * HD];
__device__ float g_a1[N1 * HD];
__device__ float g_a2[N2 * HD];
__device__ __half g_xlh[NBUF * SLAB];  // fp16 Wl outputs (gathered randomly)
__device__ float g_xr[NBUF * SLAB];    // fp32 Wr outputs (read linearly)
__device__ float g_cbias[LL * 3 * HD];
__device__ float g_zero128[HD];        // zero bias (zero-initialized)
// edge CSR scratch
__device__ int g_counts[NCNT];
__device__ int g_offs[NCNT];
__device__ int g_fill[NCNT];
__device__ int g_sums[NBLK];
__device__ int g_ssorted[RR * NE];     // src ids grouped by dst
// atom CSR scratch
__device__ int g_counts2[NCNT2];
__device__ int g_offs2[NCNT2];
__device__ int g_fill2[NCNT2];
__device__ int g_sums2[NBLK2];
__device__ int g_asorted[NA];          // atom ids grouped by chemical

__constant__ int c_RD[RR] = {2, 2, 1, 1, 1, 1, 1, 0, 0, 0, 0, 0, 2};

// ---------------- helpers ----------------
__device__ __forceinline__ float wsum(float v) {
#pragma unroll
    for (int o = 16; o; o >>= 1) v += __shfl_xor_sync(0xffffffffu, v, o);
    return v;
}
__device__ __forceinline__ void ldsm4(uint32_t* r, uint32_t addr) {
    asm volatile(
        "ldmatrix.sync.aligned.m8n8.x4.shared.b16 {%0,%1,%2,%3}, [%4];"
        : "=r"(r[0]), "=r"(r[1]), "=r"(r[2]), "=r"(r[3])
        : "r"(addr));
}
__device__ __forceinline__ void ldsm4t(uint32_t* r, uint32_t addr) {
    asm volatile(
        "ldmatrix.sync.aligned.m8n8.x4.trans.shared.b16 {%0,%1,%2,%3}, [%4];"
        : "=r"(r[0]), "=r"(r[1]), "=r"(r[2]), "=r"(r[3])
        : "r"(addr));
}
__device__ __forceinline__ void mma16816(float* d, const uint32_t* a,
                                         const uint32_t* b) {
    asm volatile(
        "mma.sync.aligned.m16n8k16.row.col.f32.bf16.bf16.f32 "
        "{%0,%1,%2,%3}, {%4,%5,%6,%7}, {%8,%9}, {%0,%1,%2,%3};"
        : "+f"(d[0]), "+f"(d[1]), "+f"(d[2]), "+f"(d[3])
        : "r"(a[0]), "r"(a[1]), "r"(a[2]), "r"(a[3]), "r"(b[0]), "r"(b[1]));
}
__device__ __forceinline__ void split4(float4 v, uint2& hi, uint2& lo) {
    __nv_bfloat162 h0 = __floats2bfloat162_rn(v.x, v.y);
    __nv_bfloat162 h1 = __floats2bfloat162_rn(v.z, v.w);
    float2 f0 = __bfloat1622float2(h0);
    float2 f1 = __bfloat1622float2(h1);
    __nv_bfloat162 l0 = __floats2bfloat162_rn(v.x - f0.x, v.y - f0.y);
    __nv_bfloat162 l1 = __floats2bfloat162_rn(v.z - f1.x, v.w - f1.y);
    hi = make_uint2(*(uint32_t*)&h0, *(uint32_t*)&h1);
    lo = make_uint2(*(uint32_t*)&l0, *(uint32_t*)&l1);
}

// ---------------- zero kernels ----------------
__global__ void zero_i_kernel(int* p, int n) {
    int i = blockIdx.x * blockDim.x + threadIdx.x;
    int st = gridDim.x * blockDim.x;
    for (; i < n; i += st) p[i] = 0;
}

// ---------------- generic CSR build pieces ----------------
__global__ void hist_kernel(const int* __restrict__ eir,
                            int* __restrict__ cnt) {
    int r = blockIdx.y;
    int i = blockIdx.x * blockDim.x + threadIdx.x;
    if (i < NE) atomicAdd(&cnt[r * CBASE + eir[(size_t)r * 2 * NE + NE + i]], 1);
}
__global__ void hist2_kernel(const int* __restrict__ hyper,
                             int* __restrict__ cnt) {
    int i = blockIdx.x * blockDim.x + threadIdx.x;
    if (i < NA) atomicAdd(&cnt[hyper[i]], 1);
}
__global__ void scanA_kernel(const int* __restrict__ cnt, int* __restrict__ out,
                             int* __restrict__ sums) {
    __shared__ int sh[256];
    int i = blockIdx.x * 256 + threadIdx.x;
    int v = cnt[i];
    sh[threadIdx.x] = v;
    __syncthreads();
    for (int o = 1; o < 256; o <<= 1) {
        int t = (threadIdx.x >= o) ? sh[threadIdx.x - o] : 0;
        __syncthreads();
        sh[threadIdx.x] += t;
        __syncthreads();
    }
    out[i] = sh[threadIdx.x] - v;
    if (threadIdx.x == 255) sums[blockIdx.x] = sh[255];
}
__global__ void scanB_kernel(int* __restrict__ sums, int n) {
    __shared__ int sh[1024];
    int v = (threadIdx.x < n) ? sums[threadIdx.x] : 0;
    sh[threadIdx.x] = v;
    __syncthreads();
    for (int o = 1; o < 1024; o <<= 1) {
        int t = (threadIdx.x >= o) ? sh[threadIdx.x - o] : 0;
        __syncthreads();
        sh[threadIdx.x] += t;
        __syncthreads();
    }
    if (threadIdx.x < n) sums[threadIdx.x] = sh[threadIdx.x] - v;
}
__global__ void scanC_kernel(int* __restrict__ out, const int* __restrict__ sums,
                             int* __restrict__ fill) {
    int i = blockIdx.x * 256 + threadIdx.x;
    int v = out[i] + sums[blockIdx.x];
    out[i] = v;
    fill[i] = v;
}
__global__ void csr_scatter_kernel(const int* __restrict__ eir,
                                   int* __restrict__ fill,
                                   int* __restrict__ ssorted) {
    int r = blockIdx.y;
    int i = blockIdx.x * blockDim.x + threadIdx.x;
    if (i >= NE) return;
    int d = eir[(size_t)r * 2 * NE + NE + i];
    int s = eir[(size_t)r * 2 * NE + i];
    int pos = atomicAdd(&fill[r * CBASE + d], 1);
    ssorted[pos] = s;
}
__global__ void acsr_scatter_kernel(const int* __restrict__ hyper,
                                    int* __restrict__ fill,
                                    int* __restrict__ asorted) {
    int i = blockIdx.x * blockDim.x + threadIdx.x;
    if (i >= NA) return;
    int pos = atomicAdd(&fill[hyper[i]], 1);
    asorted[pos] = i;
}

// ---------------- atom aggregation: warp per chemical, no atomics ------------
__global__ __launch_bounds__(256) void atom_sum_kernel(
    const int* __restrict__ asorted, const int* __restrict__ aoffs,
    const float* __restrict__ xa, float* __restrict__ g) {
    int d = (blockIdx.x * blockDim.x + threadIdx.x) >> 5;
    int lane = threadIdx.x & 31;
    if (d >= N0) return;
    int beg = aoffs[d], end = aoffs[d + 1];
    float4 acc = make_float4(0.f, 0.f, 0.f, 0.f);
    int j = beg;
    for (; j + 1 < end; j += 2) {
        int a0 = asorted[j], a1 = asorted[j + 1];
        float4 v0 = *(const float4*)&xa[(size_t)a0 * 128 + lane * 4];
        float4 v1 = *(const float4*)&xa[(size_t)a1 * 128 + lane * 4];
        acc.x += v0.x + v1.x; acc.y += v0.y + v1.y;
        acc.z += v0.z + v1.z; acc.w += v0.w + v1.w;
    }
    if (j < end) {
        int a0 = asorted[j];
        float4 v0 = *(const float4*)&xa[(size_t)a0 * 128 + lane * 4];
        acc.x += v0.x; acc.y += v0.y; acc.z += v0.z; acc.w += v0.w;
    }
    *(float4*)&g[(size_t)d * 128 + lane * 4] = acc;
}

// x0 = gemm_out/max(cnt,1) + x_chem   (cnt from atom histogram, int)
__global__ void combine_kernel(const float* __restrict__ t,
                               const int* __restrict__ cnt,
                               const float* __restrict__ xc,
                               float* __restrict__ out, int n) {
    int i = blockIdx.x * blockDim.x + threadIdx.x;
    if (i < n) out[i] = t[i] / fmaxf((float)cnt[i >> 7], 1.f) + xc[i];
}

// ---------------- tensor-core bf16x3 GEMM core ------------------------------
template <bool HALFOUT>
__device__ __forceinline__ void tc_gemm_core(const float* __restrict__ A,
                                             const float* __restrict__ B,
                                             const float* __restrict__ bias,
                                             void* __restrict__ Cv, int M) {
    extern __shared__ __nv_bfloat16 sm[];
    __nv_bfloat16* sAh = sm;
    __nv_bfloat16* sAl = sm + 8192;
    __nv_bfloat16* sBh = sm + 16384;
    __nv_bfloat16* sBl = sm + 24576;
    const int tid = threadIdx.x;
    const int lane = tid & 31, warp = tid >> 5;
    const int wm = warp & 3, wn = warp >> 2;
    const int rowBase = blockIdx.x * 128;
    if (rowBase >= M) return;

    float acc[2][8][4];
#pragma unroll
    for (int a = 0; a < 2; ++a)
#pragma unroll
        for (int b = 0; b < 8; ++b)
#pragma unroll
            for (int c = 0; c < 4; ++c) acc[a][b][c] = 0.f;

    uint32_t sAh_b = (uint32_t)__cvta_generic_to_shared(sAh);
    uint32_t sAl_b = (uint32_t)__cvta_generic_to_shared(sAl);
    uint32_t sBh_b = (uint32_t)__cvta_generic_to_shared(sBh);
    uint32_t sBl_b = (uint32_t)__cvta_generic_to_shared(sBl);

    for (int kc = 0; kc < 128; kc += 64) {
        __syncthreads();
#pragma unroll
        for (int i = 0; i < 8; ++i) {
            int j = tid + 256 * i;
            int row = j >> 4, c4 = j & 15;
            float4 v = make_float4(0.f, 0.f, 0.f, 0.f);
            if (rowBase + row < M)
                v = *(const float4*)&A[(size_t)(rowBase + row) * 128 + kc +
                                       c4 * 4];
            uint2 h, l;
            split4(v, h, l);
            int off = row * 64 + (((c4 >> 1) ^ (row & 7)) << 3) + (c4 & 1) * 4;
            *(uint2*)&sAh[off] = h;
            *(uint2*)&sAl[off] = l;
        }
#pragma unroll
        for (int i = 0; i < 8; ++i) {
            int j = tid + 256 * i;
            int row = j >> 5, c4 = j & 31;
            float4 v = *(const float4*)&B[(size_t)(kc + row) * 128 + c4 * 4];
            uint2 h, l;
            split4(v, h, l);
            int off = row * 128 + (((c4 >> 1) ^ (row & 7)) << 3) + (c4 & 1) * 4;
            *(uint2*)&sBh[off] = h;
            *(uint2*)&sBl[off] = l;
        }
        __syncthreads();
#pragma unroll
        for (int s = 0; s < 4; ++s) {
            uint32_t ah[2][4], al[2][4];
#pragma unroll
            for (int mf = 0; mf < 2; ++mf) {
                int mr = wm * 32 + mf * 16 + (lane & 15);
                int ck = 2 * s + (lane >> 4);
                uint32_t off = (uint32_t)(mr * 64 + ((ck ^ (mr & 7)) << 3)) * 2;
                ldsm4(ah[mf], sAh_b + off);
                ldsm4(al[mf], sAl_b + off);
            }
#pragma unroll
            for (int nf2 = 0; nf2 < 4; ++nf2) {
                int kr = s * 16 + (lane & 7) + ((lane >> 3) & 1) * 8;
                int cn = wn * 8 + nf2 * 2 + (lane >> 4);
                uint32_t off =
                    (uint32_t)(kr * 128 + ((cn ^ (kr & 7)) << 3)) * 2;
                uint32_t bh[4], bl[4];
                ldsm4t(bh, sBh_b + off);
                ldsm4t(bl, sBl_b + off);
#pragma unroll
                for (int mf = 0; mf < 2; ++mf) {
                    mma16816(acc[mf][nf2 * 2], ah[mf], bh);
                    mma16816(acc[mf][nf2 * 2], ah[mf], bl);
                    mma16816(acc[mf][nf2 * 2], al[mf], bh);
                    mma16816(acc[mf][nf2 * 2 + 1], ah[mf], bh + 2);
                    mma16816(acc[mf][nf2 * 2 + 1], ah[mf], bl + 2);
                    mma16816(acc[mf][nf2 * 2 + 1], al[mf], bh + 2);
                }
            }
        }
    }
    int c0 = wn * 64 + (lane & 3) * 2;
#pragma unroll
    for (int mf = 0; mf < 2; ++mf) {
        int r0 = rowBase + wm * 32 + mf * 16 + (lane >> 2);
#pragma unroll
        for (int nf = 0; nf < 8; ++nf) {
            int col = c0 + nf * 8;
            float2 bv = *(const float2*)&bias[col];
            if (HALFOUT) {
                __half* C = (__half*)Cv;
                if (r0 < M)
                    *(__half2*)&C[(size_t)r0 * 128 + col] = __floats2half2_rn(
                        acc[mf][nf][0] + bv.x, acc[mf][nf][1] + bv.y);
                if (r0 + 8 < M)
                    *(__half2*)&C[(size_t)(r0 + 8) * 128 + col] =
                        __floats2half2_rn(acc[mf][nf][2] + bv.x,
                                          acc[mf][nf][3] + bv.y);
            } else {
                float* C = (float*)Cv;
                if (r0 < M) {
                    C[(size_t)r0 * 128 + col] = acc[mf][nf][0] + bv.x;
                    C[(size_t)r0 * 128 + col + 1] = acc[mf][nf][1] + bv.y;
                }
                if (r0 + 8 < M) {
                    C[(size_t)(r0 + 8) * 128 + col] = acc[mf][nf][2] + bv.x;
                    C[(size_t)(r0 + 8) * 128 + col + 1] = acc[mf][nf][3] + bv.y;
                }
            }
        }
    }
}

struct Pair {
    const float* A[2];
    const float* W[2];
    const float* bias[2];
    void* C[2];
    int M[2];
};

// z=0 -> Wl GEMM, fp16 output; z=1 -> Wr GEMM, fp32 output
__global__ __launch_bounds__(256, 2) void tc_gemm_pair_kernel(Pair pr) {
    int z = blockIdx.y;
    if (z == 0)
        tc_gemm_core<true>(pr.A[0], pr.W[0], pr.bias[0], pr.C[0], pr.M[0]);
    else
        tc_gemm_core<false>(pr.A[1], pr.W[1], pr.bias[1], pr.C[1], pr.M[1]);
}
__global__ __launch_bounds__(256, 2) void tc_gemm_f32_kernel(
    const float* __restrict__ A, const float* __restrict__ B,
    const float* __restrict__ bias, float* __restrict__ C, int M) {
    tc_gemm_core<false>(A, B, bias, C, M);
}

// ---------------- CSR edge aggregation (one warp per dst node) ---------------
// xl fp16 gathers, unroll-4 for memory-level parallelism; __expf.
template <bool STORE>
__global__ __launch_bounds__(256) void edge_csr_kernel(
    const int* __restrict__ ssorted, const int* __restrict__ offs,
    const __half* __restrict__ xl, const float* __restrict__ xr,
    const float* __restrict__ a, float* __restrict__ agg, int Nd, int robase) {
    int d = (blockIdx.x * blockDim.x + threadIdx.x) >> 5;
    int lane = threadIdx.x & 31;
    if (d >= Nd) return;
    int beg = offs[robase + d], end = offs[robase + d + 1];
    float* o = &agg[(size_t)d * 128 + lane * 4];
    if (beg == end) {
        if (STORE) *(float4*)o = make_float4(0.f, 0.f, 0.f, 0.f);
        return;
    }
    float4 r4 = *(const float4*)&xr[(size_t)d * 128 + lane * 4];
    float4 av = *(const float4*)&a[lane * 4];
    float4 acc = make_float4(0.f, 0.f, 0.f, 0.f);
    float sden = 0.f;
    int j = beg;
    for (; j + 3 < end; j += 4) {
        int s0 = ssorted[j], s1 = ssorted[j + 1];
        int s2 = ssorted[j + 2], s3 = ssorted[j + 3];
        uint2 u0 = *(const uint2*)&xl[(size_t)s0 * 128 + lane * 4];
        uint2 u1 = *(const uint2*)&xl[(size_t)s1 * 128 + lane * 4];
        uint2 u2 = *(const uint2*)&xl[(size_t)s2 * 128 + lane * 4];
        uint2 u3 = *(const uint2*)&xl[(size_t)s3 * 128 + lane * 4];
        float2 A01 = __half22float2(*(__half2*)&u0.x);
        float2 A23 = __half22float2(*(__half2*)&u0.y);
        float2 B01 = __half22float2(*(__half2*)&u1.x);
        float2 B23 = __half22float2(*(__half2*)&u1.y);
        float2 C01 = __half22float2(*(__half2*)&u2.x);
        float2 C23 = __half22float2(*(__half2*)&u2.y);
        float2 D01 = __half22float2(*(__half2*)&u3.x);
        float2 D23 = __half22float2(*(__half2*)&u3.y);
        float t;
        float pA, pB, pC, pD;
        t = A01.x + r4.x; t = t > 0.f ? t : 0.2f * t; pA = t * av.x;
        t = A01.y + r4.y; t = t > 0.f ? t : 0.2f * t; pA += t * av.y;
        t = A23.x + r4.z; t = t > 0.f ? t : 0.2f * t; pA += t * av.z;
        t = A23.y + r4.w; t = t > 0.f ? t : 0.2f * t; pA += t * av.w;
        t = B01.x + r4.x; t = t > 0.f ? t : 0.2f * t; pB = t * av.x;
        t = B01.y + r4.y; t = t > 0.f ? t : 0.2f * t; pB += t * av.y;
        t = B23.x + r4.z; t = t > 0.f ? t : 0.2f * t; pB += t * av.z;
        t = B23.y + r4.w; t = t > 0.f ? t : 0.2f * t; pB += t * av.w;
        t = C01.x + r4.x; t = t > 0.f ? t : 0.2f * t; pC = t * av.x;
        t = C01.y + r4.y; t = t > 0.f ? t : 0.2f * t; pC += t * av.y;
        t = C23.x + r4.z; t = t > 0.f ? t : 0.2f * t; pC += t * av.z;
        t = C23.y + r4.w; t = t > 0.f ? t : 0.2f * t; pC += t * av.w;
        t = D01.x + r4.x; t = t > 0.f ? t : 0.2f * t; pD = t * av.x;
        t = D01.y + r4.y; t = t > 0.f ? t : 0.2f * t; pD += t * av.y;
        t = D23.x + r4.z; t = t > 0.f ? t : 0.2f * t; pD += t * av.z;
        t = D23.y + r4.w; t = t > 0.f ? t : 0.2f * t; pD += t * av.w;
        pA = wsum(pA); pB = wsum(pB); pC = wsum(pC); pD = wsum(pD);
        float eA = __expf(pA), eB = __expf(pB);
        float eC = __expf(pC), eD = __expf(pD);
        acc.x += eA * A01.x + eB * B01.x + eC * C01.x + eD * D01.x;
        acc.y += eA * A01.y + eB * B01.y + eC * C01.y + eD * D01.y;
        acc.z += eA * A23.x + eB * B23.x + eC * C23.x + eD * D23.x;
        acc.w += eA * A23.y + eB * B23.y + eC * C23.y + eD * D23.y;
        sden += (eA + eB) + (eC + eD);
    }
    for (; j < end; ++j) {
        int s0 = ssorted[j];
        uint2 u0 = *(const uint2*)&xl[(size_t)s0 * 128 + lane * 4];
        float2 A01 = __half22float2(*(__half2*)&u0.x);
        float2 A23 = __half22float2(*(__half2*)&u0.y);
        float t, pA;
        t = A01.x + r4.x; t = t > 0.f ? t : 0.2f * t; pA = t * av.x;
        t = A01.y + r4.y; t = t > 0.f ? t : 0.2f * t; pA += t * av.y;
        t = A23.x + r4.z; t = t > 0.f ? t : 0.2f * t; pA += t * av.z;
        t = A23.y + r4.w; t = t > 0.f ? t : 0.2f * t; pA += t * av.w;
        pA = wsum(pA);
        float eA = __expf(pA);
        acc.x += eA * A01.x; acc.y += eA * A01.y;
        acc.z += eA * A23.x; acc.w += eA * A23.y;
        sden += eA;
    }
    float inv = 1.f / fmaxf(sden, 1e-16f);
    if (STORE) {
        *(float4*)o = make_float4(acc.x * inv, acc.y * inv, acc.z * inv,
                                  acc.w * inv);
    } else {
        float4 g = *(float4*)o;
        g.x += acc.x * inv; g.y += acc.y * inv;
        g.z += acc.z * inv; g.w += acc.w * inv;
        *(float4*)o = g;
    }
}

// combined GATv2 output bias per (layer, dst type)
__global__ void cbias2_kernel(const float* __restrict__ cb,
                              float* __restrict__ out) {
    int l = blockIdx.x;
    int c = threadIdx.x;
    float s[3] = {0.f, 0.f, 0.f};
#pragma unroll
    for (int r = 0; r < RR; ++r) s[c_RD[r]] += cb[(l * RR + r) * HD + c];
    out[(l * 3 + 0) * HD + c] = s[0];
    out[(l * 3 + 1) * HD + c] = s[1];
    out[(l * 3 + 2) * HD + c] = s[2];
}

// ---------------- merged layernorm + relu over all 3 types -------------------
__global__ void ln_relu_all_kernel(const float* __restrict__ a0,
                                   const float* __restrict__ a1,
                                   const float* __restrict__ a2,
                                   float* __restrict__ x0,
                                   float* __restrict__ x1,
                                   float* __restrict__ x2,
                                   const float* __restrict__ cb3,
                                   const float* __restrict__ g3,
                                   const float* __restrict__ b3) {
    int row = (blockIdx.x * blockDim.x + threadIdx.x) >> 5;
    int lane = threadIdx.x & 31;
    if (row >= NROWS) return;
    int t, lr;
    const float* in;
    float* out;
    if (row < N0) { t = 0; lr = row; in = a0; out = x0; }
    else if (row < N0 + N1) { t = 1; lr = row - N0; in = a1; out = x1; }
    else { t = 2; lr = row - N0 - N1; in = a2; out = x2; }
    float4 v = *(const float4*)&in[(size_t)lr * 128 + lane * 4];
    float4 cv = *(const float4*)&cb3[t * HD + lane * 4];
    v.x += cv.x; v.y += cv.y; v.z += cv.z; v.w += cv.w;
    float s = v.x + v.y + v.z + v.w;
    s = wsum(s);
    float mu = s * (1.f / 128.f);
    float d0 = v.x - mu, d1 = v.y - mu, d2 = v.z - mu, d3 = v.w - mu;
    float ss = d0 * d0 + d1 * d1 + d2 * d2 + d3 * d3;
    ss = wsum(ss);
    float inv = rsqrtf(ss * (1.f / 128.f) + 1e-5f);
    float4 gv = *(const float4*)&g3[t * HD + lane * 4];
    float4 bv = *(const float4*)&b3[t * HD + lane * 4];
    float4 o;
    o.x = fmaxf(d0 * inv * gv.x + bv.x, 0.f);
    o.y = fmaxf(d1 * inv * gv.y + bv.y, 0.f);
    o.z = fmaxf(d2 * inv * gv.z + bv.z, 0.f);
    o.w = fmaxf(d3 * inv * gv.w + bv.w, 0.f);
    *(float4*)&out[(size_t)lr * 128 + lane * 4] = o;
}

// ---------------- prediction head ----------------
__global__ void pred_kernel(const float* __restrict__ x,
                            const float* __restrict__ Wp,
                            const float* __restrict__ bp,
                            float* __restrict__ out, int N) {
    int row = (blockIdx.x * blockDim.x + threadIdx.x) >> 5;
    int lane = threadIdx.x & 31;
    if (row >= N) return;
    float4 xv = *(const float4*)&x[(size_t)row * 128 + lane * 4];
    float4 w01 = *(const float4*)&Wp[lane * 8];
    float4 w23 = *(const float4*)&Wp[lane * 8 + 4];
    float a0 = xv.x * w01.x + xv.y * w01.z + xv.z * w23.x + xv.w * w23.z;
    float a1 = xv.x * w01.y + xv.y * w01.w + xv.z * w23.y + xv.w * w23.w;
    a0 = wsum(a0);
    a1 = wsum(a1);
    if (lane == 0) {
        out[row * 2 + 0] = a0 + bp[0];
        out[row * 2 + 1] = a1 + bp[1];
    }
}

// ---------------- host orchestration ----------------
extern "C" void kernel_launch(void* const* d_in, const int* in_sizes, int n_in,
                              void* d_out, int out_size) {
    const float* x_atom = (const float*)d_in[0];
    const float* x_chem = (const float*)d_in[1];
    const float* x_gene = (const float*)d_in[2];
    const float* x_assay = (const float*)d_in[3];
    const float* W_mol = (const float*)d_in[4];
    const float* Wl = (const float*)d_in[5];
    const float* Wr = (const float*)d_in[6];
    const float* bl = (const float*)d_in[7];
    const float* br = (const float*)d_in[8];
    const float* att = (const float*)d_in[9];
    const float* cb = (const float*)d_in[10];
    const float* lng = (const float*)d_in[11];
    const float* lnb = (const float*)d_in[12];
    const float* Wp = (const float*)d_in[13];
    const float* bp = (const float*)d_in[14];
    const int* hyper = (const int*)d_in[15];
    const int* eir = (const int*)d_in[16];
    float* out = (float*)d_out;
    (void)in_sizes; (void)n_in; (void)out_size;

    float *px0, *px1, *px2, *pa0, *pa1, *pa2, *pxr, *pcb, *pz;
    __half* pxlh;
    int *pcounts, *poffs, *pfill, *psums, *pss;
    int *pcounts2, *poffs2, *pfill2, *psums2, *pas;
    cudaGetSymbolAddress((void**)&px0, g_x0);
    cudaGetSymbolAddress((void**)&px1, g_x1);
    cudaGetSymbolAddress((void**)&px2, g_x2);
    cudaGetSymbolAddress((void**)&pa0, g_a0);
    cudaGetSymbolAddress((void**)&pa1, g_a1);
    cudaGetSymbolAddress((void**)&pa2, g_a2);
    cudaGetSymbolAddress((void**)&pxlh, g_xlh);
    cudaGetSymbolAddress((void**)&pxr, g_xr);
    cudaGetSymbolAddress((void**)&pcb, g_cbias);
    cudaGetSymbolAddress((void**)&pz, g_zero128);
    cudaGetSymbolAddress((void**)&pcounts, g_counts);
    cudaGetSymbolAddress((void**)&poffs, g_offs);
    cudaGetSymbolAddress((void**)&pfill, g_fill);
    cudaGetSymbolAddress((void**)&psums, g_sums);
    cudaGetSymbolAddress((void**)&pss, g_ssorted);
    cudaGetSymbolAddress((void**)&pcounts2, g_counts2);
    cudaGetSymbolAddress((void**)&poffs2, g_offs2);
    cudaGetSymbolAddress((void**)&pfill2, g_fill2);
    cudaGetSymbolAddress((void**)&psums2, g_sums2);
    cudaGetSymbolAddress((void**)&pas, g_asorted);

    // 2-stream topology (teardown-safe configuration from rounds 6-8/10)
    static cudaStream_t s1 = nullptr;
    static cudaEvent_t evStart, evFork, evCSR, evG[LL * RR], evE[LL * RR],
        evL[LL];
    if (!s1) {
        cudaStreamCreateWithFlags(&s1, cudaStreamNonBlocking);
        cudaEventCreateWithFlags(&evStart, cudaEventDisableTiming);
        cudaEventCreateWithFlags(&evFork, cudaEventDisableTiming);
        cudaEventCreateWithFlags(&evCSR, cudaEventDisableTiming);
        for (int i = 0; i < LL * RR; ++i) {
            cudaEventCreateWithFlags(&evG[i], cudaEventDisableTiming);
            cudaEventCreateWithFlags(&evE[i], cudaEventDisableTiming);
        }
        for (int i = 0; i < LL; ++i)
            cudaEventCreateWithFlags(&evL[i], cudaEventDisableTiming);
    }

    const int T = 256;
    const int SMEMB = 65536;

    cudaFuncSetAttribute(tc_gemm_pair_kernel,
                         cudaFuncAttributeMaxDynamicSharedMemorySize, SMEMB);
    cudaFuncSetAttribute(tc_gemm_f32_kernel,
                         cudaFuncAttributeMaxDynamicSharedMemorySize, SMEMB);

    static const int RS[RR] = {0, 0, 0, 0, 0, 2, 1, 2, 2, 1, 1, 1, 1};
    static const int RD[RR] = {2, 2, 1, 1, 1, 1, 1, 0, 0, 0, 0, 0, 2};
    static const int ORD[RR] = {0, 2, 7, 1, 3, 8, 12, 4, 9, 5, 10, 6, 11};
    static const bool FIRST[RR] = {true,  false, true,  false, false,
                                   false, false, true,  false, false,
                                   false, false, false};
    const int NT[3] = {N0, N1, N2};

    // s1: edge CSR build + cbias precompute, concurrent with the prelude
    cudaEventRecord(evStart, 0);
    cudaStreamWaitEvent(s1, evStart, 0);
    zero_i_kernel<<<256, T, 0, s1>>>(pcounts, NCNT);
    {
        dim3 hg((NE + T - 1) / T, RR);
        hist_kernel<<<hg, T, 0, s1>>>(eir, pcounts);
        scanA_kernel<<<NBLK, 256, 0, s1>>>(pcounts, poffs, psums);
        scanB_kernel<<<1, 1024, 0, s1>>>(psums, NBLK);
        scanC_kernel<<<NBLK, 256, 0, s1>>>(poffs, psums, pfill);
        csr_scatter_kernel<<<hg, T, 0, s1>>>(eir, pfill, pss);
        cbias2_kernel<<<LL, HD, 0, s1>>>(cb, pcb);
    }
    cudaEventRecord(evCSR, s1);

    // ---- stream 0 prelude: atom CSR -> gather-sum -> 20k GEMM -> combine ----
    // segment_mean(x_atom @ W) == (segment_sum(x_atom)) @ W / cnt
    zero_i_kernel<<<80, T>>>(pcounts2, NCNT2);
    hist2_kernel<<<(NA + T - 1) / T, T>>>(hyper, pcounts2);
    scanA_kernel<<<NBLK2, 256>>>(pcounts2, poffs2, psums2);
    scanB_kernel<<<1, 1024>>>(psums2, NBLK2);
    scanC_kernel<<<NBLK2, 256>>>(poffs2, psums2, pfill2);
    acsr_scatter_kernel<<<(NA + T - 1) / T, T>>>(hyper, pfill2, pas);
    atom_sum_kernel<<<(N0 * 32 + T - 1) / T, T>>>(pas, poffs2, x_atom, pa1);
    tc_gemm_f32_kernel<<<(N0 + 127) / 128, T, SMEMB>>>(pa1, W_mol, pz, pa0,
                                                       N0);
    combine_kernel<<<(N0 * HD + T - 1) / T, T>>>(pa0, pcounts2, x_chem, px0,
                                                 N0 * HD);
    cudaEventRecord(evFork, 0);
    cudaStreamWaitEvent(s1, evFork, 0);  // s1's GEMMs read px0
    cudaStreamWaitEvent(0, evCSR, 0);    // edge kernels need CSR + cbias

    const float* xsrc[3] = {px0, x_gene, x_assay};
    float* agg[3] = {pa0, pa1, pa2};

    for (int l = 0; l < LL; ++l) {
        size_t lo = (size_t)l * RR;

        for (int q = 0; q < RR; ++q) {
            int r = ORD[q];
            int s = RS[r], d = RD[r];
            int Ns = NT[s], Nd = NT[d];
            size_t wo = lo + r;
            int k = l * RR + q;
            int buf = k & (NBUF - 1);
            __half* bxl = pxlh + (size_t)buf * SLAB;
            float* bxr = pxr + (size_t)buf * SLAB;

            if (k >= NBUF) cudaStreamWaitEvent(s1, evE[k - NBUF], 0);  // WAR
            Pair pr;
            pr.A[0] = xsrc[s];  pr.M[0] = Ns;
            pr.A[1] = xsrc[d];  pr.M[1] = Nd;
            pr.W[0] = Wl + wo * HD * HD;
            pr.W[1] = Wr + wo * HD * HD;
            pr.bias[0] = bl + wo * HD;
            pr.bias[1] = br + wo * HD;
            pr.C[0] = bxl;
            pr.C[1] = bxr;
            int mx = Ns > Nd ? Ns : Nd;
            dim3 ggrid((mx + 127) / 128, 2);
            tc_gemm_pair_kernel<<<ggrid, T, SMEMB, s1>>>(pr);
            cudaEventRecord(evG[k], s1);

            cudaStreamWaitEvent(0, evG[k], 0);
            int eg = (Nd * 32 + T - 1) / T;
            if (FIRST[r])
                edge_csr_kernel<true><<<eg, T>>>(pss, poffs, bxl, bxr,
                                                 att + wo * HD, agg[d], Nd,
                                                 r * CBASE);
            else
                edge_csr_kernel<false><<<eg, T>>>(pss, poffs, bxl, bxr,
                                                  att + wo * HD, agg[d], Nd,
                                                  r * CBASE);
            cudaEventRecord(evE[k], 0);
        }
        ln_relu_all_kernel<<<(NROWS * 32 + T - 1) / T, T>>>(
            pa0, pa1, pa2, px0, px1, px2, pcb + l * 3 * HD,
            lng + (size_t)l * 3 * HD, lnb + (size_t)l * 3 * HD);
        xsrc[0] = px0; xsrc[1] = px1; xsrc[2] = px2;
        cudaEventRecord(evL[l], 0);
        cudaStreamWaitEvent(s1, evL[l], 0);
    }

    pred_kernel<<<(N0 * 32 + T - 1) / T, T>>>(px0, Wp, bp, out, N0);
}

// round 12
// speedup vs baseline: 6.1084x; 1.0759x over previous
#include <cuda_runtime.h>
#include <cuda_bf16.h>
#include <cuda_fp16.h>
#include <math.h>
#include <stdint.h>

#define N0 20000
#define N1 20000
#define N2 10000
#define NA 600000
#define NE 400000
#define HD 128
#define RR 13
#define LL 2
#define SLAB (N0 * HD)
#define CBASE 20000           // per-relation counter stride (edge CSR)
#define NCNT 260096           // 1016 * 256 (edge counter array, zero-padded)
#define NBLK 1016
#define NCNT2 20224           // 79 * 256 (atom counter array, zero-padded)
#define NBLK2 79
#define NROWS (N0 + N1 + N2)  // 50000
#define NG 5                  // relation groups per layer

// ---------------- scratch (static device globals; no allocation) ---------------
__device__ float g_x0[N0 * HD];
__device__ float g_x1[N1 * HD];
__device__ float g_x2[N2 * HD];
__device__ float g_a0[N0 * HD];
__device__ float g_a1[N1 * HD];
__device__ float g_a2[N2 * HD];
__device__ __half g_xlh[RR * SLAB];  // per-relation fp16 Wl outputs
__device__ float g_xr[RR * SLAB];    // per-relation fp32 Wr outputs
__device__ float g_cbias[LL * 3 * HD];
__device__ float g_zero128[HD];      // zero bias (zero-initialized)
// edge CSR scratch
__device__ int g_counts[NCNT];
__device__ int g_offs[NCNT];
__device__ int g_fill[NCNT];
__device__ int g_sums[NBLK];
__device__ int g_ssorted[RR * NE];   // src ids grouped by dst
// atom CSR scratch
__device__ int g_counts2[NCNT2];
__device__ int g_offs2[NCNT2];
__device__ int g_fill2[NCNT2];
__device__ int g_sums2[NBLK2];
__device__ int g_asorted[NA];        // atom ids grouped by chemical

__constant__ int c_RD[RR] = {2, 2, 1, 1, 1, 1, 1, 0, 0, 0, 0, 0, 2};

// ---------------- helpers ----------------
__device__ __forceinline__ float wsum(float v) {
#pragma unroll
    for (int o = 16; o; o >>= 1) v += __shfl_xor_sync(0xffffffffu, v, o);
    return v;
}
__device__ __forceinline__ void ldsm4(uint32_t* r, uint32_t addr) {
    asm volatile(
        "ldmatrix.sync.aligned.m8n8.x4.shared.b16 {%0,%1,%2,%3}, [%4];"
        : "=r"(r[0]), "=r"(r[1]), "=r"(r[2]), "=r"(r[3])
        : "r"(addr));
}
__device__ __forceinline__ void ldsm4t(uint32_t* r, uint32_t addr) {
    asm volatile(
        "ldmatrix.sync.aligned.m8n8.x4.trans.shared.b16 {%0,%1,%2,%3}, [%4];"
        : "=r"(r[0]), "=r"(r[1]), "=r"(r[2]), "=r"(r[3])
        : "r"(addr));
}
__device__ __forceinline__ void mma16816(float* d, const uint32_t* a,
                                         const uint32_t* b) {
    asm volatile(
        "mma.sync.aligned.m16n8k16.row.col.f32.bf16.bf16.f32 "
        "{%0,%1,%2,%3}, {%4,%5,%6,%7}, {%8,%9}, {%0,%1,%2,%3};"
        : "+f"(d[0]), "+f"(d[1]), "+f"(d[2]), "+f"(d[3])
        : "r"(a[0]), "r"(a[1]), "r"(a[2]), "r"(a[3]), "r"(b[0]), "r"(b[1]));
}
__device__ __forceinline__ void split4(float4 v, uint2& hi, uint2& lo) {
    __nv_bfloat162 h0 = __floats2bfloat162_rn(v.x, v.y);
    __nv_bfloat162 h1 = __floats2bfloat162_rn(v.z, v.w);
    float2 f0 = __bfloat1622float2(h0);
    float2 f1 = __bfloat1622float2(h1);
    __nv_bfloat162 l0 = __floats2bfloat162_rn(v.x - f0.x, v.y - f0.y);
    __nv_bfloat162 l1 = __floats2bfloat162_rn(v.z - f1.x, v.w - f1.y);
    hi = make_uint2(*(uint32_t*)&h0, *(uint32_t*)&h1);
    lo = make_uint2(*(uint32_t*)&l0, *(uint32_t*)&l1);
}

// ---------------- zero kernels ----------------
__global__ void zero_i_kernel(int* p, int n) {
    int i = blockIdx.x * blockDim.x + threadIdx.x;
    int st = gridDim.x * blockDim.x;
    for (; i < n; i += st) p[i] = 0;
}

// ---------------- generic CSR build pieces ----------------
__global__ void hist_kernel(const int* __restrict__ eir,
                            int* __restrict__ cnt) {
    int r = blockIdx.y;
    int i = blockIdx.x * blockDim.x + threadIdx.x;
    if (i < NE) atomicAdd(&cnt[r * CBASE + eir[(size_t)r * 2 * NE + NE + i]], 1);
}
__global__ void hist2_kernel(const int* __restrict__ hyper,
                             int* __restrict__ cnt) {
    int i = blockIdx.x * blockDim.x + threadIdx.x;
    if (i < NA) atomicAdd(&cnt[hyper[i]], 1);
}
__global__ void scanA_kernel(const int* __restrict__ cnt, int* __restrict__ out,
                             int* __restrict__ sums) {
    __shared__ int sh[256];
    int i = blockIdx.x * 256 + threadIdx.x;
    int v = cnt[i];
    sh[threadIdx.x] = v;
    __syncthreads();
    for (int o = 1; o < 256; o <<= 1) {
        int t = (threadIdx.x >= o) ? sh[threadIdx.x - o] : 0;
        __syncthreads();
        sh[threadIdx.x] += t;
        __syncthreads();
    }
    out[i] = sh[threadIdx.x] - v;
    if (threadIdx.x == 255) sums[blockIdx.x] = sh[255];
}
__global__ void scanB_kernel(int* __restrict__ sums, int n) {
    __shared__ int sh[1024];
    int v = (threadIdx.x < n) ? sums[threadIdx.x] : 0;
    sh[threadIdx.x] = v;
    __syncthreads();
    for (int o = 1; o < 1024; o <<= 1) {
        int t = (threadIdx.x >= o) ? sh[threadIdx.x - o] : 0;
        __syncthreads();
        sh[threadIdx.x] += t;
        __syncthreads();
    }
    if (threadIdx.x < n) sums[threadIdx.x] = sh[threadIdx.x] - v;
}
__global__ void scanC_kernel(int* __restrict__ out, const int* __restrict__ sums,
                             int* __restrict__ fill) {
    int i = blockIdx.x * 256 + threadIdx.x;
    int v = out[i] + sums[blockIdx.x];
    out[i] = v;
    fill[i] = v;
}
__global__ void csr_scatter_kernel(const int* __restrict__ eir,
                                   int* __restrict__ fill,
                                   int* __restrict__ ssorted) {
    int r = blockIdx.y;
    int i = blockIdx.x * blockDim.x + threadIdx.x;
    if (i >= NE) return;
    int d = eir[(size_t)r * 2 * NE + NE + i];
    int s = eir[(size_t)r * 2 * NE + i];
    int pos = atomicAdd(&fill[r * CBASE + d], 1);
    ssorted[pos] = s;
}
__global__ void acsr_scatter_kernel(const int* __restrict__ hyper,
                                    int* __restrict__ fill,
                                    int* __restrict__ asorted) {
    int i = blockIdx.x * blockDim.x + threadIdx.x;
    if (i >= NA) return;
    int pos = atomicAdd(&fill[hyper[i]], 1);
    asorted[pos] = i;
}

// ---------------- atom aggregation: warp per chemical, no atomics ------------
__global__ __launch_bounds__(256) void atom_sum_kernel(
    const int* __restrict__ asorted, const int* __restrict__ aoffs,
    const float* __restrict__ xa, float* __restrict__ g) {
    int d = (blockIdx.x * blockDim.x + threadIdx.x) >> 5;
    int lane = threadIdx.x & 31;
    if (d >= N0) return;
    int beg = aoffs[d], end = aoffs[d + 1];
    float4 acc = make_float4(0.f, 0.f, 0.f, 0.f);
    int j = beg;
    for (; j + 1 < end; j += 2) {
        int a0 = asorted[j], a1 = asorted[j + 1];
        float4 v0 = *(const float4*)&xa[(size_t)a0 * 128 + lane * 4];
        float4 v1 = *(const float4*)&xa[(size_t)a1 * 128 + lane * 4];
        acc.x += v0.x + v1.x; acc.y += v0.y + v1.y;
        acc.z += v0.z + v1.z; acc.w += v0.w + v1.w;
    }
    if (j < end) {
        int a0 = asorted[j];
        float4 v0 = *(const float4*)&xa[(size_t)a0 * 128 + lane * 4];
        acc.x += v0.x; acc.y += v0.y; acc.z += v0.z; acc.w += v0.w;
    }
    *(float4*)&g[(size_t)d * 128 + lane * 4] = acc;
}

// x0 = gemm_out/max(cnt,1) + x_chem
__global__ void combine_kernel(const float* __restrict__ t,
                               const int* __restrict__ cnt,
                               const float* __restrict__ xc,
                               float* __restrict__ out, int n) {
    int i = blockIdx.x * blockDim.x + threadIdx.x;
    if (i < n) out[i] = t[i] / fmaxf((float)cnt[i >> 7], 1.f) + xc[i];
}

// ---------------- tensor-core bf16x3 GEMM core (runtime halfout) -------------
__device__ __forceinline__ void tc_gemm_core(const float* __restrict__ A,
                                             const float* __restrict__ B,
                                             const float* __restrict__ bias,
                                             void* __restrict__ Cv, int M,
                                             int halfout) {
    extern __shared__ __nv_bfloat16 sm[];
    __nv_bfloat16* sAh = sm;
    __nv_bfloat16* sAl = sm + 8192;
    __nv_bfloat16* sBh = sm + 16384;
    __nv_bfloat16* sBl = sm + 24576;
    const int tid = threadIdx.x;
    const int lane = tid & 31, warp = tid >> 5;
    const int wm = warp & 3, wn = warp >> 2;
    const int rowBase = blockIdx.x * 128;
    if (rowBase >= M) return;

    float acc[2][8][4];
#pragma unroll
    for (int a = 0; a < 2; ++a)
#pragma unroll
        for (int b = 0; b < 8; ++b)
#pragma unroll
            for (int c = 0; c < 4; ++c) acc[a][b][c] = 0.f;

    uint32_t sAh_b = (uint32_t)__cvta_generic_to_shared(sAh);
    uint32_t sAl_b = (uint32_t)__cvta_generic_to_shared(sAl);
    uint32_t sBh_b = (uint32_t)__cvta_generic_to_shared(sBh);
    uint32_t sBl_b = (uint32_t)__cvta_generic_to_shared(sBl);

    for (int kc = 0; kc < 128; kc += 64) {
        __syncthreads();
#pragma unroll
        for (int i = 0; i < 8; ++i) {
            int j = tid + 256 * i;
            int row = j >> 4, c4 = j & 15;
            float4 v = make_float4(0.f, 0.f, 0.f, 0.f);
            if (rowBase + row < M)
                v = *(const float4*)&A[(size_t)(rowBase + row) * 128 + kc +
                                       c4 * 4];
            uint2 h, l;
            split4(v, h, l);
            int off = row * 64 + (((c4 >> 1) ^ (row & 7)) << 3) + (c4 & 1) * 4;
            *(uint2*)&sAh[off] = h;
            *(uint2*)&sAl[off] = l;
        }
#pragma unroll
        for (int i = 0; i < 8; ++i) {
            int j = tid + 256 * i;
            int row = j >> 5, c4 = j & 31;
            float4 v = *(const float4*)&B[(size_t)(kc + row) * 128 + c4 * 4];
            uint2 h, l;
            split4(v, h, l);
            int off = row * 128 + (((c4 >> 1) ^ (row & 7)) << 3) + (c4 & 1) * 4;
            *(uint2*)&sBh[off] = h;
            *(uint2*)&sBl[off] = l;
        }
        __syncthreads();
#pragma unroll
        for (int s = 0; s < 4; ++s) {
            uint32_t ah[2][4], al[2][4];
#pragma unroll
            for (int mf = 0; mf < 2; ++mf) {
                int mr = wm * 32 + mf * 16 + (lane & 15);
                int ck = 2 * s + (lane >> 4);
                uint32_t off = (uint32_t)(mr * 64 + ((ck ^ (mr & 7)) << 3)) * 2;
                ldsm4(ah[mf], sAh_b + off);
                ldsm4(al[mf], sAl_b + off);
            }
#pragma unroll
            for (int nf2 = 0; nf2 < 4; ++nf2) {
                int kr = s * 16 + (lane & 7) + ((lane >> 3) & 1) * 8;
                int cn = wn * 8 + nf2 * 2 + (lane >> 4);
                uint32_t off =
                    (uint32_t)(kr * 128 + ((cn ^ (kr & 7)) << 3)) * 2;
                uint32_t bh[4], bl[4];
                ldsm4t(bh, sBh_b + off);
                ldsm4t(bl, sBl_b + off);
#pragma unroll
                for (int mf = 0; mf < 2; ++mf) {
                    mma16816(acc[mf][nf2 * 2], ah[mf], bh);
                    mma16816(acc[mf][nf2 * 2], ah[mf], bl);
                    mma16816(acc[mf][nf2 * 2], al[mf], bh);
                    mma16816(acc[mf][nf2 * 2 + 1], ah[mf], bh + 2);
                    mma16816(acc[mf][nf2 * 2 + 1], ah[mf], bl + 2);
                    mma16816(acc[mf][nf2 * 2 + 1], al[mf], bh + 2);
                }
            }
        }
    }
    int c0 = wn * 64 + (lane & 3) * 2;
#pragma unroll
    for (int mf = 0; mf < 2; ++mf) {
        int r0 = rowBase + wm * 32 + mf * 16 + (lane >> 2);
#pragma unroll
        for (int nf = 0; nf < 8; ++nf) {
            int col = c0 + nf * 8;
            float2 bv = *(const float2*)&bias[col];
            if (halfout) {
                __half* C = (__half*)Cv;
                if (r0 < M)
                    *(__half2*)&C[(size_t)r0 * 128 + col] = __floats2half2_rn(
                        acc[mf][nf][0] + bv.x, acc[mf][nf][1] + bv.y);
                if (r0 + 8 < M)
                    *(__half2*)&C[(size_t)(r0 + 8) * 128 + col] =
                        __floats2half2_rn(acc[mf][nf][2] + bv.x,
                                          acc[mf][nf][3] + bv.y);
            } else {
                float* C = (float*)Cv;
                if (r0 < M) {
                    C[(size_t)r0 * 128 + col] = acc[mf][nf][0] + bv.x;
                    C[(size_t)r0 * 128 + col + 1] = acc[mf][nf][1] + bv.y;
                }
                if (r0 + 8 < M) {
                    C[(size_t)(r0 + 8) * 128 + col] = acc[mf][nf][2] + bv.x;
                    C[(size_t)(r0 + 8) * 128 + col + 1] = acc[mf][nf][3] + bv.y;
                }
            }
        }
    }
}

// batched GEMM: up to 6 independent 128-N GEMMs in one launch (grid.y)
struct GBatch {
    const float* A[6];
    const float* W[6];
    const float* bias[6];
    void* C[6];
    int M[6];
    int halfout[6];
};
__global__ __launch_bounds__(256, 2) void tc_gemm_batch_kernel(GBatch gb) {
    int z = blockIdx.y;
    tc_gemm_core(gb.A[z], gb.W[z], gb.bias[z], gb.C[z], gb.M[z],
                 gb.halfout[z]);
}
__global__ __launch_bounds__(256, 2) void tc_gemm_f32_kernel(
    const float* __restrict__ A, const float* __restrict__ B,
    const float* __restrict__ bias, float* __restrict__ C, int M) {
    tc_gemm_core(A, B, bias, C, M, 0);
}

// ---------------- merged CSR edge aggregation (grid.y = relation in group) ---
struct EGroup {
    const __half* xl[3];
    const float* xr[3];
    const float* att[3];
    float* agg[3];
    int Nd[3];
    int robase[3];
    int store[3];
};
__global__ __launch_bounds__(256) void edge_group_kernel(
    EGroup eg, const int* __restrict__ ssorted, const int* __restrict__ offs) {
    int z = blockIdx.y;
    int d = (blockIdx.x * blockDim.x + threadIdx.x) >> 5;
    int lane = threadIdx.x & 31;
    if (d >= eg.Nd[z]) return;
    const __half* xl = eg.xl[z];
    const float* xr = eg.xr[z];
    int beg = offs[eg.robase[z] + d], end = offs[eg.robase[z] + d + 1];
    float* o = &eg.agg[z][(size_t)d * 128 + lane * 4];
    bool store = eg.store[z] != 0;
    if (beg == end) {
        if (store) *(float4*)o = make_float4(0.f, 0.f, 0.f, 0.f);
        return;
    }
    float4 r4 = *(const float4*)&xr[(size_t)d * 128 + lane * 4];
    float4 av = *(const float4*)&eg.att[z][lane * 4];
    float4 acc = make_float4(0.f, 0.f, 0.f, 0.f);
    float sden = 0.f;
    int j = beg;
    for (; j + 3 < end; j += 4) {
        int s0 = ssorted[j], s1 = ssorted[j + 1];
        int s2 = ssorted[j + 2], s3 = ssorted[j + 3];
        uint2 u0 = *(const uint2*)&xl[(size_t)s0 * 128 + lane * 4];
        uint2 u1 = *(const uint2*)&xl[(size_t)s1 * 128 + lane * 4];
        uint2 u2 = *(const uint2*)&xl[(size_t)s2 * 128 + lane * 4];
        uint2 u3 = *(const uint2*)&xl[(size_t)s3 * 128 + lane * 4];
        float2 A01 = __half22float2(*(__half2*)&u0.x);
        float2 A23 = __half22float2(*(__half2*)&u0.y);
        float2 B01 = __half22float2(*(__half2*)&u1.x);
        float2 B23 = __half22float2(*(__half2*)&u1.y);
        float2 C01 = __half22float2(*(__half2*)&u2.x);
        float2 C23 = __half22float2(*(__half2*)&u2.y);
        float2 D01 = __half22float2(*(__half2*)&u3.x);
        float2 D23 = __half22float2(*(__half2*)&u3.y);
        float t, pA, pB, pC, pD;
        t = A01.x + r4.x; t = t > 0.f ? t : 0.2f * t; pA = t * av.x;
        t = A01.y + r4.y; t = t > 0.f ? t : 0.2f * t; pA += t * av.y;
        t = A23.x + r4.z; t = t > 0.f ? t : 0.2f * t; pA += t * av.z;
        t = A23.y + r4.w; t = t > 0.f ? t : 0.2f * t; pA += t * av.w;
        t = B01.x + r4.x; t = t > 0.f ? t : 0.2f * t; pB = t * av.x;
        t = B01.y + r4.y; t = t > 0.f ? t : 0.2f * t; pB += t * av.y;
        t = B23.x + r4.z; t = t > 0.f ? t : 0.2f * t; pB += t * av.z;
        t = B23.y + r4.w; t = t > 0.f ? t : 0.2f * t; pB += t * av.w;
        t = C01.x + r4.x; t = t > 0.f ? t : 0.2f * t; pC = t * av.x;
        t = C01.y + r4.y; t = t > 0.f ? t : 0.2f * t; pC += t * av.y;
        t = C23.x + r4.z; t = t > 0.f ? t : 0.2f * t; pC += t * av.z;
        t = C23.y + r4.w; t = t > 0.f ? t : 0.2f * t; pC += t * av.w;
        t = D01.x + r4.x; t = t > 0.f ? t : 0.2f * t; pD = t * av.x;
        t = D01.y + r4.y; t = t > 0.f ? t : 0.2f * t; pD += t * av.y;
        t = D23.x + r4.z; t = t > 0.f ? t : 0.2f * t; pD += t * av.z;
        t = D23.y + r4.w; t = t > 0.f ? t : 0.2f * t; pD += t * av.w;
        pA = wsum(pA); pB = wsum(pB); pC = wsum(pC); pD = wsum(pD);
        float eA = __expf(pA), eB = __expf(pB);
        float eC = __expf(pC), eD = __expf(pD);
        acc.x += eA * A01.x + eB * B01.x + eC * C01.x + eD * D01.x;
        acc.y += eA * A01.y + eB * B01.y + eC * C01.y + eD * D01.y;
        acc.z += eA * A23.x + eB * B23.x + eC * C23.x + eD * D23.x;
        acc.w += eA * A23.y + eB * B23.y + eC * C23.y + eD * D23.y;
        sden += (eA + eB) + (eC + eD);
    }
    for (; j < end; ++j) {
        int s0 = ssorted[j];
        uint2 u0 = *(const uint2*)&xl[(size_t)s0 * 128 + lane * 4];
        float2 A01 = __half22float2(*(__half2*)&u0.x);
        float2 A23 = __half22float2(*(__half2*)&u0.y);
        float t, pA;
        t = A01.x + r4.x; t = t > 0.f ? t : 0.2f * t; pA = t * av.x;
        t = A01.y + r4.y; t = t > 0.f ? t : 0.2f * t; pA += t * av.y;
        t = A23.x + r4.z; t = t > 0.f ? t : 0.2f * t; pA += t * av.z;
        t = A23.y + r4.w; t = t > 0.f ? t : 0.2f * t; pA += t * av.w;
        pA = wsum(pA);
        float eA = __expf(pA);
        acc.x += eA * A01.x; acc.y += eA * A01.y;
        acc.z += eA * A23.x; acc.w += eA * A23.y;
        sden += eA;
    }
    float inv = 1.f / fmaxf(sden, 1e-16f);
    if (store) {
        *(float4*)o = make_float4(acc.x * inv, acc.y * inv, acc.z * inv,
                                  acc.w * inv);
    } else {
        float4 g = *(float4*)o;
        g.x += acc.x * inv; g.y += acc.y * inv;
        g.z += acc.z * inv; g.w += acc.w * inv;
        *(float4*)o = g;
    }
}

// combined GATv2 output bias per (layer, dst type)
__global__ void cbias2_kernel(const float* __restrict__ cb,
                              float* __restrict__ out) {
    int l = blockIdx.x;
    int c = threadIdx.x;
    float s[3] = {0.f, 0.f, 0.f};
#pragma unroll
    for (int r = 0; r < RR; ++r) s[c_RD[r]] += cb[(l * RR + r) * HD + c];
    out[(l * 3 + 0) * HD + c] = s[0];
    out[(l * 3 + 1) * HD + c] = s[1];
    out[(l * 3 + 2) * HD + c] = s[2];
}

// ---------------- merged layernorm + relu over all 3 types -------------------
__global__ void ln_relu_all_kernel(const float* __restrict__ a0,
                                   const float* __restrict__ a1,
                                   const float* __restrict__ a2,
                                   float* __restrict__ x0,
                                   float* __restrict__ x1,
                                   float* __restrict__ x2,
                                   const float* __restrict__ cb3,
                                   const float* __restrict__ g3,
                                   const float* __restrict__ b3) {
    int row = (blockIdx.x * blockDim.x + threadIdx.x) >> 5;
    int lane = threadIdx.x & 31;
    if (row >= NROWS) return;
    int t, lr;
    const float* in;
    float* out;
    if (row < N0) { t = 0; lr = row; in = a0; out = x0; }
    else if (row < N0 + N1) { t = 1; lr = row - N0; in = a1; out = x1; }
    else { t = 2; lr = row - N0 - N1; in = a2; out = x2; }
    float4 v = *(const float4*)&in[(size_t)lr * 128 + lane * 4];
    float4 cv = *(const float4*)&cb3[t * HD + lane * 4];
    v.x += cv.x; v.y += cv.y; v.z += cv.z; v.w += cv.w;
    float s = v.x + v.y + v.z + v.w;
    s = wsum(s);
    float mu = s * (1.f / 128.f);
    float d0 = v.x - mu, d1 = v.y - mu, d2 = v.z - mu, d3 = v.w - mu;
    float ss = d0 * d0 + d1 * d1 + d2 * d2 + d3 * d3;
    ss = wsum(ss);
    float inv = rsqrtf(ss * (1.f / 128.f) + 1e-5f);
    float4 gv = *(const float4*)&g3[t * HD + lane * 4];
    float4 bv = *(const float4*)&b3[t * HD + lane * 4];
    float4 o;
    o.x = fmaxf(d0 * inv * gv.x + bv.x, 0.f);
    o.y = fmaxf(d1 * inv * gv.y + bv.y, 0.f);
    o.z = fmaxf(d2 * inv * gv.z + bv.z, 0.f);
    o.w = fmaxf(d3 * inv * gv.w + bv.w, 0.f);
    *(float4*)&out[(size_t)lr * 128 + lane * 4] = o;
}

// ---------------- prediction head ----------------
__global__ void pred_kernel(const float* __restrict__ x,
                            const float* __restrict__ Wp,
                            const float* __restrict__ bp,
                            float* __restrict__ out, int N) {
    int row = (blockIdx.x * blockDim.x + threadIdx.x) >> 5;
    int lane = threadIdx.x & 31;
    if (row >= N) return;
    float4 xv = *(const float4*)&x[(size_t)row * 128 + lane * 4];
    float4 w01 = *(const float4*)&Wp[lane * 8];
    float4 w23 = *(const float4*)&Wp[lane * 8 + 4];
    float a0 = xv.x * w01.x + xv.y * w01.z + xv.z * w23.x + xv.w * w23.z;
    float a1 = xv.x * w01.y + xv.y * w01.w + xv.z * w23.y + xv.w * w23.w;
    a0 = wsum(a0);
    a1 = wsum(a1);
    if (lane == 0) {
        out[row * 2 + 0] = a0 + bp[0];
        out[row * 2 + 1] = a1 + bp[1];
    }
}

// ---------------- host orchestration ----------------
extern "C" void kernel_launch(void* const* d_in, const int* in_sizes, int n_in,
                              void* d_out, int out_size) {
    const float* x_atom = (const float*)d_in[0];
    const float* x_chem = (const float*)d_in[1];
    const float* x_gene = (const float*)d_in[2];
    const float* x_assay = (const float*)d_in[3];
    const float* W_mol = (const float*)d_in[4];
    const float* Wl = (const float*)d_in[5];
    const float* Wr = (const float*)d_in[6];
    const float* bl = (const float*)d_in[7];
    const float* br = (const float*)d_in[8];
    const float* att = (const float*)d_in[9];
    const float* cb = (const float*)d_in[10];
    const float* lng = (const float*)d_in[11];
    const float* lnb = (const float*)d_in[12];
    const float* Wp = (const float*)d_in[13];
    const float* bp = (const float*)d_in[14];
    const int* hyper = (const int*)d_in[15];
    const int* eir = (const int*)d_in[16];
    float* out = (float*)d_out;
    (void)in_sizes; (void)n_in; (void)out_size;

    float *px0, *px1, *px2, *pa0, *pa1, *pa2, *pxr, *pcb, *pz;
    __half* pxlh;
    int *pcounts, *poffs, *pfill, *psums, *pss;
    int *pcounts2, *poffs2, *pfill2, *psums2, *pas;
    cudaGetSymbolAddress((void**)&px0, g_x0);
    cudaGetSymbolAddress((void**)&px1, g_x1);
    cudaGetSymbolAddress((void**)&px2, g_x2);
    cudaGetSymbolAddress((void**)&pa0, g_a0);
    cudaGetSymbolAddress((void**)&pa1, g_a1);
    cudaGetSymbolAddress((void**)&pa2, g_a2);
    cudaGetSymbolAddress((void**)&pxlh, g_xlh);
    cudaGetSymbolAddress((void**)&pxr, g_xr);
    cudaGetSymbolAddress((void**)&pcb, g_cbias);
    cudaGetSymbolAddress((void**)&pz, g_zero128);
    cudaGetSymbolAddress((void**)&pcounts, g_counts);
    cudaGetSymbolAddress((void**)&poffs, g_offs);
    cudaGetSymbolAddress((void**)&pfill, g_fill);
    cudaGetSymbolAddress((void**)&psums, g_sums);
    cudaGetSymbolAddress((void**)&pss, g_ssorted);
    cudaGetSymbolAddress((void**)&pcounts2, g_counts2);
    cudaGetSymbolAddress((void**)&poffs2, g_offs2);
    cudaGetSymbolAddress((void**)&pfill2, g_fill2);
    cudaGetSymbolAddress((void**)&psums2, g_sums2);
    cudaGetSymbolAddress((void**)&pas, g_asorted);

    // 2-stream topology (teardown-safe configuration)
    static cudaStream_t s1 = nullptr;
    static cudaEvent_t evStart, evFork, evCSR, evG[LL * NG], evL[LL];
    if (!s1) {
        cudaStreamCreateWithFlags(&s1, cudaStreamNonBlocking);
        cudaEventCreateWithFlags(&evStart, cudaEventDisableTiming);
        cudaEventCreateWithFlags(&evFork, cudaEventDisableTiming);
        cudaEventCreateWithFlags(&evCSR, cudaEventDisableTiming);
        for (int i = 0; i < LL * NG; ++i)
            cudaEventCreateWithFlags(&evG[i], cudaEventDisableTiming);
        for (int i = 0; i < LL; ++i)
            cudaEventCreateWithFlags(&evL[i], cudaEventDisableTiming);
    }

    const int T = 256;
    const int SMEMB = 65536;

    cudaFuncSetAttribute(tc_gemm_batch_kernel,
                         cudaFuncAttributeMaxDynamicSharedMemorySize, SMEMB);
    cudaFuncSetAttribute(tc_gemm_f32_kernel,
                         cudaFuncAttributeMaxDynamicSharedMemorySize, SMEMB);

    static const int RS[RR] = {0, 0, 0, 0, 0, 2, 1, 2, 2, 1, 1, 1, 1};
    static const int RD[RR] = {2, 2, 1, 1, 1, 1, 1, 0, 0, 0, 0, 0, 2};
    // relation groups: distinct dst types within each group
    static const int GREL[NG][3] = {
        {5, 12, 7}, {6, 0, 8}, {2, 1, 9}, {3, 10, -1}, {4, 11, -1}};
    static const int GNr[NG] = {3, 3, 3, 2, 2};
    // STORE for the first relation of each dst type in processing order
    static const bool FIRST[RR] = {false, false, false, false, false,
                                   true,  false, true,  false, false,
                                   false, false, true};
    const int NT[3] = {N0, N1, N2};

    // s1: edge CSR build + cbias precompute, concurrent with the prelude
    cudaEventRecord(evStart, 0);
    cudaStreamWaitEvent(s1, evStart, 0);
    zero_i_kernel<<<256, T, 0, s1>>>(pcounts, NCNT);
    {
        dim3 hg((NE + T - 1) / T, RR);
        hist_kernel<<<hg, T, 0, s1>>>(eir, pcounts);
        scanA_kernel<<<NBLK, 256, 0, s1>>>(pcounts, poffs, psums);
        scanB_kernel<<<1, 1024, 0, s1>>>(psums, NBLK);
        scanC_kernel<<<NBLK, 256, 0, s1>>>(poffs, psums, pfill);
        csr_scatter_kernel<<<hg, T, 0, s1>>>(eir, pfill, pss);
        cbias2_kernel<<<LL, HD, 0, s1>>>(cb, pcb);
    }
    cudaEventRecord(evCSR, s1);

    // ---- stream 0 prelude: atom CSR -> gather-sum -> 20k GEMM -> combine ----
    zero_i_kernel<<<80, T>>>(pcounts2, NCNT2);
    hist2_kernel<<<(NA + T - 1) / T, T>>>(hyper, pcounts2);
    scanA_kernel<<<NBLK2, 256>>>(pcounts2, poffs2, psums2);
    scanB_kernel<<<1, 1024>>>(psums2, NBLK2);
    scanC_kernel<<<NBLK2, 256>>>(poffs2, psums2, pfill2);
    acsr_scatter_kernel<<<(NA + T - 1) / T, T>>>(hyper, pfill2, pas);
    atom_sum_kernel<<<(N0 * 32 + T - 1) / T, T>>>(pas, poffs2, x_atom, pa1);
    tc_gemm_f32_kernel<<<(N0 + 127) / 128, T, SMEMB>>>(pa1, W_mol, pz, pa0,
                                                       N0);
    combine_kernel<<<(N0 * HD + T - 1) / T, T>>>(pa0, pcounts2, x_chem, px0,
                                                 N0 * HD);
    cudaEventRecord(evFork, 0);
    cudaStreamWaitEvent(s1, evFork, 0);  // s1's GEMMs read px0
    cudaStreamWaitEvent(0, evCSR, 0);    // edge kernels need CSR + cbias

    const float* xsrc[3] = {px0, x_gene, x_assay};
    float* agg[3] = {pa0, pa1, pa2};

    for (int l = 0; l < LL; ++l) {
        size_t lo = (size_t)l * RR;

        for (int g = 0; g < NG; ++g) {
            int n = GNr[g];
            // --- producer batch (s1): Wl+Wr GEMMs for all rels in group ---
            GBatch gb;
            int mx = 0;
            for (int i = 0; i < n; ++i) {
                int r = GREL[g][i];
                size_t wo = lo + r;
                int s = RS[r], d = RD[r];
                gb.A[2 * i] = xsrc[s];
                gb.W[2 * i] = Wl + wo * HD * HD;
                gb.bias[2 * i] = bl + wo * HD;
                gb.C[2 * i] = pxlh + (size_t)r * SLAB;
                gb.M[2 * i] = NT[s];
                gb.halfout[2 * i] = 1;
                gb.A[2 * i + 1] = xsrc[d];
                gb.W[2 * i + 1] = Wr + wo * HD * HD;
                gb.bias[2 * i + 1] = br + wo * HD;
                gb.C[2 * i + 1] = pxr + (size_t)r * SLAB;
                gb.M[2 * i + 1] = NT[d];
                gb.halfout[2 * i + 1] = 0;
                if (NT[s] > mx) mx = NT[s];
                if (NT[d] > mx) mx = NT[d];
            }
            dim3 ggrid((mx + 127) / 128, 2 * n);
            tc_gemm_batch_kernel<<<ggrid, T, SMEMB, s1>>>(gb);
            int ge = l * NG + g;
            cudaEventRecord(evG[ge], s1);

            // --- consumer (stream 0): merged edge group ---
            cudaStreamWaitEvent(0, evG[ge], 0);
            EGroup egp;
            int mxd = 0;
            for (int i = 0; i < n; ++i) {
                int r = GREL[g][i];
                int d = RD[r];
                egp.xl[i] = pxlh + (size_t)r * SLAB;
                egp.xr[i] = pxr + (size_t)r * SLAB;
                egp.att[i] = att + (lo + r) * HD;
                egp.agg[i] = agg[d];
                egp.Nd[i] = NT[d];
                egp.robase[i] = r * CBASE;
                egp.store[i] = FIRST[r] ? 1 : 0;
                if (NT[d] > mxd) mxd = NT[d];
            }
            dim3 egrid((mxd * 32 + T - 1) / T, n);
            edge_group_kernel<<<egrid, T>>>(egp, pss, poffs);
        }
        ln_relu_all_kernel<<<(NROWS * 32 + T - 1) / T, T>>>(
            pa0, pa1, pa2, px0, px1, px2, pcb + l * 3 * HD,
            lng + (size_t)l * 3 * HD, lnb + (size_t)l * 3 * HD);
        xsrc[0] = px0; xsrc[1] = px1; xsrc[2] = px2;
        cudaEventRecord(evL[l], 0);
        cudaStreamWaitEvent(s1, evL[l], 0);
    }

    pred_kernel<<<(N0 * 32 + T - 1) / T, T>>>(px0, Wp, bp, out, N0);
}